// round 9
// baseline (speedup 1.0000x reference)
#include <cuda_runtime.h>
#include <cuda_fp16.h>
#include <math.h>
#include <stdint.h>

// ---------------------------------------------------------------------------
// MLA forward, per-head expanded attention + fused flash attention.
// GEMMs: fp16x3 emulated fp32 (hi/lo fp16 planes), mma.sync m16n8k16.
// Main product Ah*Bh -> f32 accumulator; cross products Ah*Bl + Al*Bh ->
// ONE chained f16x2 accumulator (2x rate hypothesis), promoted at the end.
// ---------------------------------------------------------------------------

#define BSZ    2
#define SEQ    2048
#define DMODEL 2048
#define NH     16
#define QLR    1536
#define KVLR   512
#define D_NOPE 128
#define D_ROPE 64
#define D_QK   192
#define D_V    128
#define MS     (BSZ*SEQ)          /* 4096 */
#define QDIM   (NH*D_QK)          /* 3072 */
#define KVD    (KVLR + D_ROPE)    /* 576  */
#define HDIM   (D_NOPE + D_V)     /* 256  */
#define EPSF   1e-6f

typedef __half hf16;

// ---------------- scratch: every tensor is [2][elems] fp16 planes ----------
__device__ hf16 g_xp   [2 * (size_t)MS * DMODEL];
__device__ hf16 g_wqaT [2 * (size_t)QLR * DMODEL];
__device__ hf16 g_wkvaT[2 * (size_t)KVD * DMODEL];
__device__ hf16 g_wqbT [2 * (size_t)QDIM * QLR];
__device__ hf16 g_wkvbT[2 * (size_t)NH * HDIM * KVLR];
__device__ hf16 g_woT  [2 * (size_t)DMODEL * DMODEL];
__device__ hf16 g_qa   [2 * (size_t)MS * QLR];
__device__ hf16 g_q    [2 * (size_t)MS * QDIM];
__device__ hf16 g_kv   [2 * (size_t)MS * KVD];
__device__ hf16 g_kext [2 * (size_t)MS * KVD];
__device__ hf16 g_kfull[2 * (size_t)BSZ * NH * SEQ * D_QK];
__device__ hf16 g_vT   [2 * (size_t)BSZ * NH * D_V * SEQ];
__device__ hf16 g_ohead[2 * (size_t)MS * DMODEL];

// ------------------------------ helpers -------------------------------------
__device__ __forceinline__ void split2(float x, hf16& h, hf16& l) {
    h = __float2half_rn(x);
    l = __float2half_rn(x - __half2float(h));
}
__device__ __forceinline__ float join2(hf16 h, hf16 l) {
    return __half2float(h) + __half2float(l);
}
__device__ __forceinline__ void cp16(uint32_t smem, const void* g, int srcBytes) {
    asm volatile("cp.async.cg.shared.global [%0], [%1], 16, %2;"
                 :: "r"(smem), "l"(g), "r"(srcBytes));
}
__device__ __forceinline__ void cp_commit() { asm volatile("cp.async.commit_group;"); }
__device__ __forceinline__ void cp_wait1()  { asm volatile("cp.async.wait_group 1;"); }

__device__ __forceinline__ void ldsm4(uint32_t* r, uint32_t addr) {
    asm volatile("ldmatrix.sync.aligned.m8n8.x4.shared.b16 {%0,%1,%2,%3}, [%4];"
                 : "=r"(r[0]), "=r"(r[1]), "=r"(r[2]), "=r"(r[3]) : "r"(addr));
}
// main product: fp16 inputs, fp32 accumulator
__device__ __forceinline__ void mma_f32(float* d, const uint32_t* a,
                                        uint32_t b0, uint32_t b1) {
    asm volatile(
        "mma.sync.aligned.m16n8k16.row.col.f32.f16.f16.f32 "
        "{%0,%1,%2,%3}, {%4,%5,%6,%7}, {%8,%9}, {%0,%1,%2,%3};"
        : "+f"(d[0]), "+f"(d[1]), "+f"(d[2]), "+f"(d[3])
        : "r"(a[0]), "r"(a[1]), "r"(a[2]), "r"(a[3]), "r"(b0), "r"(b1));
}
// cross products: fp16 inputs, fp16x2 accumulator (2 b32 regs)
__device__ __forceinline__ void mma_f16(uint32_t* d, const uint32_t* a,
                                        uint32_t b0, uint32_t b1) {
    asm volatile(
        "mma.sync.aligned.m16n8k16.row.col.f16.f16.f16.f16 "
        "{%0,%1}, {%2,%3,%4,%5}, {%6,%7}, {%0,%1};"
        : "+r"(d[0]), "+r"(d[1])
        : "r"(a[0]), "r"(a[1]), "r"(a[2]), "r"(a[3]), "r"(b0), "r"(b1));
}
// promote f16x2 cross accumulator into the f32 accumulator fragment
__device__ __forceinline__ void addcross(float* d, const uint32_t* c) {
    float2 f0 = __half22float2(*(const __half2*)&c[0]);
    float2 f1 = __half22float2(*(const __half2*)&c[1]);
    d[0] += f0.x; d[1] += f0.y; d[2] += f1.x; d[3] += f1.y;
}

// ----------------------------- GEMM kernel ----------------------------------
// C = A * B^T. A: [M][K] planes (hi at A, lo at A+aPS), row stride lda.
// B: [N][K] planes, row stride ldb. CTA tile 128x128, K-slab 16, 8 warps,
// warp tile 64x32. outMode 0: fp32 C. outMode 1: fp16 planes C (lo at +cPS).
struct GemmP {
    const hf16 *A, *B; void* C;
    long long aPS, bPS, cPS;
    int M, N, K;
    long long lda, ldb, ldc;
    long long aSb, aSh, bSb, bSh, cSb, cSh;
    int nInner, causal, outMode;
};

// stage: Ah[0,4096) Al[4096,8192) Bh[8192,12288) Bl[12288,16384)
#define STG_BYTES 16384

__global__ __launch_bounds__(256, 1) void gemm_hmma(GemmP p) {
    __shared__ __align__(16) hf16 stg[3][4][128 * 16];   // 48KB

    const int m0 = blockIdx.y * 128;
    const int n0 = blockIdx.x * 128;
    if (p.causal == 1 && n0 >= m0 + 128) return;

    const int z  = blockIdx.z;
    const int zb = z / p.nInner;
    const int zh = z - zb * p.nInner;
    const hf16* A = p.A + zb * p.aSb + zh * p.aSh;
    const hf16* B = p.B + zb * p.bSb + zh * p.bSh;

    int kEnd = p.K;
    if (p.causal == 2) { int km = m0 + 128; if (km < kEnd) kEnd = km; }
    const int nSlab = kEnd >> 4;

    const int tid  = threadIdx.x;
    const int lane = tid & 31;
    const int warp = tid >> 5;
    const int wm   = warp >> 2;    // 0..1
    const int wn   = warp & 3;     // 0..3

    const uint32_t smBase = (uint32_t)__cvta_generic_to_shared(&stg[0][0][0]);

    // ---- producer addressing: thread -> row r, one 16B chunk cc ----
    const int r  = tid >> 1;
    const int cc = tid & 1;
    const uint32_t pOff = (uint32_t)(r * 32 + ((cc ^ ((r >> 2) & 1)) << 4));

    int mr = m0 + r;
    const bool aok = mr < p.M;
    if (!aok) mr = m0;
    const hf16* gA0 = A + (size_t)mr * p.lda + cc * 8;
    const hf16* gA1 = gA0 + p.aPS;
    const int asz = aok ? 16 : 0;
    int nr = n0 + r;
    const bool bok = nr < p.N;
    if (!bok) nr = n0;
    const hf16* gB0 = B + (size_t)nr * p.ldb + cc * 8;
    const hf16* gB1 = gB0 + p.bPS;
    const int bsz = bok ? 16 : 0;

#define ISSUE(S)                                                               \
    do {                                                                       \
        uint32_t sb = smBase + (uint32_t)(((S) % 3) * STG_BYTES);              \
        const size_t ko = (size_t)(S) * 16;                                    \
        cp16(sb + pOff,         gA0 + ko, asz);                                \
        cp16(sb + 4096 + pOff,  gA1 + ko, asz);                                \
        cp16(sb + 8192 + pOff,  gB0 + ko, bsz);                                \
        cp16(sb + 12288 + pOff, gB1 + ko, bsz);                                \
    } while (0)

    // ---- consumer (ldmatrix) base offsets, plane-relative ----
    const int rowA = wm * 64 + (lane & 7) + ((lane >> 3) & 1) * 8;
    const int cA   = lane >> 4;
    const uint32_t offA = (uint32_t)(rowA * 32 + ((cA ^ ((rowA >> 2) & 1)) << 4));
    const int rowB = wn * 32 + (lane & 7) + ((lane >> 4) << 3);
    const int cB   = (lane >> 3) & 1;
    const uint32_t offB = (uint32_t)(rowB * 32 + ((cB ^ ((rowB >> 2) & 1)) << 4));

    float acc[4][4][4];
    uint32_t cacc[4][4][2];
#pragma unroll
    for (int i = 0; i < 4; ++i)
#pragma unroll
        for (int j = 0; j < 4; ++j) {
#pragma unroll
            for (int l = 0; l < 4; ++l) acc[i][j][l] = 0.f;
            cacc[i][j][0] = 0u; cacc[i][j][1] = 0u;
        }

    // prologue: 2 slabs ahead
    ISSUE(0); cp_commit();
    if (nSlab > 1) ISSUE(1);
    cp_commit();

    for (int it = 0; it < nSlab; ++it) {
        cp_wait1();
        __syncthreads();   // stage ready; also orders prior reads before overwrite

        const uint32_t sb   = smBase + (uint32_t)((it % 3) * STG_BYTES);
        const uint32_t aAdr = sb + offA;
        const uint32_t bAdr = sb + 8192 + offB;

        uint32_t bh[2][4], bl[2][4];
        ldsm4(bh[0], bAdr);
        ldsm4(bh[1], bAdr + 512);
        ldsm4(bl[0], bAdr + 4096);
        ldsm4(bl[1], bAdr + 4096 + 512);

#pragma unroll
        for (int mi = 0; mi < 4; ++mi) {
            uint32_t ah[4], al[4];
            ldsm4(ah, aAdr + mi * 512);
            ldsm4(al, aAdr + 4096 + mi * 512);
#pragma unroll
            for (int nt = 0; nt < 4; ++nt) {
                const int np = nt >> 1, hf = (nt & 1) * 2;
                const uint32_t b0h = bh[np][hf], b1h = bh[np][hf + 1];
                const uint32_t b0l = bl[np][hf], b1l = bl[np][hf + 1];
                mma_f32(acc[mi][nt], ah, b0h, b1h);
                mma_f16(cacc[mi][nt], ah, b0l, b1l);
                mma_f16(cacc[mi][nt], al, b0h, b1h);
            }
        }

        if (it + 2 < nSlab) ISSUE(it + 2);
        cp_commit();
    }
#undef ISSUE

    // ---- epilogue ----
    const int g = lane >> 2;
    const int c = lane & 3;
#pragma unroll
    for (int mi = 0; mi < 4; ++mi)
#pragma unroll
        for (int nt = 0; nt < 4; ++nt) addcross(acc[mi][nt], cacc[mi][nt]);

    if (p.outMode == 0) {
        float* C = (float*)p.C + zb * p.cSb + zh * p.cSh;
#pragma unroll
        for (int mi = 0; mi < 4; ++mi) {
            const int gm = m0 + wm * 64 + mi * 16 + g;
            if (gm >= p.M) continue;
            float* r0 = C + (long long)gm * p.ldc;
            float* r1 = r0 + 8 * p.ldc;
#pragma unroll
            for (int nt = 0; nt < 4; ++nt) {
                const int gn = n0 + wn * 32 + nt * 8 + 2 * c;
                if (gn < p.N) {
                    *(float2*)(r0 + gn) = make_float2(acc[mi][nt][0], acc[mi][nt][1]);
                    *(float2*)(r1 + gn) = make_float2(acc[mi][nt][2], acc[mi][nt][3]);
                }
            }
        }
    } else {
        hf16* Ch = (hf16*)p.C + zb * p.cSb + zh * p.cSh;
        hf16* Cl = Ch + p.cPS;
#pragma unroll
        for (int mi = 0; mi < 4; ++mi) {
            const int gm = m0 + wm * 64 + mi * 16 + g;
            if (gm >= p.M) continue;
            const long long ro0 = (long long)gm * p.ldc;
            const long long ro1 = ro0 + 8 * p.ldc;
#pragma unroll
            for (int nt = 0; nt < 4; ++nt) {
                const int gn = n0 + wn * 32 + nt * 8 + 2 * c;
                if (gn < p.N) {
                    hf16 h0, l0, h1, l1;
                    split2(acc[mi][nt][0], h0, l0);
                    split2(acc[mi][nt][1], h1, l1);
                    *(__half2*)(Ch + ro0 + gn) = __halves2half2(h0, h1);
                    *(__half2*)(Cl + ro0 + gn) = __halves2half2(l0, l1);
                    split2(acc[mi][nt][2], h0, l0);
                    split2(acc[mi][nt][3], h1, l1);
                    *(__half2*)(Ch + ro1 + gn) = __halves2half2(h0, h1);
                    *(__half2*)(Cl + ro1 + gn) = __halves2half2(l0, l1);
                }
            }
        }
    }
}

// --------------------------- flash attention --------------------------------
// One CTA per (q-block 128, (b,h)). Q in smem; K/V streamed via 3-stage
// cp.async ring across phase boundaries. Online softmax in registers.
// Cross-product f16 accumulator reused across disjoint S / PV phases.
// smem layout (bytes):
//   Qh 0..51200   Ql 51200..102400          (128 rows x 400B, 192 cols used)
//   Ph 102400..137216  Pl 137216..172032    (128 rows x 272B, 128 cols used)
//   stages 172032 + s*8192 (Bh 4KB, Bl 4KB)
//   RED 196608..198656 (float[4][128])
#define FL_SMEM 198656

__global__ __launch_bounds__(256, 1) void flash_k(
    const hf16* __restrict__ q, const hf16* __restrict__ kfull,
    const hf16* __restrict__ vT, hf16* __restrict__ ohead, float s2) {
    extern __shared__ __align__(16) char dyn[];
    const int tid = threadIdx.x, lane = tid & 31, warp = tid >> 5;
    const int wm = warp >> 2, wn = warp & 3, g = lane >> 2, c = lane & 3;
    const int iq = 15 - blockIdx.x;       // heavy blocks first
    const int bh = blockIdx.y, b = bh >> 4, h = bh & 15;
    const int m0 = iq * 128;
    const long long psQ  = (long long)MS * QDIM;
    const long long psKF = (long long)BSZ * NH * SEQ * D_QK;
    const long long psVT = (long long)BSZ * NH * D_V * SEQ;
    const long long psOH = (long long)MS * DMODEL;

    const uint32_t smb = (uint32_t)__cvta_generic_to_shared(dyn);
    const uint32_t smQ = smb;
    const uint32_t smP = smb + 102400;
    const uint32_t smS = smb + 172032;
    float* RED = (float*)(dyn + 196608);

    // ---- Q block load (one commit group) ----
    {
        const int r = tid >> 1, hf = tid & 1;
        const hf16* src = q + ((size_t)(b * SEQ + m0 + r)) * QDIM + h * D_QK + hf * 96;
        const uint32_t d0 = smQ + (uint32_t)(r * 400 + hf * 192);
#pragma unroll
        for (int ch = 0; ch < 12; ++ch) {
            cp16(d0 + ch * 16, src + ch * 8, 16);
            cp16(d0 + 51200 + ch * 16, src + psQ + ch * 8, 16);
        }
        cp_commit();
    }

    const int prow = tid >> 1, pcc = tid & 1;
    const uint32_t pOff = (uint32_t)(prow * 32 + ((pcc ^ ((prow >> 2) & 1)) << 4));
    const hf16* kf = kfull + (size_t)bh * SEQ * D_QK;
    const hf16* vt = vT + (size_t)bh * D_V * SEQ;
    const int u_total = 20 * (iq + 1);

    // slab u -> (kv block j = u/20, s = u%20): s<12 K-slab (K=192), else V-slab
#define FL_ISSUE(U)                                                            \
    do {                                                                       \
        const int _j = (U) / 20, _s = (U) % 20;                                \
        uint32_t _sb = smS + (uint32_t)(((U) % 3) * 8192);                     \
        const hf16* _s0; long long _ps;                                        \
        if (_s < 12) {                                                         \
            _s0 = kf + ((size_t)(_j * 128 + prow)) * D_QK + _s * 16 + pcc * 8; \
            _ps = psKF;                                                        \
        } else {                                                               \
            _s0 = vt + (size_t)prow * SEQ + _j * 128 + (_s - 12) * 16 + pcc * 8; \
            _ps = psVT;                                                        \
        }                                                                      \
        cp16(_sb + pOff, _s0, 16);                                             \
        cp16(_sb + 4096 + pOff, _s0 + _ps, 16);                                \
    } while (0)

    FL_ISSUE(0); cp_commit();
    FL_ISSUE(1); cp_commit();

    // consumer fragment offsets
    const int rowA = wm * 64 + (lane & 7) + ((lane >> 3) & 1) * 8;
    const int cA   = lane >> 4;
    const uint32_t offAq = (uint32_t)(rowA * 400 + cA * 16);
    const uint32_t offAp = (uint32_t)(rowA * 272 + cA * 16);
    const int rowB = wn * 32 + (lane & 7) + ((lane >> 4) << 3);
    const int cB   = (lane >> 3) & 1;
    const uint32_t offB = (uint32_t)(rowB * 32 + ((cB ^ ((rowB >> 2) & 1)) << 4));

    float oacc[4][4][4];
    float m_r[4][2], l_r[4][2];
#pragma unroll
    for (int mi = 0; mi < 4; ++mi) {
#pragma unroll
        for (int nt = 0; nt < 4; ++nt)
#pragma unroll
            for (int k = 0; k < 4; ++k) oacc[mi][nt][k] = 0.f;
        m_r[mi][0] = m_r[mi][1] = -1e30f;
        l_r[mi][0] = l_r[mi][1] = 0.f;
    }

    int u = 0;
    for (int j = 0; j <= iq; ++j) {
        float sacc[4][4][4];
        uint32_t cacc[4][4][2];
#pragma unroll
        for (int mi = 0; mi < 4; ++mi)
#pragma unroll
            for (int nt = 0; nt < 4; ++nt) {
#pragma unroll
                for (int k = 0; k < 4; ++k) sacc[mi][nt][k] = 0.f;
                cacc[mi][nt][0] = 0u; cacc[mi][nt][1] = 0u;
            }

        // ---- S phase: 12 K-slabs (K=192) ----
        for (int s = 0; s < 12; ++s) {
            cp_wait1(); __syncthreads();
            const uint32_t sb = smS + (uint32_t)((u % 3) * 8192);
            uint32_t bh4[2][4], bl4[2][4];
            ldsm4(bh4[0], sb + offB); ldsm4(bh4[1], sb + offB + 512);
            ldsm4(bl4[0], sb + 4096 + offB); ldsm4(bl4[1], sb + 4096 + offB + 512);
#pragma unroll
            for (int mi = 0; mi < 4; ++mi) {
                uint32_t ah[4], al[4];
                ldsm4(ah, smQ + offAq + mi * 6400 + s * 32);
                ldsm4(al, smQ + 51200 + offAq + mi * 6400 + s * 32);
#pragma unroll
                for (int nt = 0; nt < 4; ++nt) {
                    const int np = nt >> 1, hf2 = (nt & 1) * 2;
                    mma_f32(sacc[mi][nt], ah, bh4[np][hf2], bh4[np][hf2 + 1]);
                    mma_f16(cacc[mi][nt], ah, bl4[np][hf2], bl4[np][hf2 + 1]);
                    mma_f16(cacc[mi][nt], al, bh4[np][hf2], bh4[np][hf2 + 1]);
                }
            }
            if (u + 2 < u_total) FL_ISSUE(u + 2);
            cp_commit(); ++u;
        }
        // promote cross terms into sacc
#pragma unroll
        for (int mi = 0; mi < 4; ++mi)
#pragma unroll
            for (int nt = 0; nt < 4; ++nt) {
                addcross(sacc[mi][nt], cacc[mi][nt]);
                cacc[mi][nt][0] = 0u; cacc[mi][nt][1] = 0u;   // reuse for PV
            }

        // ---- diagonal block mask ----
        if (j == iq) {
#pragma unroll
            for (int mi = 0; mi < 4; ++mi)
#pragma unroll
                for (int nt = 0; nt < 4; ++nt)
#pragma unroll
                    for (int k = 0; k < 4; ++k) {
                        const int rl = wm * 64 + mi * 16 + g + (k >> 1) * 8;
                        const int cl = wn * 32 + nt * 8 + 2 * c + (k & 1);
                        if (cl > rl) sacc[mi][nt][k] = -1e30f;
                    }
        }

        // ---- online softmax ----
        float alpha[4][2];
#pragma unroll
        for (int mi = 0; mi < 4; ++mi)
#pragma unroll
            for (int h2 = 0; h2 < 2; ++h2) {
                float v = fmaxf(fmaxf(sacc[mi][0][h2 * 2], sacc[mi][0][h2 * 2 + 1]),
                                fmaxf(sacc[mi][1][h2 * 2], sacc[mi][1][h2 * 2 + 1]));
                v = fmaxf(v, fmaxf(fmaxf(sacc[mi][2][h2 * 2], sacc[mi][2][h2 * 2 + 1]),
                                   fmaxf(sacc[mi][3][h2 * 2], sacc[mi][3][h2 * 2 + 1])));
                v = fmaxf(v, __shfl_xor_sync(0xffffffffu, v, 1));
                v = fmaxf(v, __shfl_xor_sync(0xffffffffu, v, 2));
                if (c == 0) RED[wn * 128 + wm * 64 + mi * 16 + g + h2 * 8] = v;
            }
        __syncthreads();
#pragma unroll
        for (int mi = 0; mi < 4; ++mi)
#pragma unroll
            for (int h2 = 0; h2 < 2; ++h2) {
                const int row = wm * 64 + mi * 16 + g + h2 * 8;
                float mrow = fmaxf(fmaxf(RED[row], RED[128 + row]),
                                   fmaxf(RED[256 + row], RED[384 + row]));
                float mnew = fmaxf(m_r[mi][h2], mrow);
                alpha[mi][h2] = exp2f((m_r[mi][h2] - mnew) * s2);
                m_r[mi][h2] = mnew;
            }
        __syncthreads();   // RED reads done before sum-round rewrite
#pragma unroll
        for (int mi = 0; mi < 4; ++mi)
#pragma unroll
            for (int h2 = 0; h2 < 2; ++h2) {
                const float mn = m_r[mi][h2];
                const float a = alpha[mi][h2];
                float sum = 0.f;
#pragma unroll
                for (int nt = 0; nt < 4; ++nt) {
                    float p0 = exp2f((sacc[mi][nt][h2 * 2] - mn) * s2);
                    float p1 = exp2f((sacc[mi][nt][h2 * 2 + 1] - mn) * s2);
                    sacc[mi][nt][h2 * 2] = p0;
                    sacc[mi][nt][h2 * 2 + 1] = p1;
                    oacc[mi][nt][h2 * 2] *= a;
                    oacc[mi][nt][h2 * 2 + 1] *= a;
                    sum += p0 + p1;
                }
                sum += __shfl_xor_sync(0xffffffffu, sum, 1);
                sum += __shfl_xor_sync(0xffffffffu, sum, 2);
                if (c == 0) RED[wn * 128 + wm * 64 + mi * 16 + g + h2 * 8] = sum;
            }
        // write P planes to smem
#pragma unroll
        for (int mi = 0; mi < 4; ++mi)
#pragma unroll
            for (int nt = 0; nt < 4; ++nt) {
                const int r0 = wm * 64 + mi * 16 + g;
                const int cb = wn * 32 + nt * 8 + 2 * c;
                hf16 h0, l0, h1, l1;
                split2(sacc[mi][nt][0], h0, l0); split2(sacc[mi][nt][1], h1, l1);
                *(__half2*)(dyn + 102400 + r0 * 272 + cb * 2) = __halves2half2(h0, h1);
                *(__half2*)(dyn + 137216 + r0 * 272 + cb * 2) = __halves2half2(l0, l1);
                split2(sacc[mi][nt][2], h0, l0); split2(sacc[mi][nt][3], h1, l1);
                *(__half2*)(dyn + 102400 + (r0 + 8) * 272 + cb * 2) = __halves2half2(h0, h1);
                *(__half2*)(dyn + 137216 + (r0 + 8) * 272 + cb * 2) = __halves2half2(l0, l1);
            }
        __syncthreads();   // P + sums visible
#pragma unroll
        for (int mi = 0; mi < 4; ++mi)
#pragma unroll
            for (int h2 = 0; h2 < 2; ++h2) {
                const int row = wm * 64 + mi * 16 + g + h2 * 8;
                const float ls = RED[row] + RED[128 + row] + RED[256 + row] + RED[384 + row];
                l_r[mi][h2] = l_r[mi][h2] * alpha[mi][h2] + ls;
            }

        // ---- PV phase: 8 V-slabs (K=128 over t) ----
        for (int s = 0; s < 8; ++s) {
            cp_wait1(); __syncthreads();
            const uint32_t sb = smS + (uint32_t)((u % 3) * 8192);
            uint32_t vh4[2][4], vl4[2][4];
            ldsm4(vh4[0], sb + offB); ldsm4(vh4[1], sb + offB + 512);
            ldsm4(vl4[0], sb + 4096 + offB); ldsm4(vl4[1], sb + 4096 + offB + 512);
#pragma unroll
            for (int mi = 0; mi < 4; ++mi) {
                uint32_t ph[4], pl[4];
                ldsm4(ph, smP + offAp + mi * 4352 + s * 32);
                ldsm4(pl, smP + 34816 + offAp + mi * 4352 + s * 32);
#pragma unroll
                for (int nt = 0; nt < 4; ++nt) {
                    const int np = nt >> 1, hf2 = (nt & 1) * 2;
                    mma_f32(oacc[mi][nt], ph, vh4[np][hf2], vh4[np][hf2 + 1]);
                    mma_f16(cacc[mi][nt], ph, vl4[np][hf2], vl4[np][hf2 + 1]);
                    mma_f16(cacc[mi][nt], pl, vh4[np][hf2], vh4[np][hf2 + 1]);
                }
            }
            if (u + 2 < u_total) FL_ISSUE(u + 2);
            cp_commit(); ++u;
        }
        // promote PV cross terms (before next block's alpha rescale)
#pragma unroll
        for (int mi = 0; mi < 4; ++mi)
#pragma unroll
            for (int nt = 0; nt < 4; ++nt) addcross(oacc[mi][nt], cacc[mi][nt]);
    }
#undef FL_ISSUE

    // ---- epilogue: O / l -> ohead planes ----
    hf16* Cb = ohead + (size_t)(b * SEQ + m0) * DMODEL + h * D_V;
#pragma unroll
    for (int mi = 0; mi < 4; ++mi) {
        const int r0 = wm * 64 + mi * 16 + g;
        const float i0 = 1.f / l_r[mi][0], i1 = 1.f / l_r[mi][1];
#pragma unroll
        for (int nt = 0; nt < 4; ++nt) {
            const int cb = wn * 32 + nt * 8 + 2 * c;
            hf16 h0, l0, h1, l1;
            split2(oacc[mi][nt][0] * i0, h0, l0);
            split2(oacc[mi][nt][1] * i0, h1, l1);
            hf16* p = Cb + (size_t)r0 * DMODEL + cb;
            *(__half2*)p = __halves2half2(h0, h1);
            *(__half2*)(p + psOH) = __halves2half2(l0, l1);
            split2(oacc[mi][nt][2] * i1, h0, l0);
            split2(oacc[mi][nt][3] * i1, h1, l1);
            p = Cb + (size_t)(r0 + 8) * DMODEL + cb;
            *(__half2*)p = __halves2half2(h0, h1);
            *(__half2*)(p + psOH) = __halves2half2(l0, l1);
        }
    }
}

// ---------------------------- block reduction ------------------------------
__device__ __forceinline__ float blockReduce(float v, bool isMax) {
    __shared__ float sh[32];
    const int lane = threadIdx.x & 31, wid = threadIdx.x >> 5;
    __syncthreads();
#pragma unroll
    for (int o = 16; o > 0; o >>= 1) {
        float t = __shfl_down_sync(0xffffffffu, v, o);
        v = isMax ? fmaxf(v, t) : (v + t);
    }
    if (lane == 0) sh[wid] = v;
    __syncthreads();
    const int nw = blockDim.x >> 5;
    if (wid == 0) {
        v = (lane < nw) ? sh[lane] : (isMax ? -1e30f : 0.f);
#pragma unroll
        for (int o = 16; o > 0; o >>= 1) {
            float t = __shfl_down_sync(0xffffffffu, v, o);
            v = isMax ? fmaxf(v, t) : (v + t);
        }
        if (lane == 0) sh[0] = v;
    }
    __syncthreads();
    return sh[0];
}

// ------------------------------ aux kernels --------------------------------
__global__ void pack2_k(const float* __restrict__ in, hf16* __restrict__ out,
                        long long ps, int n) {
    for (int i = blockIdx.x * blockDim.x + threadIdx.x; i < n; i += gridDim.x * blockDim.x) {
        hf16 h, l; split2(in[i], h, l);
        out[i] = h; out[i + ps] = l;
    }
}

// fp32 [R][C] -> planes [C][R]
__global__ void packT2_k(const float* __restrict__ in, hf16* __restrict__ out,
                         long long ps, int R, int C) {
    __shared__ float t[32][33];
    const int c0 = blockIdx.x * 32, r0 = blockIdx.y * 32;
#pragma unroll
    for (int i = threadIdx.y; i < 32; i += 8)
        t[i][threadIdx.x] = in[(long long)(r0 + i) * C + c0 + threadIdx.x];
    __syncthreads();
#pragma unroll
    for (int i = threadIdx.y; i < 32; i += 8) {
        hf16 h, l; split2(t[threadIdx.x][i], h, l);
        long long o = (long long)(c0 + i) * R + r0 + threadIdx.x;
        out[o] = h; out[o + ps] = l;
    }
}

__global__ void rmsnorm_rows_k(hf16* x, long long ps, const float* __restrict__ w, int n) {
    long long base = (long long)blockIdx.x * n;
    float ss = 0.f;
    for (int i = threadIdx.x; i < n; i += blockDim.x) {
        float v = join2(x[base + i], x[base + i + ps]); ss += v * v;
    }
    ss = blockReduce(ss, false);
    float rn = rsqrtf(ss / (float)n + EPSF);
    for (int i = threadIdx.x; i < n; i += blockDim.x) {
        float v = join2(x[base + i], x[base + i + ps]) * rn * w[i];
        hf16 h, l; split2(v, h, l);
        x[base + i] = h; x[base + i + ps] = l;
    }
}

__global__ void kv_process_k(const hf16* __restrict__ kv, hf16* __restrict__ kext,
                             const float* __restrict__ w, const float* __restrict__ freqs) {
    const long long psKV = (long long)MS * KVD;
    const int m = blockIdx.x;
    const int s = m & (SEQ - 1);
    const hf16* kr = kv   + (long long)m * KVD;
    hf16*       ke = kext + (long long)m * KVD;
    float ss = 0.f;
    for (int i = threadIdx.x; i < KVLR; i += blockDim.x) {
        float v = join2(kr[i], kr[i + psKV]); ss += v * v;
    }
    ss = blockReduce(ss, false);
    float rn = rsqrtf(ss / (float)KVLR + EPSF);
    for (int i = threadIdx.x; i < KVLR; i += blockDim.x) {
        float v = join2(kr[i], kr[i + psKV]) * rn * w[i];
        hf16 h, l; split2(v, h, l);
        ke[i] = h; ke[i + psKV] = l;
    }
    if (threadIdx.x < 32) {
        const int i = threadIdx.x;
        float th = freqs[s * 32 + i];
        float co, sn; sincosf(th, &sn, &co);
        float x0 = join2(kr[KVLR + 2 * i], kr[KVLR + 2 * i + psKV]);
        float x1 = join2(kr[KVLR + 2 * i + 1], kr[KVLR + 2 * i + 1 + psKV]);
        hf16 h, l;
        split2(x0 * co - x1 * sn, h, l);
        ke[KVLR + 2 * i] = h; ke[KVLR + 2 * i + psKV] = l;
        split2(x0 * sn + x1 * co, h, l);
        ke[KVLR + 2 * i + 1] = h; ke[KVLR + 2 * i + 1 + psKV] = l;
    }
}

// rope q_pe in place inside g_q planes ([m][h*192+128 .. +191])
__global__ void rope_q_k(hf16* q, const float* __restrict__ freqs) {
    const long long psQ = (long long)MS * QDIM;
    const int m = blockIdx.x;
    const int s = m & (SEQ - 1);
    const int h = threadIdx.x >> 5;
    const int i = threadIdx.x & 31;
    float th = freqs[s * 32 + i];
    float co, sn; sincosf(th, &sn, &co);
    hf16* qr = q + (long long)m * QDIM + h * D_QK + D_NOPE;
    float x0 = join2(qr[2 * i], qr[2 * i + psQ]);
    float x1 = join2(qr[2 * i + 1], qr[2 * i + 1 + psQ]);
    hf16 hh, ll;
    split2(x0 * co - x1 * sn, hh, ll);
    qr[2 * i] = hh; qr[2 * i + psQ] = ll;
    split2(x0 * sn + x1 * co, hh, ll);
    qr[2 * i + 1] = hh; qr[2 * i + 1 + psQ] = ll;
}

// broadcast roped k_pe into kfull[b,h,s,128:192] for all heads
__global__ void pe_bcast_k(const hf16* __restrict__ kext, hf16* __restrict__ kfull) {
    const long long psKV = (long long)MS * KVD;
    const long long psKF = (long long)BSZ * NH * SEQ * D_QK;
    const int m = blockIdx.x;
    const int s = m & (SEQ - 1);
    const int b = m >> 11;
    const hf16* pe = kext + (long long)m * KVD + KVLR;
    for (int idx = threadIdx.x; idx < NH * D_ROPE; idx += blockDim.x) {
        const int h = idx >> 6, j = idx & 63;
        long long o = (((long long)b * NH + h) * SEQ + s) * D_QK + D_NOPE + j;
        kfull[o] = pe[j];
        kfull[o + psKF] = pe[j + psKV];
    }
}

// ------------------------------- host side ---------------------------------
static void launchGemm(const hf16* A, long long aPS, const hf16* B, long long bPS,
                       void* C, long long cPS,
                       int M, int N, int K,
                       long long lda, long long ldb, long long ldc,
                       int nb, int nInner,
                       long long aSb, long long aSh,
                       long long bSb, long long bSh,
                       long long cSb, long long cSh,
                       int causal, int outMode) {
    GemmP p;
    p.A = A; p.B = B; p.C = C;
    p.aPS = aPS; p.bPS = bPS; p.cPS = cPS;
    p.M = M; p.N = N; p.K = K;
    p.lda = lda; p.ldb = ldb; p.ldc = ldc;
    p.aSb = aSb; p.aSh = aSh; p.bSb = bSb; p.bSh = bSh; p.cSb = cSb; p.cSh = cSh;
    p.nInner = nInner; p.causal = causal; p.outMode = outMode;
    dim3 grid((N + 127) / 128, (M + 127) / 128, nb);
    gemm_hmma<<<grid, 256>>>(p);
}

extern "C" void kernel_launch(void* const* d_in, const int* in_sizes, int n_in,
                              void* d_out, int out_size) {
    const float* x         = (const float*)d_in[0];
    const float* freqs     = (const float*)d_in[1];
    const float* wq_a      = (const float*)d_in[3];
    const float* q_norm_w  = (const float*)d_in[4];
    const float* wq_b      = (const float*)d_in[5];
    const float* wkv_a     = (const float*)d_in[6];
    const float* kv_norm_w = (const float*)d_in[7];
    const float* wkv_b     = (const float*)d_in[8];
    const float* wo        = (const float*)d_in[9];
    float* out = (float*)d_out;

    cudaFuncSetAttribute(flash_k, cudaFuncAttributeMaxDynamicSharedMemorySize, FL_SMEM);

    hf16 *xp, *wqaT, *wkvaT, *wqbT, *wkvbT, *woT;
    hf16 *qa, *q, *kv, *kext, *kfull, *vT, *ohead;
    cudaGetSymbolAddress((void**)&xp,     g_xp);
    cudaGetSymbolAddress((void**)&wqaT,   g_wqaT);
    cudaGetSymbolAddress((void**)&wkvaT,  g_wkvaT);
    cudaGetSymbolAddress((void**)&wqbT,   g_wqbT);
    cudaGetSymbolAddress((void**)&wkvbT,  g_wkvbT);
    cudaGetSymbolAddress((void**)&woT,    g_woT);
    cudaGetSymbolAddress((void**)&qa,     g_qa);
    cudaGetSymbolAddress((void**)&q,      g_q);
    cudaGetSymbolAddress((void**)&kv,     g_kv);
    cudaGetSymbolAddress((void**)&kext,   g_kext);
    cudaGetSymbolAddress((void**)&kfull,  g_kfull);
    cudaGetSymbolAddress((void**)&vT,     g_vT);
    cudaGetSymbolAddress((void**)&ohead,  g_ohead);

    const float scale = 1.0f / sqrtf((float)D_QK);
    const float s2 = scale * 1.4426950408889634f;   // scale * log2(e)

    // plane strides
    const long long psX   = (long long)MS * DMODEL;
    const long long psWQA = (long long)QLR * DMODEL;
    const long long psWKA = (long long)KVD * DMODEL;
    const long long psWQB = (long long)QDIM * QLR;
    const long long psWBT = (long long)NH * HDIM * KVLR;
    const long long psWO  = (long long)DMODEL * DMODEL;
    const long long psQA  = (long long)MS * QLR;
    const long long psQ   = (long long)MS * QDIM;
    const long long psKV  = (long long)MS * KVD;
    const long long psKF  = (long long)BSZ * NH * SEQ * D_QK;
    const long long psVT  = (long long)BSZ * NH * D_V * SEQ;
    const long long psOH  = (long long)MS * DMODEL;

    // ---- pack inputs into planes ----
    pack2_k<<<512, 256>>>(x, xp, psX, MS * DMODEL);
    packT2_k<<<dim3(QLR / 32, DMODEL / 32), dim3(32, 8)>>>(wq_a, wqaT, psWQA, DMODEL, QLR);
    packT2_k<<<dim3(KVD / 32, DMODEL / 32), dim3(32, 8)>>>(wkv_a, wkvaT, psWKA, DMODEL, KVD);
    packT2_k<<<dim3(QDIM / 32, QLR / 32), dim3(32, 8)>>>(wq_b, wqbT, psWQB, QLR, QDIM);
    packT2_k<<<dim3((NH * HDIM) / 32, KVLR / 32), dim3(32, 8)>>>(wkv_b, wkvbT, psWBT, KVLR, NH * HDIM);
    packT2_k<<<dim3(DMODEL / 32, DMODEL / 32), dim3(32, 8)>>>(wo, woT, psWO, DMODEL, DMODEL);

    // 1. qa = x @ wq_a
    launchGemm(xp, psX, wqaT, psWQA, qa, psQA, MS, QLR, DMODEL,
               DMODEL, DMODEL, QLR, 1, 1, 0, 0, 0, 0, 0, 0, 0, 1);
    // 2. kv = x @ wkv_a (N=576)
    launchGemm(xp, psX, wkvaT, psWKA, kv, psKV, MS, KVD, DMODEL,
               DMODEL, DMODEL, KVD, 1, 1, 0, 0, 0, 0, 0, 0, 0, 1);
    // 3. rmsnorm(qa)
    rmsnorm_rows_k<<<MS, 256>>>(qa, psQA, q_norm_w, QLR);
    // 4. kext = [rmsnorm(latent), rope(k_pe)]
    kv_process_k<<<MS, 256>>>(kv, kext, kv_norm_w, freqs);
    // 5. q = qa @ wq_b
    launchGemm(qa, psQA, wqbT, psWQB, q, psQ, MS, QDIM, QLR,
               QLR, QLR, QDIM, 1, 1, 0, 0, 0, 0, 0, 0, 0, 1);
    // 6. rope q_pe in place
    rope_q_k<<<MS, NH * 32>>>(q, freqs);
    // 7. k_abs: kfull[b,h,s,0:128] = kv_cache @ Wuk[h]^T
    launchGemm(kext, psKV, wkvbT, psWBT, kfull, psKF,
               SEQ, D_NOPE, KVLR,
               KVD, KVLR, D_QK,
               BSZ * NH, NH,
               (long long)SEQ * KVD, 0,
               0, (long long)HDIM * KVLR,
               (long long)NH * SEQ * D_QK, (long long)SEQ * D_QK,
               0, 1);
    // 8. broadcast roped k_pe into kfull[...,128:192]
    pe_bcast_k<<<MS, 256>>>(kext, kfull);
    // 9. vT[b,h,d,t] = Wuv[h] @ kv_cache^T
    launchGemm(wkvbT + (long long)D_NOPE * KVLR, psWBT, kext, psKV, vT, psVT,
               D_V, SEQ, KVLR,
               KVLR, KVD, SEQ,
               BSZ * NH, NH,
               0, (long long)HDIM * KVLR,
               (long long)SEQ * KVD, 0,
               (long long)NH * D_V * SEQ, (long long)D_V * SEQ,
               0, 1);
    // 10. fused flash attention -> ohead planes
    flash_k<<<dim3(16, BSZ * NH), 256, FL_SMEM>>>(q, kfull, vT, ohead, s2);
    // 11. out = ohead @ wo (fp32)
    launchGemm(ohead, psOH, woT, psWO, out, 0, MS, DMODEL, DMODEL,
               DMODEL, DMODEL, DMODEL, 1, 1, 0, 0, 0, 0, 0, 0, 0, 0);
}

// round 10
// speedup vs baseline: 1.0805x; 1.0805x over previous
#include <cuda_runtime.h>
#include <cuda_fp16.h>
#include <math.h>
#include <stdint.h>

// ---------------------------------------------------------------------------
// MLA forward, per-head expanded attention + fused flash attention (64-row
// q-tiles, 2 CTAs/SM so softmax overlaps MMA across CTAs).
// GEMMs: fp16x3 emulated fp32 (hi/lo fp16 planes), mma.sync m16n8k16,
// all-f32 accumulators, cp.async 3-stage pipeline, ldmatrix fragment loads.
// ---------------------------------------------------------------------------

#define BSZ    2
#define SEQ    2048
#define DMODEL 2048
#define NH     16
#define QLR    1536
#define KVLR   512
#define D_NOPE 128
#define D_ROPE 64
#define D_QK   192
#define D_V    128
#define MS     (BSZ*SEQ)          /* 4096 */
#define QDIM   (NH*D_QK)          /* 3072 */
#define KVD    (KVLR + D_ROPE)    /* 576  */
#define HDIM   (D_NOPE + D_V)     /* 256  */
#define EPSF   1e-6f

typedef __half hf16;

// ---------------- scratch: every tensor is [2][elems] fp16 planes ----------
__device__ hf16 g_xp   [2 * (size_t)MS * DMODEL];
__device__ hf16 g_wqaT [2 * (size_t)QLR * DMODEL];
__device__ hf16 g_wkvaT[2 * (size_t)KVD * DMODEL];
__device__ hf16 g_wqbT [2 * (size_t)QDIM * QLR];
__device__ hf16 g_wkvbT[2 * (size_t)NH * HDIM * KVLR];
__device__ hf16 g_woT  [2 * (size_t)DMODEL * DMODEL];
__device__ hf16 g_qa   [2 * (size_t)MS * QLR];
__device__ hf16 g_q    [2 * (size_t)MS * QDIM];
__device__ hf16 g_kv   [2 * (size_t)MS * KVD];
__device__ hf16 g_kext [2 * (size_t)MS * KVD];
__device__ hf16 g_kabs [2 * (size_t)BSZ * NH * SEQ * D_NOPE];
__device__ hf16 g_vT   [2 * (size_t)BSZ * NH * D_V * SEQ];
__device__ hf16 g_ohead[2 * (size_t)MS * DMODEL];

// ------------------------------ helpers -------------------------------------
__device__ __forceinline__ void split2(float x, hf16& h, hf16& l) {
    h = __float2half_rn(x);
    l = __float2half_rn(x - __half2float(h));
}
__device__ __forceinline__ float join2(hf16 h, hf16 l) {
    return __half2float(h) + __half2float(l);
}
__device__ __forceinline__ void cp16(uint32_t smem, const void* g, int srcBytes) {
    asm volatile("cp.async.cg.shared.global [%0], [%1], 16, %2;"
                 :: "r"(smem), "l"(g), "r"(srcBytes));
}
__device__ __forceinline__ void cp_commit() { asm volatile("cp.async.commit_group;"); }
__device__ __forceinline__ void cp_wait1()  { asm volatile("cp.async.wait_group 1;"); }

__device__ __forceinline__ void ldsm4(uint32_t* r, uint32_t addr) {
    asm volatile("ldmatrix.sync.aligned.m8n8.x4.shared.b16 {%0,%1,%2,%3}, [%4];"
                 : "=r"(r[0]), "=r"(r[1]), "=r"(r[2]), "=r"(r[3]) : "r"(addr));
}
__device__ __forceinline__ void mma_f32(float* d, const uint32_t* a,
                                        uint32_t b0, uint32_t b1) {
    asm volatile(
        "mma.sync.aligned.m16n8k16.row.col.f32.f16.f16.f32 "
        "{%0,%1,%2,%3}, {%4,%5,%6,%7}, {%8,%9}, {%0,%1,%2,%3};"
        : "+f"(d[0]), "+f"(d[1]), "+f"(d[2]), "+f"(d[3])
        : "r"(a[0]), "r"(a[1]), "r"(a[2]), "r"(a[3]), "r"(b0), "r"(b1));
}

// ----------------------------- GEMM kernel ----------------------------------
// C = A * B^T. A: [M][K] planes (hi at A, lo at A+aPS), row stride lda.
// B: [N][K] planes, row stride ldb. CTA tile 128x128, K-slab 16, 8 warps,
// warp tile 64x32. outMode 0: fp32 C. outMode 1: fp16 planes C (lo at +cPS).
struct GemmP {
    const hf16 *A, *B; void* C;
    long long aPS, bPS, cPS;
    int M, N, K;
    long long lda, ldb, ldc;
    long long aSb, aSh, bSb, bSh, cSb, cSh;
    int nInner, causal, outMode;
};

// stage: Ah[0,4096) Al[4096,8192) Bh[8192,12288) Bl[12288,16384)
#define STG_BYTES 16384

__global__ __launch_bounds__(256, 2) void gemm_hmma(GemmP p) {
    __shared__ __align__(16) hf16 stg[3][4][128 * 16];   // 48KB

    const int m0 = blockIdx.y * 128;
    const int n0 = blockIdx.x * 128;
    if (p.causal == 1 && n0 >= m0 + 128) return;

    const int z  = blockIdx.z;
    const int zb = z / p.nInner;
    const int zh = z - zb * p.nInner;
    const hf16* A = p.A + zb * p.aSb + zh * p.aSh;
    const hf16* B = p.B + zb * p.bSb + zh * p.bSh;

    int kEnd = p.K;
    if (p.causal == 2) { int km = m0 + 128; if (km < kEnd) kEnd = km; }
    const int nSlab = kEnd >> 4;

    const int tid  = threadIdx.x;
    const int lane = tid & 31;
    const int warp = tid >> 5;
    const int wm   = warp >> 2;    // 0..1
    const int wn   = warp & 3;     // 0..3

    const uint32_t smBase = (uint32_t)__cvta_generic_to_shared(&stg[0][0][0]);

    const int r  = tid >> 1;
    const int cc = tid & 1;
    const uint32_t pOff = (uint32_t)(r * 32 + ((cc ^ ((r >> 2) & 1)) << 4));

    int mr = m0 + r;
    const bool aok = mr < p.M;
    if (!aok) mr = m0;
    const hf16* gA0 = A + (size_t)mr * p.lda + cc * 8;
    const hf16* gA1 = gA0 + p.aPS;
    const int asz = aok ? 16 : 0;
    int nr = n0 + r;
    const bool bok = nr < p.N;
    if (!bok) nr = n0;
    const hf16* gB0 = B + (size_t)nr * p.ldb + cc * 8;
    const hf16* gB1 = gB0 + p.bPS;
    const int bsz = bok ? 16 : 0;

#define ISSUE(S)                                                               \
    do {                                                                       \
        uint32_t sb = smBase + (uint32_t)(((S) % 3) * STG_BYTES);              \
        const size_t ko = (size_t)(S) * 16;                                    \
        cp16(sb + pOff,         gA0 + ko, asz);                                \
        cp16(sb + 4096 + pOff,  gA1 + ko, asz);                                \
        cp16(sb + 8192 + pOff,  gB0 + ko, bsz);                                \
        cp16(sb + 12288 + pOff, gB1 + ko, bsz);                                \
    } while (0)

    const int rowA = wm * 64 + (lane & 7) + ((lane >> 3) & 1) * 8;
    const int cA   = lane >> 4;
    const uint32_t offA = (uint32_t)(rowA * 32 + ((cA ^ ((rowA >> 2) & 1)) << 4));
    const int rowB = wn * 32 + (lane & 7) + ((lane >> 4) << 3);
    const int cB   = (lane >> 3) & 1;
    const uint32_t offB = (uint32_t)(rowB * 32 + ((cB ^ ((rowB >> 2) & 1)) << 4));

    float acc[4][4][4];
#pragma unroll
    for (int i = 0; i < 4; ++i)
#pragma unroll
        for (int j = 0; j < 4; ++j)
#pragma unroll
            for (int l = 0; l < 4; ++l) acc[i][j][l] = 0.f;

    ISSUE(0); cp_commit();
    if (nSlab > 1) ISSUE(1);
    cp_commit();

    for (int it = 0; it < nSlab; ++it) {
        cp_wait1();
        __syncthreads();

        const uint32_t sb   = smBase + (uint32_t)((it % 3) * STG_BYTES);
        const uint32_t aAdr = sb + offA;
        const uint32_t bAdr = sb + 8192 + offB;

        uint32_t bh[2][4], bl[2][4];
        ldsm4(bh[0], bAdr);
        ldsm4(bh[1], bAdr + 512);
        ldsm4(bl[0], bAdr + 4096);
        ldsm4(bl[1], bAdr + 4096 + 512);

#pragma unroll
        for (int mi = 0; mi < 4; ++mi) {
            uint32_t ah[4], al[4];
            ldsm4(ah, aAdr + mi * 512);
            ldsm4(al, aAdr + 4096 + mi * 512);
#pragma unroll
            for (int nt = 0; nt < 4; ++nt) {
                const int np = nt >> 1, hf = (nt & 1) * 2;
                const uint32_t b0h = bh[np][hf], b1h = bh[np][hf + 1];
                const uint32_t b0l = bl[np][hf], b1l = bl[np][hf + 1];
                mma_f32(acc[mi][nt], ah, b0h, b1h);
                mma_f32(acc[mi][nt], ah, b0l, b1l);
                mma_f32(acc[mi][nt], al, b0h, b1h);
            }
        }

        if (it + 2 < nSlab) ISSUE(it + 2);
        cp_commit();
    }
#undef ISSUE

    const int g = lane >> 2;
    const int c = lane & 3;
    if (p.outMode == 0) {
        float* C = (float*)p.C + zb * p.cSb + zh * p.cSh;
#pragma unroll
        for (int mi = 0; mi < 4; ++mi) {
            const int gm = m0 + wm * 64 + mi * 16 + g;
            if (gm >= p.M) continue;
            float* r0 = C + (long long)gm * p.ldc;
            float* r1 = r0 + 8 * p.ldc;
#pragma unroll
            for (int nt = 0; nt < 4; ++nt) {
                const int gn = n0 + wn * 32 + nt * 8 + 2 * c;
                if (gn < p.N) {
                    *(float2*)(r0 + gn) = make_float2(acc[mi][nt][0], acc[mi][nt][1]);
                    *(float2*)(r1 + gn) = make_float2(acc[mi][nt][2], acc[mi][nt][3]);
                }
            }
        }
    } else {
        hf16* Ch = (hf16*)p.C + zb * p.cSb + zh * p.cSh;
        hf16* Cl = Ch + p.cPS;
#pragma unroll
        for (int mi = 0; mi < 4; ++mi) {
            const int gm = m0 + wm * 64 + mi * 16 + g;
            if (gm >= p.M) continue;
            const long long ro0 = (long long)gm * p.ldc;
            const long long ro1 = ro0 + 8 * p.ldc;
#pragma unroll
            for (int nt = 0; nt < 4; ++nt) {
                const int gn = n0 + wn * 32 + nt * 8 + 2 * c;
                if (gn < p.N) {
                    hf16 h0, l0, h1, l1;
                    split2(acc[mi][nt][0], h0, l0);
                    split2(acc[mi][nt][1], h1, l1);
                    *(__half2*)(Ch + ro0 + gn) = __halves2half2(h0, h1);
                    *(__half2*)(Cl + ro0 + gn) = __halves2half2(l0, l1);
                    split2(acc[mi][nt][2], h0, l0);
                    split2(acc[mi][nt][3], h1, l1);
                    *(__half2*)(Ch + ro1 + gn) = __halves2half2(h0, h1);
                    *(__half2*)(Cl + ro1 + gn) = __halves2half2(l0, l1);
                }
            }
        }
    }
}

// --------------------------- flash attention --------------------------------
// TM=64 q-rows per CTA, 2 CTAs/SM. grid (32 q-blocks, 32 bh).
// K-nope streamed from kabs, roped pe from kext, V from vT.
// smem layout (bytes):
//   Qh 0..25600   Ql 25600..51200        (64 rows x 400B, 192 cols used)
//   Ph 51200..68608  Pl 68608..86016     (64 rows x 272B, 128 cols used)
//   stages 86016 + s*8192 (Bh 4KB, Bl 4KB), 3 stages -> 110592
//   RED 110592..111616 (float[4][64])
#define FL_SMEM 111616

__global__ __launch_bounds__(256, 2) void flash_k(
    const hf16* __restrict__ q, const hf16* __restrict__ kabs,
    const hf16* __restrict__ kext, const hf16* __restrict__ vT,
    hf16* __restrict__ ohead, float s2) {
    extern __shared__ __align__(16) char dyn[];
    const int tid = threadIdx.x, lane = tid & 31, warp = tid >> 5;
    const int wm = warp >> 2, wn = warp & 3, g = lane >> 2, c = lane & 3;
    const int iq = 31 - blockIdx.x;       // heavy blocks first
    const int bh = blockIdx.y, b = bh >> 4, h = bh & 15;
    const int m0 = iq * 64;
    const int nkv = (iq >> 1) + 1;
    const long long psQ  = (long long)MS * QDIM;
    const long long psKA = (long long)BSZ * NH * SEQ * D_NOPE;
    const long long psKV = (long long)MS * KVD;
    const long long psVT = (long long)BSZ * NH * D_V * SEQ;
    const long long psOH = (long long)MS * DMODEL;

    const uint32_t smb = (uint32_t)__cvta_generic_to_shared(dyn);
    const uint32_t smQ = smb;
    const uint32_t smP = smb + 51200;
    const uint32_t smS = smb + 86016;
    float* RED = (float*)(dyn + 110592);

    // ---- Q block load: 64 rows, 2 planes; 4 threads/row ----
    {
        const int r = tid >> 2, sub = tid & 3;
        const int plane = sub >> 1, half = sub & 1;
        const hf16* src = q + ((size_t)(b * SEQ + m0 + r)) * QDIM + h * D_QK
                            + half * 96 + (size_t)plane * psQ;
        const uint32_t d0 = smQ + (uint32_t)(plane * 25600 + r * 400 + half * 192);
#pragma unroll
        for (int ch = 0; ch < 12; ++ch) cp16(d0 + ch * 16, src + ch * 8, 16);
        cp_commit();
    }

    const int prow = tid >> 1, pcc = tid & 1;
    const uint32_t pOff = (uint32_t)(prow * 32 + ((pcc ^ ((prow >> 2) & 1)) << 4));
    const hf16* ka = kabs + (size_t)bh * SEQ * D_NOPE;
    const hf16* ke = kext + (size_t)b * SEQ * KVD;
    const hf16* vt = vT + (size_t)bh * D_V * SEQ;
    const int u_total = 20 * nkv;

    // slab u -> (kv block j = u/20, s = u%20):
    //   s<8: K-nope from kabs; s in 8..11: pe from kext; s>=12: V-slab
#define FL_ISSUE(U)                                                            \
    do {                                                                       \
        const int _j = (U) / 20, _s = (U) % 20;                                \
        uint32_t _sb = smS + (uint32_t)(((U) % 3) * 8192);                     \
        const hf16* _s0; long long _ps;                                        \
        if (_s < 8) {                                                          \
            _s0 = ka + ((size_t)(_j * 128 + prow)) * D_NOPE + _s * 16 + pcc * 8; \
            _ps = psKA;                                                        \
        } else if (_s < 12) {                                                  \
            _s0 = ke + ((size_t)(_j * 128 + prow)) * KVD + KVLR                \
                     + (_s - 8) * 16 + pcc * 8;                                \
            _ps = psKV;                                                        \
        } else {                                                               \
            _s0 = vt + (size_t)prow * SEQ + _j * 128 + (_s - 12) * 16 + pcc * 8; \
            _ps = psVT;                                                        \
        }                                                                      \
        cp16(_sb + pOff, _s0, 16);                                             \
        cp16(_sb + 4096 + pOff, _s0 + _ps, 16);                                \
    } while (0)

    FL_ISSUE(0); cp_commit();
    FL_ISSUE(1); cp_commit();

    // consumer fragment offsets
    const int rowA = wm * 32 + (lane & 7) + ((lane >> 3) & 1) * 8;
    const int cA   = lane >> 4;
    const uint32_t offAq = (uint32_t)(rowA * 400 + cA * 16);
    const uint32_t offAp = (uint32_t)(rowA * 272 + cA * 16);
    const int rowB = wn * 32 + (lane & 7) + ((lane >> 4) << 3);
    const int cB   = (lane >> 3) & 1;
    const uint32_t offB = (uint32_t)(rowB * 32 + ((cB ^ ((rowB >> 2) & 1)) << 4));

    float oacc[2][4][4];
    float m_r[2][2], l_r[2][2];
#pragma unroll
    for (int mi = 0; mi < 2; ++mi) {
#pragma unroll
        for (int nt = 0; nt < 4; ++nt)
#pragma unroll
            for (int k = 0; k < 4; ++k) oacc[mi][nt][k] = 0.f;
        m_r[mi][0] = m_r[mi][1] = -1e30f;
        l_r[mi][0] = l_r[mi][1] = 0.f;
    }

    int u = 0;
    for (int j = 0; j < nkv; ++j) {
        float sacc[2][4][4];
#pragma unroll
        for (int mi = 0; mi < 2; ++mi)
#pragma unroll
            for (int nt = 0; nt < 4; ++nt)
#pragma unroll
                for (int k = 0; k < 4; ++k) sacc[mi][nt][k] = 0.f;

        // ---- S phase: 12 K-slabs (K=192) ----
        for (int s = 0; s < 12; ++s) {
            cp_wait1(); __syncthreads();
            const uint32_t sb = smS + (uint32_t)((u % 3) * 8192);
            uint32_t bh4[2][4], bl4[2][4];
            ldsm4(bh4[0], sb + offB); ldsm4(bh4[1], sb + offB + 512);
            ldsm4(bl4[0], sb + 4096 + offB); ldsm4(bl4[1], sb + 4096 + offB + 512);
#pragma unroll
            for (int mi = 0; mi < 2; ++mi) {
                uint32_t ah[4], al[4];
                ldsm4(ah, smQ + offAq + mi * 6400 + s * 32);
                ldsm4(al, smQ + 25600 + offAq + mi * 6400 + s * 32);
#pragma unroll
                for (int nt = 0; nt < 4; ++nt) {
                    const int np = nt >> 1, hf2 = (nt & 1) * 2;
                    mma_f32(sacc[mi][nt], ah, bh4[np][hf2], bh4[np][hf2 + 1]);
                    mma_f32(sacc[mi][nt], ah, bl4[np][hf2], bl4[np][hf2 + 1]);
                    mma_f32(sacc[mi][nt], al, bh4[np][hf2], bh4[np][hf2 + 1]);
                }
            }
            if (u + 2 < u_total) FL_ISSUE(u + 2);
            cp_commit(); ++u;
        }

        // ---- causal mask on last kv block ----
        if (j == nkv - 1) {
#pragma unroll
            for (int mi = 0; mi < 2; ++mi)
#pragma unroll
                for (int nt = 0; nt < 4; ++nt)
#pragma unroll
                    for (int k = 0; k < 4; ++k) {
                        const int rl = m0 + wm * 32 + mi * 16 + g + (k >> 1) * 8;
                        const int cl = j * 128 + wn * 32 + nt * 8 + 2 * c + (k & 1);
                        if (cl > rl) sacc[mi][nt][k] = -1e30f;
                    }
        }

        // ---- online softmax ----
        float alpha[2][2];
#pragma unroll
        for (int mi = 0; mi < 2; ++mi)
#pragma unroll
            for (int h2 = 0; h2 < 2; ++h2) {
                float v = fmaxf(fmaxf(sacc[mi][0][h2 * 2], sacc[mi][0][h2 * 2 + 1]),
                                fmaxf(sacc[mi][1][h2 * 2], sacc[mi][1][h2 * 2 + 1]));
                v = fmaxf(v, fmaxf(fmaxf(sacc[mi][2][h2 * 2], sacc[mi][2][h2 * 2 + 1]),
                                   fmaxf(sacc[mi][3][h2 * 2], sacc[mi][3][h2 * 2 + 1])));
                v = fmaxf(v, __shfl_xor_sync(0xffffffffu, v, 1));
                v = fmaxf(v, __shfl_xor_sync(0xffffffffu, v, 2));
                if (c == 0) RED[wn * 64 + wm * 32 + mi * 16 + g + h2 * 8] = v;
            }
        __syncthreads();
#pragma unroll
        for (int mi = 0; mi < 2; ++mi)
#pragma unroll
            for (int h2 = 0; h2 < 2; ++h2) {
                const int row = wm * 32 + mi * 16 + g + h2 * 8;
                float mrow = fmaxf(fmaxf(RED[row], RED[64 + row]),
                                   fmaxf(RED[128 + row], RED[192 + row]));
                float mnew = fmaxf(m_r[mi][h2], mrow);
                alpha[mi][h2] = exp2f((m_r[mi][h2] - mnew) * s2);
                m_r[mi][h2] = mnew;
            }
        __syncthreads();   // RED reads done before sum-round rewrite
#pragma unroll
        for (int mi = 0; mi < 2; ++mi)
#pragma unroll
            for (int h2 = 0; h2 < 2; ++h2) {
                const float mn = m_r[mi][h2];
                const float a = alpha[mi][h2];
                float sum = 0.f;
#pragma unroll
                for (int nt = 0; nt < 4; ++nt) {
                    float p0 = exp2f((sacc[mi][nt][h2 * 2] - mn) * s2);
                    float p1 = exp2f((sacc[mi][nt][h2 * 2 + 1] - mn) * s2);
                    sacc[mi][nt][h2 * 2] = p0;
                    sacc[mi][nt][h2 * 2 + 1] = p1;
                    oacc[mi][nt][h2 * 2] *= a;
                    oacc[mi][nt][h2 * 2 + 1] *= a;
                    sum += p0 + p1;
                }
                sum += __shfl_xor_sync(0xffffffffu, sum, 1);
                sum += __shfl_xor_sync(0xffffffffu, sum, 2);
                if (c == 0) RED[wn * 64 + wm * 32 + mi * 16 + g + h2 * 8] = sum;
            }
        // write P planes to smem
#pragma unroll
        for (int mi = 0; mi < 2; ++mi)
#pragma unroll
            for (int nt = 0; nt < 4; ++nt) {
                const int r0 = wm * 32 + mi * 16 + g;
                const int cb = wn * 32 + nt * 8 + 2 * c;
                hf16 h0, l0, h1, l1;
                split2(sacc[mi][nt][0], h0, l0); split2(sacc[mi][nt][1], h1, l1);
                *(__half2*)(dyn + 51200 + r0 * 272 + cb * 2) = __halves2half2(h0, h1);
                *(__half2*)(dyn + 68608 + r0 * 272 + cb * 2) = __halves2half2(l0, l1);
                split2(sacc[mi][nt][2], h0, l0); split2(sacc[mi][nt][3], h1, l1);
                *(__half2*)(dyn + 51200 + (r0 + 8) * 272 + cb * 2) = __halves2half2(h0, h1);
                *(__half2*)(dyn + 68608 + (r0 + 8) * 272 + cb * 2) = __halves2half2(l0, l1);
            }
        __syncthreads();   // P + sums visible
#pragma unroll
        for (int mi = 0; mi < 2; ++mi)
#pragma unroll
            for (int h2 = 0; h2 < 2; ++h2) {
                const int row = wm * 32 + mi * 16 + g + h2 * 8;
                const float ls = RED[row] + RED[64 + row] + RED[128 + row] + RED[192 + row];
                l_r[mi][h2] = l_r[mi][h2] * alpha[mi][h2] + ls;
            }

        // ---- PV phase: 8 V-slabs (K=128 over t) ----
        for (int s = 0; s < 8; ++s) {
            cp_wait1(); __syncthreads();
            const uint32_t sb = smS + (uint32_t)((u % 3) * 8192);
            uint32_t vh4[2][4], vl4[2][4];
            ldsm4(vh4[0], sb + offB); ldsm4(vh4[1], sb + offB + 512);
            ldsm4(vl4[0], sb + 4096 + offB); ldsm4(vl4[1], sb + 4096 + offB + 512);
#pragma unroll
            for (int mi = 0; mi < 2; ++mi) {
                uint32_t ph[4], pl[4];
                ldsm4(ph, smP + offAp + mi * 4352 + s * 32);
                ldsm4(pl, smP + 17408 + offAp + mi * 4352 + s * 32);
#pragma unroll
                for (int nt = 0; nt < 4; ++nt) {
                    const int np = nt >> 1, hf2 = (nt & 1) * 2;
                    mma_f32(oacc[mi][nt], ph, vh4[np][hf2], vh4[np][hf2 + 1]);
                    mma_f32(oacc[mi][nt], ph, vl4[np][hf2], vl4[np][hf2 + 1]);
                    mma_f32(oacc[mi][nt], pl, vh4[np][hf2], vh4[np][hf2 + 1]);
                }
            }
            if (u + 2 < u_total) FL_ISSUE(u + 2);
            cp_commit(); ++u;
        }
    }
#undef FL_ISSUE

    // ---- epilogue: O / l -> ohead planes ----
    hf16* Cb = ohead + (size_t)(b * SEQ + m0) * DMODEL + h * D_V;
#pragma unroll
    for (int mi = 0; mi < 2; ++mi) {
        const int r0 = wm * 32 + mi * 16 + g;
        const float i0 = 1.f / l_r[mi][0], i1 = 1.f / l_r[mi][1];
#pragma unroll
        for (int nt = 0; nt < 4; ++nt) {
            const int cb = wn * 32 + nt * 8 + 2 * c;
            hf16 h0, l0, h1, l1;
            split2(oacc[mi][nt][0] * i0, h0, l0);
            split2(oacc[mi][nt][1] * i0, h1, l1);
            hf16* p = Cb + (size_t)r0 * DMODEL + cb;
            *(__half2*)p = __halves2half2(h0, h1);
            *(__half2*)(p + psOH) = __halves2half2(l0, l1);
            split2(oacc[mi][nt][2] * i1, h0, l0);
            split2(oacc[mi][nt][3] * i1, h1, l1);
            p = Cb + (size_t)(r0 + 8) * DMODEL + cb;
            *(__half2*)p = __halves2half2(h0, h1);
            *(__half2*)(p + psOH) = __halves2half2(l0, l1);
        }
    }
}

// ---------------------------- block reduction ------------------------------
__device__ __forceinline__ float blockReduce(float v, bool isMax) {
    __shared__ float sh[32];
    const int lane = threadIdx.x & 31, wid = threadIdx.x >> 5;
    __syncthreads();
#pragma unroll
    for (int o = 16; o > 0; o >>= 1) {
        float t = __shfl_down_sync(0xffffffffu, v, o);
        v = isMax ? fmaxf(v, t) : (v + t);
    }
    if (lane == 0) sh[wid] = v;
    __syncthreads();
    const int nw = blockDim.x >> 5;
    if (wid == 0) {
        v = (lane < nw) ? sh[lane] : (isMax ? -1e30f : 0.f);
#pragma unroll
        for (int o = 16; o > 0; o >>= 1) {
            float t = __shfl_down_sync(0xffffffffu, v, o);
            v = isMax ? fmaxf(v, t) : (v + t);
        }
        if (lane == 0) sh[0] = v;
    }
    __syncthreads();
    return sh[0];
}

// ------------------------------ aux kernels --------------------------------
__global__ void pack2_k(const float* __restrict__ in, hf16* __restrict__ out,
                        long long ps, int n) {
    for (int i = blockIdx.x * blockDim.x + threadIdx.x; i < n; i += gridDim.x * blockDim.x) {
        hf16 h, l; split2(in[i], h, l);
        out[i] = h; out[i + ps] = l;
    }
}

// fp32 [R][C] -> planes [C][R]
__global__ void packT2_k(const float* __restrict__ in, hf16* __restrict__ out,
                         long long ps, int R, int C) {
    __shared__ float t[32][33];
    const int c0 = blockIdx.x * 32, r0 = blockIdx.y * 32;
#pragma unroll
    for (int i = threadIdx.y; i < 32; i += 8)
        t[i][threadIdx.x] = in[(long long)(r0 + i) * C + c0 + threadIdx.x];
    __syncthreads();
#pragma unroll
    for (int i = threadIdx.y; i < 32; i += 8) {
        hf16 h, l; split2(t[threadIdx.x][i], h, l);
        long long o = (long long)(c0 + i) * R + r0 + threadIdx.x;
        out[o] = h; out[o + ps] = l;
    }
}

__global__ void rmsnorm_rows_k(hf16* x, long long ps, const float* __restrict__ w, int n) {
    long long base = (long long)blockIdx.x * n;
    float ss = 0.f;
    for (int i = threadIdx.x; i < n; i += blockDim.x) {
        float v = join2(x[base + i], x[base + i + ps]); ss += v * v;
    }
    ss = blockReduce(ss, false);
    float rn = rsqrtf(ss / (float)n + EPSF);
    for (int i = threadIdx.x; i < n; i += blockDim.x) {
        float v = join2(x[base + i], x[base + i + ps]) * rn * w[i];
        hf16 h, l; split2(v, h, l);
        x[base + i] = h; x[base + i + ps] = l;
    }
}

__global__ void kv_process_k(const hf16* __restrict__ kv, hf16* __restrict__ kext,
                             const float* __restrict__ w, const float* __restrict__ freqs) {
    const long long psKV = (long long)MS * KVD;
    const int m = blockIdx.x;
    const int s = m & (SEQ - 1);
    const hf16* kr = kv   + (long long)m * KVD;
    hf16*       ke = kext + (long long)m * KVD;
    float ss = 0.f;
    for (int i = threadIdx.x; i < KVLR; i += blockDim.x) {
        float v = join2(kr[i], kr[i + psKV]); ss += v * v;
    }
    ss = blockReduce(ss, false);
    float rn = rsqrtf(ss / (float)KVLR + EPSF);
    for (int i = threadIdx.x; i < KVLR; i += blockDim.x) {
        float v = join2(kr[i], kr[i + psKV]) * rn * w[i];
        hf16 h, l; split2(v, h, l);
        ke[i] = h; ke[i + psKV] = l;
    }
    if (threadIdx.x < 32) {
        const int i = threadIdx.x;
        float th = freqs[s * 32 + i];
        float co, sn; sincosf(th, &sn, &co);
        float x0 = join2(kr[KVLR + 2 * i], kr[KVLR + 2 * i + psKV]);
        float x1 = join2(kr[KVLR + 2 * i + 1], kr[KVLR + 2 * i + 1 + psKV]);
        hf16 h, l;
        split2(x0 * co - x1 * sn, h, l);
        ke[KVLR + 2 * i] = h; ke[KVLR + 2 * i + psKV] = l;
        split2(x0 * sn + x1 * co, h, l);
        ke[KVLR + 2 * i + 1] = h; ke[KVLR + 2 * i + 1 + psKV] = l;
    }
}

// rope q_pe in place inside g_q planes ([m][h*192+128 .. +191])
__global__ void rope_q_k(hf16* q, const float* __restrict__ freqs) {
    const long long psQ = (long long)MS * QDIM;
    const int m = blockIdx.x;
    const int s = m & (SEQ - 1);
    const int h = threadIdx.x >> 5;
    const int i = threadIdx.x & 31;
    float th = freqs[s * 32 + i];
    float co, sn; sincosf(th, &sn, &co);
    hf16* qr = q + (long long)m * QDIM + h * D_QK + D_NOPE;
    float x0 = join2(qr[2 * i], qr[2 * i + psQ]);
    float x1 = join2(qr[2 * i + 1], qr[2 * i + 1 + psQ]);
    hf16 hh, ll;
    split2(x0 * co - x1 * sn, hh, ll);
    qr[2 * i] = hh; qr[2 * i + psQ] = ll;
    split2(x0 * sn + x1 * co, hh, ll);
    qr[2 * i + 1] = hh; qr[2 * i + 1 + psQ] = ll;
}

// ------------------------------- host side ---------------------------------
static void launchGemm(const hf16* A, long long aPS, const hf16* B, long long bPS,
                       void* C, long long cPS,
                       int M, int N, int K,
                       long long lda, long long ldb, long long ldc,
                       int nb, int nInner,
                       long long aSb, long long aSh,
                       long long bSb, long long bSh,
                       long long cSb, long long cSh,
                       int causal, int outMode) {
    GemmP p;
    p.A = A; p.B = B; p.C = C;
    p.aPS = aPS; p.bPS = bPS; p.cPS = cPS;
    p.M = M; p.N = N; p.K = K;
    p.lda = lda; p.ldb = ldb; p.ldc = ldc;
    p.aSb = aSb; p.aSh = aSh; p.bSb = bSb; p.bSh = bSh; p.cSb = cSb; p.cSh = cSh;
    p.nInner = nInner; p.causal = causal; p.outMode = outMode;
    dim3 grid((N + 127) / 128, (M + 127) / 128, nb);
    gemm_hmma<<<grid, 256>>>(p);
}

extern "C" void kernel_launch(void* const* d_in, const int* in_sizes, int n_in,
                              void* d_out, int out_size) {
    const float* x         = (const float*)d_in[0];
    const float* freqs     = (const float*)d_in[1];
    const float* wq_a      = (const float*)d_in[3];
    const float* q_norm_w  = (const float*)d_in[4];
    const float* wq_b      = (const float*)d_in[5];
    const float* wkv_a     = (const float*)d_in[6];
    const float* kv_norm_w = (const float*)d_in[7];
    const float* wkv_b     = (const float*)d_in[8];
    const float* wo        = (const float*)d_in[9];
    float* out = (float*)d_out;

    cudaFuncSetAttribute(flash_k, cudaFuncAttributeMaxDynamicSharedMemorySize, FL_SMEM);

    hf16 *xp, *wqaT, *wkvaT, *wqbT, *wkvbT, *woT;
    hf16 *qa, *q, *kv, *kext, *kabs, *vT, *ohead;
    cudaGetSymbolAddress((void**)&xp,     g_xp);
    cudaGetSymbolAddress((void**)&wqaT,   g_wqaT);
    cudaGetSymbolAddress((void**)&wkvaT,  g_wkvaT);
    cudaGetSymbolAddress((void**)&wqbT,   g_wqbT);
    cudaGetSymbolAddress((void**)&wkvbT,  g_wkvbT);
    cudaGetSymbolAddress((void**)&woT,    g_woT);
    cudaGetSymbolAddress((void**)&qa,     g_qa);
    cudaGetSymbolAddress((void**)&q,      g_q);
    cudaGetSymbolAddress((void**)&kv,     g_kv);
    cudaGetSymbolAddress((void**)&kext,   g_kext);
    cudaGetSymbolAddress((void**)&kabs,   g_kabs);
    cudaGetSymbolAddress((void**)&vT,     g_vT);
    cudaGetSymbolAddress((void**)&ohead,  g_ohead);

    const float scale = 1.0f / sqrtf((float)D_QK);
    const float s2 = scale * 1.4426950408889634f;   // scale * log2(e)

    // plane strides
    const long long psX   = (long long)MS * DMODEL;
    const long long psWQA = (long long)QLR * DMODEL;
    const long long psWKA = (long long)KVD * DMODEL;
    const long long psWQB = (long long)QDIM * QLR;
    const long long psWBT = (long long)NH * HDIM * KVLR;
    const long long psWO  = (long long)DMODEL * DMODEL;
    const long long psQA  = (long long)MS * QLR;
    const long long psQ   = (long long)MS * QDIM;
    const long long psKV  = (long long)MS * KVD;
    const long long psKA  = (long long)BSZ * NH * SEQ * D_NOPE;
    const long long psVT  = (long long)BSZ * NH * D_V * SEQ;
    const long long psOH  = (long long)MS * DMODEL;

    // ---- pack inputs into planes ----
    pack2_k<<<512, 256>>>(x, xp, psX, MS * DMODEL);
    packT2_k<<<dim3(QLR / 32, DMODEL / 32), dim3(32, 8)>>>(wq_a, wqaT, psWQA, DMODEL, QLR);
    packT2_k<<<dim3(KVD / 32, DMODEL / 32), dim3(32, 8)>>>(wkv_a, wkvaT, psWKA, DMODEL, KVD);
    packT2_k<<<dim3(QDIM / 32, QLR / 32), dim3(32, 8)>>>(wq_b, wqbT, psWQB, QLR, QDIM);
    packT2_k<<<dim3((NH * HDIM) / 32, KVLR / 32), dim3(32, 8)>>>(wkv_b, wkvbT, psWBT, KVLR, NH * HDIM);
    packT2_k<<<dim3(DMODEL / 32, DMODEL / 32), dim3(32, 8)>>>(wo, woT, psWO, DMODEL, DMODEL);

    // 1. qa = x @ wq_a
    launchGemm(xp, psX, wqaT, psWQA, qa, psQA, MS, QLR, DMODEL,
               DMODEL, DMODEL, QLR, 1, 1, 0, 0, 0, 0, 0, 0, 0, 1);
    // 2. kv = x @ wkv_a (N=576)
    launchGemm(xp, psX, wkvaT, psWKA, kv, psKV, MS, KVD, DMODEL,
               DMODEL, DMODEL, KVD, 1, 1, 0, 0, 0, 0, 0, 0, 0, 1);
    // 3. rmsnorm(qa)
    rmsnorm_rows_k<<<MS, 256>>>(qa, psQA, q_norm_w, QLR);
    // 4. kext = [rmsnorm(latent), rope(k_pe)]
    kv_process_k<<<MS, 256>>>(kv, kext, kv_norm_w, freqs);
    // 5. q = qa @ wq_b
    launchGemm(qa, psQA, wqbT, psWQB, q, psQ, MS, QDIM, QLR,
               QLR, QLR, QDIM, 1, 1, 0, 0, 0, 0, 0, 0, 0, 1);
    // 6. rope q_pe in place
    rope_q_k<<<MS, NH * 32>>>(q, freqs);
    // 7. k_abs[b,h,s,0:128] = kv_cache @ Wuk[h]^T
    launchGemm(kext, psKV, wkvbT, psWBT, kabs, psKA,
               SEQ, D_NOPE, KVLR,
               KVD, KVLR, D_NOPE,
               BSZ * NH, NH,
               (long long)SEQ * KVD, 0,
               0, (long long)HDIM * KVLR,
               (long long)NH * SEQ * D_NOPE, (long long)SEQ * D_NOPE,
               0, 1);
    // 8. vT[b,h,d,t] = Wuv[h] @ kv_cache^T
    launchGemm(wkvbT + (long long)D_NOPE * KVLR, psWBT, kext, psKV, vT, psVT,
               D_V, SEQ, KVLR,
               KVLR, KVD, SEQ,
               BSZ * NH, NH,
               0, (long long)HDIM * KVLR,
               (long long)SEQ * KVD, 0,
               (long long)NH * D_V * SEQ, (long long)D_V * SEQ,
               0, 1);
    // 9. fused flash attention -> ohead planes
    flash_k<<<dim3(32, BSZ * NH), 256, FL_SMEM>>>(q, kabs, kext, vT, ohead, s2);
    // 10. out = ohead @ wo (fp32)
    launchGemm(ohead, psOH, woT, psWO, out, 0, MS, DMODEL, DMODEL,
               DMODEL, DMODEL, DMODEL, 1, 1, 0, 0, 0, 0, 0, 0, 0, 0);
}

// round 12
// speedup vs baseline: 1.3679x; 1.2660x over previous
#include <cuda_runtime.h>
#include <cuda_fp16.h>
#include <math.h>
#include <stdint.h>

// ---------------------------------------------------------------------------
// MLA forward, per-head expanded attention + fused flash attention.
// GEMMs: fp16x2 emulated fp32, TWO MMAs per k-slab: D = Ah*(Bh + Bl).
// A operands are fp16 (hi plane only); B operands keep hi/lo planes (22-bit).
// cp.async 3-stage pipeline, ldmatrix fragment loads, f32 accumulate.
// ---------------------------------------------------------------------------

#define BSZ    2
#define SEQ    2048
#define DMODEL 2048
#define NH     16
#define QLR    1536
#define KVLR   512
#define D_NOPE 128
#define D_ROPE 64
#define D_QK   192
#define D_V    128
#define MS     (BSZ*SEQ)          /* 4096 */
#define QDIM   (NH*D_QK)          /* 3072 */
#define KVD    (KVLR + D_ROPE)    /* 576  */
#define HDIM   (D_NOPE + D_V)     /* 256  */
#define EPSF   1e-6f

typedef __half hf16;

// ---------------- scratch: every tensor is [2][elems] fp16 planes ----------
__device__ hf16 g_xp   [2 * (size_t)MS * DMODEL];
__device__ hf16 g_wqaT [2 * (size_t)QLR * DMODEL];
__device__ hf16 g_wkvaT[2 * (size_t)KVD * DMODEL];
__device__ hf16 g_wqbT [2 * (size_t)QDIM * QLR];
__device__ hf16 g_wkvbT[2 * (size_t)NH * HDIM * KVLR];
__device__ hf16 g_woT  [2 * (size_t)DMODEL * DMODEL];
__device__ hf16 g_qa   [2 * (size_t)MS * QLR];
__device__ hf16 g_q    [2 * (size_t)MS * QDIM];
__device__ hf16 g_kv   [2 * (size_t)MS * KVD];
__device__ hf16 g_kext [2 * (size_t)MS * KVD];
__device__ hf16 g_kabs [2 * (size_t)BSZ * NH * SEQ * D_NOPE];
__device__ hf16 g_vT   [2 * (size_t)BSZ * NH * D_V * SEQ];
__device__ hf16 g_ohead[2 * (size_t)MS * DMODEL];

// ------------------------------ helpers -------------------------------------
__device__ __forceinline__ void split2(float x, hf16& h, hf16& l) {
    h = __float2half_rn(x);
    l = __float2half_rn(x - __half2float(h));
}
__device__ __forceinline__ float join2(hf16 h, hf16 l) {
    return __half2float(h) + __half2float(l);
}
__device__ __forceinline__ void cp16(uint32_t smem, const void* g, int srcBytes) {
    asm volatile("cp.async.cg.shared.global [%0], [%1], 16, %2;"
                 :: "r"(smem), "l"(g), "r"(srcBytes));
}
__device__ __forceinline__ void cp_commit() { asm volatile("cp.async.commit_group;"); }
__device__ __forceinline__ void cp_wait1()  { asm volatile("cp.async.wait_group 1;"); }

__device__ __forceinline__ void ldsm4(uint32_t* r, uint32_t addr) {
    asm volatile("ldmatrix.sync.aligned.m8n8.x4.shared.b16 {%0,%1,%2,%3}, [%4];"
                 : "=r"(r[0]), "=r"(r[1]), "=r"(r[2]), "=r"(r[3]) : "r"(addr));
}
__device__ __forceinline__ void mma_f32(float* d, const uint32_t* a,
                                        uint32_t b0, uint32_t b1) {
    asm volatile(
        "mma.sync.aligned.m16n8k16.row.col.f32.f16.f16.f32 "
        "{%0,%1,%2,%3}, {%4,%5,%6,%7}, {%8,%9}, {%0,%1,%2,%3};"
        : "+f"(d[0]), "+f"(d[1]), "+f"(d[2]), "+f"(d[3])
        : "r"(a[0]), "r"(a[1]), "r"(a[2]), "r"(a[3]), "r"(b0), "r"(b1));
}

// ----------------------------- GEMM kernel ----------------------------------
// C = A * B^T. A: [M][K] fp16 (hi plane only consumed), row stride lda.
// B: [N][K] planes (hi at B, lo at B+bPS), row stride ldb.
// CTA tile 128x128, K-slab 16, 8 warps, warp tile 64x32.
// outMode 0: fp32 C. outMode 1: fp16 planes C (lo at +cPS).
struct GemmP {
    const hf16 *A, *B; void* C;
    long long bPS, cPS;
    int M, N, K;
    long long lda, ldb, ldc;
    long long aSb, aSh, bSb, bSh, cSb, cSh;
    int nInner, causal, outMode;
};

// stage: Ah[0,4096) Bh[4096,8192) Bl[8192,12288)
#define STG_BYTES 12288

__global__ __launch_bounds__(256, 2) void gemm_hmma(GemmP p) {
    __shared__ __align__(16) hf16 stg[3][3][128 * 16];   // 36KB

    const int m0 = blockIdx.y * 128;
    const int n0 = blockIdx.x * 128;
    if (p.causal == 1 && n0 >= m0 + 128) return;

    const int z  = blockIdx.z;
    const int zb = z / p.nInner;
    const int zh = z - zb * p.nInner;
    const hf16* A = p.A + zb * p.aSb + zh * p.aSh;
    const hf16* B = p.B + zb * p.bSb + zh * p.bSh;

    int kEnd = p.K;
    if (p.causal == 2) { int km = m0 + 128; if (km < kEnd) kEnd = km; }
    const int nSlab = kEnd >> 4;

    const int tid  = threadIdx.x;
    const int lane = tid & 31;
    const int warp = tid >> 5;
    const int wm   = warp >> 2;    // 0..1
    const int wn   = warp & 3;     // 0..3

    const uint32_t smBase = (uint32_t)__cvta_generic_to_shared(&stg[0][0][0]);

    const int r  = tid >> 1;
    const int cc = tid & 1;
    const uint32_t pOff = (uint32_t)(r * 32 + ((cc ^ ((r >> 2) & 1)) << 4));

    int mr = m0 + r;
    const bool aok = mr < p.M;
    if (!aok) mr = m0;
    const hf16* gA0 = A + (size_t)mr * p.lda + cc * 8;
    const int asz = aok ? 16 : 0;
    int nr = n0 + r;
    const bool bok = nr < p.N;
    if (!bok) nr = n0;
    const hf16* gB0 = B + (size_t)nr * p.ldb + cc * 8;
    const hf16* gB1 = gB0 + p.bPS;
    const int bsz = bok ? 16 : 0;

#define ISSUE(S)                                                               \
    do {                                                                       \
        uint32_t sb = smBase + (uint32_t)(((S) % 3) * STG_BYTES);              \
        const size_t ko = (size_t)(S) * 16;                                    \
        cp16(sb + pOff,        gA0 + ko, asz);                                 \
        cp16(sb + 4096 + pOff, gB0 + ko, bsz);                                 \
        cp16(sb + 8192 + pOff, gB1 + ko, bsz);                                 \
    } while (0)

    const int rowA = wm * 64 + (lane & 7) + ((lane >> 3) & 1) * 8;
    const int cA   = lane >> 4;
    const uint32_t offA = (uint32_t)(rowA * 32 + ((cA ^ ((rowA >> 2) & 1)) << 4));
    const int rowB = wn * 32 + (lane & 7) + ((lane >> 4) << 3);
    const int cB   = (lane >> 3) & 1;
    const uint32_t offB = (uint32_t)(rowB * 32 + ((cB ^ ((rowB >> 2) & 1)) << 4));

    float acc[4][4][4];
#pragma unroll
    for (int i = 0; i < 4; ++i)
#pragma unroll
        for (int j = 0; j < 4; ++j)
#pragma unroll
            for (int l = 0; l < 4; ++l) acc[i][j][l] = 0.f;

    ISSUE(0); cp_commit();
    if (nSlab > 1) ISSUE(1);
    cp_commit();

    for (int it = 0; it < nSlab; ++it) {
        cp_wait1();
        __syncthreads();

        const uint32_t sb   = smBase + (uint32_t)((it % 3) * STG_BYTES);
        const uint32_t aAdr = sb + offA;
        const uint32_t bAdr = sb + 4096 + offB;

        uint32_t bh[2][4], bl[2][4];
        ldsm4(bh[0], bAdr);
        ldsm4(bh[1], bAdr + 512);
        ldsm4(bl[0], bAdr + 4096);
        ldsm4(bl[1], bAdr + 4096 + 512);

#pragma unroll
        for (int mi = 0; mi < 4; ++mi) {
            uint32_t ah[4];
            ldsm4(ah, aAdr + mi * 512);
#pragma unroll
            for (int nt = 0; nt < 4; ++nt) {
                const int np = nt >> 1, hf = (nt & 1) * 2;
                mma_f32(acc[mi][nt], ah, bh[np][hf], bh[np][hf + 1]);
                mma_f32(acc[mi][nt], ah, bl[np][hf], bl[np][hf + 1]);
            }
        }

        if (it + 2 < nSlab) ISSUE(it + 2);
        cp_commit();
    }
#undef ISSUE

    const int g = lane >> 2;
    const int c = lane & 3;
    if (p.outMode == 0) {
        float* C = (float*)p.C + zb * p.cSb + zh * p.cSh;
#pragma unroll
        for (int mi = 0; mi < 4; ++mi) {
            const int gm = m0 + wm * 64 + mi * 16 + g;
            if (gm >= p.M) continue;
            float* r0 = C + (long long)gm * p.ldc;
            float* r1 = r0 + 8 * p.ldc;
#pragma unroll
            for (int nt = 0; nt < 4; ++nt) {
                const int gn = n0 + wn * 32 + nt * 8 + 2 * c;
                if (gn < p.N) {
                    *(float2*)(r0 + gn) = make_float2(acc[mi][nt][0], acc[mi][nt][1]);
                    *(float2*)(r1 + gn) = make_float2(acc[mi][nt][2], acc[mi][nt][3]);
                }
            }
        }
    } else {
        hf16* Ch = (hf16*)p.C + zb * p.cSb + zh * p.cSh;
        hf16* Cl = Ch + p.cPS;
#pragma unroll
        for (int mi = 0; mi < 4; ++mi) {
            const int gm = m0 + wm * 64 + mi * 16 + g;
            if (gm >= p.M) continue;
            const long long ro0 = (long long)gm * p.ldc;
            const long long ro1 = ro0 + 8 * p.ldc;
#pragma unroll
            for (int nt = 0; nt < 4; ++nt) {
                const int gn = n0 + wn * 32 + nt * 8 + 2 * c;
                if (gn < p.N) {
                    hf16 h0, l0, h1, l1;
                    split2(acc[mi][nt][0], h0, l0);
                    split2(acc[mi][nt][1], h1, l1);
                    *(__half2*)(Ch + ro0 + gn) = __halves2half2(h0, h1);
                    *(__half2*)(Cl + ro0 + gn) = __halves2half2(l0, l1);
                    split2(acc[mi][nt][2], h0, l0);
                    split2(acc[mi][nt][3], h1, l1);
                    *(__half2*)(Ch + ro1 + gn) = __halves2half2(h0, h1);
                    *(__half2*)(Cl + ro1 + gn) = __halves2half2(l0, l1);
                }
            }
        }
    }
}

// --------------------------- flash attention --------------------------------
// TM=64 q-rows per CTA, 2 CTAs/SM. grid (32 q-blocks, 32 bh).
// Q and P are fp16 (hi only); K/V sides keep hi/lo planes.
// smem layout (bytes):
//   Qh 0..25600                      (64 rows x 400B, 192 cols used)
//   Ph 25600..43008                  (64 rows x 272B, 128 cols used)
//   stages 43008 + s*8192 (Bh 4KB, Bl 4KB), 3 stages -> 67584
//   RED 67584..68608 (float[4][64])
#define FL_SMEM 68608

__global__ __launch_bounds__(256, 2) void flash_k(
    const hf16* __restrict__ q, const hf16* __restrict__ kabs,
    const hf16* __restrict__ kext, const hf16* __restrict__ vT,
    hf16* __restrict__ ohead, float s2) {
    extern __shared__ __align__(16) char dyn[];
    const int tid = threadIdx.x, lane = tid & 31, warp = tid >> 5;
    const int wm = warp >> 2, wn = warp & 3, g = lane >> 2, c = lane & 3;
    const int iq = 31 - blockIdx.x;       // heavy blocks first
    const int bh = blockIdx.y, b = bh >> 4, h = bh & 15;
    const int m0 = iq * 64;
    const int nkv = (iq >> 1) + 1;
    const long long psKA = (long long)BSZ * NH * SEQ * D_NOPE;
    const long long psKV = (long long)MS * KVD;
    const long long psVT = (long long)BSZ * NH * D_V * SEQ;
    const long long psOH = (long long)MS * DMODEL;

    const uint32_t smb = (uint32_t)__cvta_generic_to_shared(dyn);
    const uint32_t smQ = smb;
    const uint32_t smP = smb + 25600;
    const uint32_t smS = smb + 43008;
    float* RED = (float*)(dyn + 67584);

    // ---- Q block load: 64 rows, hi plane only; 4 threads/row, 6 chunks each
    // (sub spans 48 halves = 96 bytes = 6 x 16B chunks)
    {
        const int r = tid >> 2, sub = tid & 3;
        const hf16* src = q + ((size_t)(b * SEQ + m0 + r)) * QDIM + h * D_QK + sub * 48;
        const uint32_t d0 = smQ + (uint32_t)(r * 400 + sub * 96);
#pragma unroll
        for (int ch = 0; ch < 6; ++ch) cp16(d0 + ch * 16, src + ch * 8, 16);
        cp_commit();
    }

    const int prow = tid >> 1, pcc = tid & 1;
    const uint32_t pOff = (uint32_t)(prow * 32 + ((pcc ^ ((prow >> 2) & 1)) << 4));
    const hf16* ka = kabs + (size_t)bh * SEQ * D_NOPE;
    const hf16* ke = kext + (size_t)b * SEQ * KVD;
    const hf16* vt = vT + (size_t)bh * D_V * SEQ;
    const int u_total = 20 * nkv;

    // slab u -> (kv block j = u/20, s = u%20):
    //   s<8: K-nope from kabs; s in 8..11: pe from kext; s>=12: V-slab
#define FL_ISSUE(U)                                                            \
    do {                                                                       \
        const int _j = (U) / 20, _s = (U) % 20;                                \
        uint32_t _sb = smS + (uint32_t)(((U) % 3) * 8192);                     \
        const hf16* _s0; long long _ps;                                        \
        if (_s < 8) {                                                          \
            _s0 = ka + ((size_t)(_j * 128 + prow)) * D_NOPE + _s * 16 + pcc * 8; \
            _ps = psKA;                                                        \
        } else if (_s < 12) {                                                  \
            _s0 = ke + ((size_t)(_j * 128 + prow)) * KVD + KVLR                \
                     + (_s - 8) * 16 + pcc * 8;                                \
            _ps = psKV;                                                        \
        } else {                                                               \
            _s0 = vt + (size_t)prow * SEQ + _j * 128 + (_s - 12) * 16 + pcc * 8; \
            _ps = psVT;                                                        \
        }                                                                      \
        cp16(_sb + pOff, _s0, 16);                                             \
        cp16(_sb + 4096 + pOff, _s0 + _ps, 16);                                \
    } while (0)

    FL_ISSUE(0); cp_commit();
    FL_ISSUE(1); cp_commit();

    // consumer fragment offsets
    const int rowA = wm * 32 + (lane & 7) + ((lane >> 3) & 1) * 8;
    const int cA   = lane >> 4;
    const uint32_t offAq = (uint32_t)(rowA * 400 + cA * 16);
    const uint32_t offAp = (uint32_t)(rowA * 272 + cA * 16);
    const int rowB = wn * 32 + (lane & 7) + ((lane >> 4) << 3);
    const int cB   = (lane >> 3) & 1;
    const uint32_t offB = (uint32_t)(rowB * 32 + ((cB ^ ((rowB >> 2) & 1)) << 4));

    float oacc[2][4][4];
    float m_r[2][2], l_r[2][2];
#pragma unroll
    for (int mi = 0; mi < 2; ++mi) {
#pragma unroll
        for (int nt = 0; nt < 4; ++nt)
#pragma unroll
            for (int k = 0; k < 4; ++k) oacc[mi][nt][k] = 0.f;
        m_r[mi][0] = m_r[mi][1] = -1e30f;
        l_r[mi][0] = l_r[mi][1] = 0.f;
    }

    int u = 0;
    for (int j = 0; j < nkv; ++j) {
        float sacc[2][4][4];
#pragma unroll
        for (int mi = 0; mi < 2; ++mi)
#pragma unroll
            for (int nt = 0; nt < 4; ++nt)
#pragma unroll
                for (int k = 0; k < 4; ++k) sacc[mi][nt][k] = 0.f;

        // ---- S phase: 12 K-slabs (K=192) ----
        for (int s = 0; s < 12; ++s) {
            cp_wait1(); __syncthreads();
            const uint32_t sb = smS + (uint32_t)((u % 3) * 8192);
            uint32_t bh4[2][4], bl4[2][4];
            ldsm4(bh4[0], sb + offB); ldsm4(bh4[1], sb + offB + 512);
            ldsm4(bl4[0], sb + 4096 + offB); ldsm4(bl4[1], sb + 4096 + offB + 512);
#pragma unroll
            for (int mi = 0; mi < 2; ++mi) {
                uint32_t ah[4];
                ldsm4(ah, smQ + offAq + mi * 6400 + s * 32);
#pragma unroll
                for (int nt = 0; nt < 4; ++nt) {
                    const int np = nt >> 1, hf2 = (nt & 1) * 2;
                    mma_f32(sacc[mi][nt], ah, bh4[np][hf2], bh4[np][hf2 + 1]);
                    mma_f32(sacc[mi][nt], ah, bl4[np][hf2], bl4[np][hf2 + 1]);
                }
            }
            if (u + 2 < u_total) FL_ISSUE(u + 2);
            cp_commit(); ++u;
        }

        // ---- causal mask on last kv block ----
        if (j == nkv - 1) {
#pragma unroll
            for (int mi = 0; mi < 2; ++mi)
#pragma unroll
                for (int nt = 0; nt < 4; ++nt)
#pragma unroll
                    for (int k = 0; k < 4; ++k) {
                        const int rl = m0 + wm * 32 + mi * 16 + g + (k >> 1) * 8;
                        const int cl = j * 128 + wn * 32 + nt * 8 + 2 * c + (k & 1);
                        if (cl > rl) sacc[mi][nt][k] = -1e30f;
                    }
        }

        // ---- online softmax ----
        float alpha[2][2];
#pragma unroll
        for (int mi = 0; mi < 2; ++mi)
#pragma unroll
            for (int h2 = 0; h2 < 2; ++h2) {
                float v = fmaxf(fmaxf(sacc[mi][0][h2 * 2], sacc[mi][0][h2 * 2 + 1]),
                                fmaxf(sacc[mi][1][h2 * 2], sacc[mi][1][h2 * 2 + 1]));
                v = fmaxf(v, fmaxf(fmaxf(sacc[mi][2][h2 * 2], sacc[mi][2][h2 * 2 + 1]),
                                   fmaxf(sacc[mi][3][h2 * 2], sacc[mi][3][h2 * 2 + 1])));
                v = fmaxf(v, __shfl_xor_sync(0xffffffffu, v, 1));
                v = fmaxf(v, __shfl_xor_sync(0xffffffffu, v, 2));
                if (c == 0) RED[wn * 64 + wm * 32 + mi * 16 + g + h2 * 8] = v;
            }
        __syncthreads();
#pragma unroll
        for (int mi = 0; mi < 2; ++mi)
#pragma unroll
            for (int h2 = 0; h2 < 2; ++h2) {
                const int row = wm * 32 + mi * 16 + g + h2 * 8;
                float mrow = fmaxf(fmaxf(RED[row], RED[64 + row]),
                                   fmaxf(RED[128 + row], RED[192 + row]));
                float mnew = fmaxf(m_r[mi][h2], mrow);
                alpha[mi][h2] = exp2f((m_r[mi][h2] - mnew) * s2);
                m_r[mi][h2] = mnew;
            }
        __syncthreads();   // RED reads done before sum-round rewrite
#pragma unroll
        for (int mi = 0; mi < 2; ++mi)
#pragma unroll
            for (int h2 = 0; h2 < 2; ++h2) {
                const float mn = m_r[mi][h2];
                const float a = alpha[mi][h2];
                float sum = 0.f;
#pragma unroll
                for (int nt = 0; nt < 4; ++nt) {
                    float p0 = exp2f((sacc[mi][nt][h2 * 2] - mn) * s2);
                    float p1 = exp2f((sacc[mi][nt][h2 * 2 + 1] - mn) * s2);
                    sacc[mi][nt][h2 * 2] = p0;
                    sacc[mi][nt][h2 * 2 + 1] = p1;
                    oacc[mi][nt][h2 * 2] *= a;
                    oacc[mi][nt][h2 * 2 + 1] *= a;
                    sum += p0 + p1;
                }
                sum += __shfl_xor_sync(0xffffffffu, sum, 1);
                sum += __shfl_xor_sync(0xffffffffu, sum, 2);
                if (c == 0) RED[wn * 64 + wm * 32 + mi * 16 + g + h2 * 8] = sum;
            }
        // write P (hi plane only) to smem
#pragma unroll
        for (int mi = 0; mi < 2; ++mi)
#pragma unroll
            for (int nt = 0; nt < 4; ++nt) {
                const int r0 = wm * 32 + mi * 16 + g;
                const int cb = wn * 32 + nt * 8 + 2 * c;
                *(__half2*)(dyn + 25600 + r0 * 272 + cb * 2) =
                    __halves2half2(__float2half_rn(sacc[mi][nt][0]),
                                   __float2half_rn(sacc[mi][nt][1]));
                *(__half2*)(dyn + 25600 + (r0 + 8) * 272 + cb * 2) =
                    __halves2half2(__float2half_rn(sacc[mi][nt][2]),
                                   __float2half_rn(sacc[mi][nt][3]));
            }
        __syncthreads();   // P + sums visible
#pragma unroll
        for (int mi = 0; mi < 2; ++mi)
#pragma unroll
            for (int h2 = 0; h2 < 2; ++h2) {
                const int row = wm * 32 + mi * 16 + g + h2 * 8;
                const float ls = RED[row] + RED[64 + row] + RED[128 + row] + RED[192 + row];
                l_r[mi][h2] = l_r[mi][h2] * alpha[mi][h2] + ls;
            }

        // ---- PV phase: 8 V-slabs (K=128 over t) ----
        for (int s = 0; s < 8; ++s) {
            cp_wait1(); __syncthreads();
            const uint32_t sb = smS + (uint32_t)((u % 3) * 8192);
            uint32_t vh4[2][4], vl4[2][4];
            ldsm4(vh4[0], sb + offB); ldsm4(vh4[1], sb + offB + 512);
            ldsm4(vl4[0], sb + 4096 + offB); ldsm4(vl4[1], sb + 4096 + offB + 512);
#pragma unroll
            for (int mi = 0; mi < 2; ++mi) {
                uint32_t ph[4];
                ldsm4(ph, smP + offAp + mi * 4352 + s * 32);
#pragma unroll
                for (int nt = 0; nt < 4; ++nt) {
                    const int np = nt >> 1, hf2 = (nt & 1) * 2;
                    mma_f32(oacc[mi][nt], ph, vh4[np][hf2], vh4[np][hf2 + 1]);
                    mma_f32(oacc[mi][nt], ph, vl4[np][hf2], vl4[np][hf2 + 1]);
                }
            }
            if (u + 2 < u_total) FL_ISSUE(u + 2);
            cp_commit(); ++u;
        }
    }
#undef FL_ISSUE

    // ---- epilogue: O / l -> ohead planes ----
    hf16* Cb = ohead + (size_t)(b * SEQ + m0) * DMODEL + h * D_V;
#pragma unroll
    for (int mi = 0; mi < 2; ++mi) {
        const int r0 = wm * 32 + mi * 16 + g;
        const float i0 = 1.f / l_r[mi][0], i1 = 1.f / l_r[mi][1];
#pragma unroll
        for (int nt = 0; nt < 4; ++nt) {
            const int cb = wn * 32 + nt * 8 + 2 * c;
            hf16 h0, l0, h1, l1;
            split2(oacc[mi][nt][0] * i0, h0, l0);
            split2(oacc[mi][nt][1] * i0, h1, l1);
            hf16* p = Cb + (size_t)r0 * DMODEL + cb;
            *(__half2*)p = __halves2half2(h0, h1);
            *(__half2*)(p + psOH) = __halves2half2(l0, l1);
            split2(oacc[mi][nt][2] * i1, h0, l0);
            split2(oacc[mi][nt][3] * i1, h1, l1);
            p = Cb + (size_t)(r0 + 8) * DMODEL + cb;
            *(__half2*)p = __halves2half2(h0, h1);
            *(__half2*)(p + psOH) = __halves2half2(l0, l1);
        }
    }
}

// ---------------------------- block reduction ------------------------------
__device__ __forceinline__ float blockReduce(float v, bool isMax) {
    __shared__ float sh[32];
    const int lane = threadIdx.x & 31, wid = threadIdx.x >> 5;
    __syncthreads();
#pragma unroll
    for (int o = 16; o > 0; o >>= 1) {
        float t = __shfl_down_sync(0xffffffffu, v, o);
        v = isMax ? fmaxf(v, t) : (v + t);
    }
    if (lane == 0) sh[wid] = v;
    __syncthreads();
    const int nw = blockDim.x >> 5;
    if (wid == 0) {
        v = (lane < nw) ? sh[lane] : (isMax ? -1e30f : 0.f);
#pragma unroll
        for (int o = 16; o > 0; o >>= 1) {
            float t = __shfl_down_sync(0xffffffffu, v, o);
            v = isMax ? fmaxf(v, t) : (v + t);
        }
        if (lane == 0) sh[0] = v;
    }
    __syncthreads();
    return sh[0];
}

// ------------------------------ aux kernels --------------------------------
__global__ void pack2_k(const float* __restrict__ in, hf16* __restrict__ out,
                        long long ps, int n) {
    for (int i = blockIdx.x * blockDim.x + threadIdx.x; i < n; i += gridDim.x * blockDim.x) {
        hf16 h, l; split2(in[i], h, l);
        out[i] = h; out[i + ps] = l;
    }
}

// fp32 [R][C] -> planes [C][R]
__global__ void packT2_k(const float* __restrict__ in, hf16* __restrict__ out,
                         long long ps, int R, int C) {
    __shared__ float t[32][33];
    const int c0 = blockIdx.x * 32, r0 = blockIdx.y * 32;
#pragma unroll
    for (int i = threadIdx.y; i < 32; i += 8)
        t[i][threadIdx.x] = in[(long long)(r0 + i) * C + c0 + threadIdx.x];
    __syncthreads();
#pragma unroll
    for (int i = threadIdx.y; i < 32; i += 8) {
        hf16 h, l; split2(t[threadIdx.x][i], h, l);
        long long o = (long long)(c0 + i) * R + r0 + threadIdx.x;
        out[o] = h; out[o + ps] = l;
    }
}

__global__ void rmsnorm_rows_k(hf16* x, long long ps, const float* __restrict__ w, int n) {
    long long base = (long long)blockIdx.x * n;
    float ss = 0.f;
    for (int i = threadIdx.x; i < n; i += blockDim.x) {
        float v = join2(x[base + i], x[base + i + ps]); ss += v * v;
    }
    ss = blockReduce(ss, false);
    float rn = rsqrtf(ss / (float)n + EPSF);
    for (int i = threadIdx.x; i < n; i += blockDim.x) {
        float v = join2(x[base + i], x[base + i + ps]) * rn * w[i];
        hf16 h, l; split2(v, h, l);
        x[base + i] = h; x[base + i + ps] = l;
    }
}

__global__ void kv_process_k(const hf16* __restrict__ kv, hf16* __restrict__ kext,
                             const float* __restrict__ w, const float* __restrict__ freqs) {
    const long long psKV = (long long)MS * KVD;
    const int m = blockIdx.x;
    const int s = m & (SEQ - 1);
    const hf16* kr = kv   + (long long)m * KVD;
    hf16*       ke = kext + (long long)m * KVD;
    float ss = 0.f;
    for (int i = threadIdx.x; i < KVLR; i += blockDim.x) {
        float v = join2(kr[i], kr[i + psKV]); ss += v * v;
    }
    ss = blockReduce(ss, false);
    float rn = rsqrtf(ss / (float)KVLR + EPSF);
    for (int i = threadIdx.x; i < KVLR; i += blockDim.x) {
        float v = join2(kr[i], kr[i + psKV]) * rn * w[i];
        hf16 h, l; split2(v, h, l);
        ke[i] = h; ke[i + psKV] = l;
    }
    if (threadIdx.x < 32) {
        const int i = threadIdx.x;
        float th = freqs[s * 32 + i];
        float co, sn; sincosf(th, &sn, &co);
        float x0 = join2(kr[KVLR + 2 * i], kr[KVLR + 2 * i + psKV]);
        float x1 = join2(kr[KVLR + 2 * i + 1], kr[KVLR + 2 * i + 1 + psKV]);
        hf16 h, l;
        split2(x0 * co - x1 * sn, h, l);
        ke[KVLR + 2 * i] = h; ke[KVLR + 2 * i + psKV] = l;
        split2(x0 * sn + x1 * co, h, l);
        ke[KVLR + 2 * i + 1] = h; ke[KVLR + 2 * i + 1 + psKV] = l;
    }
}

// rope q_pe in place inside g_q planes ([m][h*192+128 .. +191])
__global__ void rope_q_k(hf16* q, const float* __restrict__ freqs) {
    const long long psQ = (long long)MS * QDIM;
    const int m = blockIdx.x;
    const int s = m & (SEQ - 1);
    const int h = threadIdx.x >> 5;
    const int i = threadIdx.x & 31;
    float th = freqs[s * 32 + i];
    float co, sn; sincosf(th, &sn, &co);
    hf16* qr = q + (long long)m * QDIM + h * D_QK + D_NOPE;
    float x0 = join2(qr[2 * i], qr[2 * i + psQ]);
    float x1 = join2(qr[2 * i + 1], qr[2 * i + 1 + psQ]);
    hf16 hh, ll;
    split2(x0 * co - x1 * sn, hh, ll);
    qr[2 * i] = hh; qr[2 * i + psQ] = ll;
    split2(x0 * sn + x1 * co, hh, ll);
    qr[2 * i + 1] = hh; qr[2 * i + 1 + psQ] = ll;
}

// ------------------------------- host side ---------------------------------
static void launchGemm(const hf16* A, const hf16* B, long long bPS,
                       void* C, long long cPS,
                       int M, int N, int K,
                       long long lda, long long ldb, long long ldc,
                       int nb, int nInner,
                       long long aSb, long long aSh,
                       long long bSb, long long bSh,
                       long long cSb, long long cSh,
                       int causal, int outMode) {
    GemmP p;
    p.A = A; p.B = B; p.C = C;
    p.bPS = bPS; p.cPS = cPS;
    p.M = M; p.N = N; p.K = K;
    p.lda = lda; p.ldb = ldb; p.ldc = ldc;
    p.aSb = aSb; p.aSh = aSh; p.bSb = bSb; p.bSh = bSh; p.cSb = cSb; p.cSh = cSh;
    p.nInner = nInner; p.causal = causal; p.outMode = outMode;
    dim3 grid((N + 127) / 128, (M + 127) / 128, nb);
    gemm_hmma<<<grid, 256>>>(p);
}

extern "C" void kernel_launch(void* const* d_in, const int* in_sizes, int n_in,
                              void* d_out, int out_size) {
    const float* x         = (const float*)d_in[0];
    const float* freqs     = (const float*)d_in[1];
    const float* wq_a      = (const float*)d_in[3];
    const float* q_norm_w  = (const float*)d_in[4];
    const float* wq_b      = (const float*)d_in[5];
    const float* wkv_a     = (const float*)d_in[6];
    const float* kv_norm_w = (const float*)d_in[7];
    const float* wkv_b     = (const float*)d_in[8];
    const float* wo        = (const float*)d_in[9];
    float* out = (float*)d_out;

    cudaFuncSetAttribute(flash_k, cudaFuncAttributeMaxDynamicSharedMemorySize, FL_SMEM);

    hf16 *xp, *wqaT, *wkvaT, *wqbT, *wkvbT, *woT;
    hf16 *qa, *q, *kv, *kext, *kabs, *vT, *ohead;
    cudaGetSymbolAddress((void**)&xp,     g_xp);
    cudaGetSymbolAddress((void**)&wqaT,   g_wqaT);
    cudaGetSymbolAddress((void**)&wkvaT,  g_wkvaT);
    cudaGetSymbolAddress((void**)&wqbT,   g_wqbT);
    cudaGetSymbolAddress((void**)&wkvbT,  g_wkvbT);
    cudaGetSymbolAddress((void**)&woT,    g_woT);
    cudaGetSymbolAddress((void**)&qa,     g_qa);
    cudaGetSymbolAddress((void**)&q,      g_q);
    cudaGetSymbolAddress((void**)&kv,     g_kv);
    cudaGetSymbolAddress((void**)&kext,   g_kext);
    cudaGetSymbolAddress((void**)&kabs,   g_kabs);
    cudaGetSymbolAddress((void**)&vT,     g_vT);
    cudaGetSymbolAddress((void**)&ohead,  g_ohead);

    const float scale = 1.0f / sqrtf((float)D_QK);
    const float s2 = scale * 1.4426950408889634f;   // scale * log2(e)

    // plane strides
    const long long psX   = (long long)MS * DMODEL;
    const long long psWQA = (long long)QLR * DMODEL;
    const long long psWKA = (long long)KVD * DMODEL;
    const long long psWQB = (long long)QDIM * QLR;
    const long long psWBT = (long long)NH * HDIM * KVLR;
    const long long psWO  = (long long)DMODEL * DMODEL;
    const long long psQA  = (long long)MS * QLR;
    const long long psQ   = (long long)MS * QDIM;
    const long long psKV  = (long long)MS * KVD;
    const long long psKA  = (long long)BSZ * NH * SEQ * D_NOPE;
    const long long psVT  = (long long)BSZ * NH * D_V * SEQ;
    const long long psOH  = (long long)MS * DMODEL;

    // ---- pack inputs into planes ----
    pack2_k<<<512, 256>>>(x, xp, psX, MS * DMODEL);
    packT2_k<<<dim3(QLR / 32, DMODEL / 32), dim3(32, 8)>>>(wq_a, wqaT, psWQA, DMODEL, QLR);
    packT2_k<<<dim3(KVD / 32, DMODEL / 32), dim3(32, 8)>>>(wkv_a, wkvaT, psWKA, DMODEL, KVD);
    packT2_k<<<dim3(QDIM / 32, QLR / 32), dim3(32, 8)>>>(wq_b, wqbT, psWQB, QLR, QDIM);
    packT2_k<<<dim3((NH * HDIM) / 32, KVLR / 32), dim3(32, 8)>>>(wkv_b, wkvbT, psWBT, KVLR, NH * HDIM);
    packT2_k<<<dim3(DMODEL / 32, DMODEL / 32), dim3(32, 8)>>>(wo, woT, psWO, DMODEL, DMODEL);

    // 1. qa = x @ wq_a
    launchGemm(xp, wqaT, psWQA, qa, psQA, MS, QLR, DMODEL,
               DMODEL, DMODEL, QLR, 1, 1, 0, 0, 0, 0, 0, 0, 0, 1);
    // 2. kv = x @ wkv_a (N=576)
    launchGemm(xp, wkvaT, psWKA, kv, psKV, MS, KVD, DMODEL,
               DMODEL, DMODEL, KVD, 1, 1, 0, 0, 0, 0, 0, 0, 0, 1);
    // 3. rmsnorm(qa)
    rmsnorm_rows_k<<<MS, 256>>>(qa, psQA, q_norm_w, QLR);
    // 4. kext = [rmsnorm(latent), rope(k_pe)]
    kv_process_k<<<MS, 256>>>(kv, kext, kv_norm_w, freqs);
    // 5. q = qa @ wq_b
    launchGemm(qa, wqbT, psWQB, q, psQ, MS, QDIM, QLR,
               QLR, QLR, QDIM, 1, 1, 0, 0, 0, 0, 0, 0, 0, 1);
    // 6. rope q_pe in place
    rope_q_k<<<MS, NH * 32>>>(q, freqs);
    // 7. k_abs[b,h,s,0:128] = kv_cache @ Wuk[h]^T
    launchGemm(kext, wkvbT, psWBT, kabs, psKA,
               SEQ, D_NOPE, KVLR,
               KVD, KVLR, D_NOPE,
               BSZ * NH, NH,
               (long long)SEQ * KVD, 0,
               0, (long long)HDIM * KVLR,
               (long long)NH * SEQ * D_NOPE, (long long)SEQ * D_NOPE,
               0, 1);
    // 8. vT[b,h,d,t] = Wuv[h] @ kv_cache^T  (A = weight hi plane; B = kext planes)
    launchGemm(wkvbT + (long long)D_NOPE * KVLR, kext, psKV, vT, psVT,
               D_V, SEQ, KVLR,
               KVLR, KVD, SEQ,
               BSZ * NH, NH,
               0, (long long)HDIM * KVLR,
               (long long)SEQ * KVD, 0,
               (long long)NH * D_V * SEQ, (long long)D_V * SEQ,
               0, 1);
    // 9. fused flash attention -> ohead planes
    flash_k<<<dim3(32, BSZ * NH), 256, FL_SMEM>>>(q, kabs, kext, vT, ohead, s2);
    // 10. out = ohead @ wo (fp32)
    launchGemm(ohead, woT, psWO, out, 0, MS, DMODEL, DMODEL,
               DMODEL, DMODEL, DMODEL, 1, 1, 0, 0, 0, 0, 0, 0, 0, 0);
}

// round 13
// speedup vs baseline: 1.3976x; 1.0217x over previous
#include <cuda_runtime.h>
#include <cuda_fp16.h>
#include <math.h>
#include <stdint.h>

// ---------------------------------------------------------------------------
// MLA forward, per-head expanded attention + fused flash attention.
// GEMMs: fp16x2 emulated fp32: D = Ah*(Bh + Bl), f32 accumulate.
// A operands fp16 (hi plane); B keeps hi/lo planes EXCEPT first (qa) and
// last (wo) GEMMs where B is plain fp16 (bLo=0, 1 MMA/slab).
// cp.async 3-stage pipeline, ldmatrix fragment loads.
// ---------------------------------------------------------------------------

#define BSZ    2
#define SEQ    2048
#define DMODEL 2048
#define NH     16
#define QLR    1536
#define KVLR   512
#define D_NOPE 128
#define D_ROPE 64
#define D_QK   192
#define D_V    128
#define MS     (BSZ*SEQ)          /* 4096 */
#define QDIM   (NH*D_QK)          /* 3072 */
#define KVD    (KVLR + D_ROPE)    /* 576  */
#define HDIM   (D_NOPE + D_V)     /* 256  */
#define EPSF   1e-6f

typedef __half hf16;

// ---------------- scratch: every tensor is [2][elems] fp16 planes ----------
__device__ hf16 g_xp   [2 * (size_t)MS * DMODEL];
__device__ hf16 g_wqaT [2 * (size_t)QLR * DMODEL];
__device__ hf16 g_wkvaT[2 * (size_t)KVD * DMODEL];
__device__ hf16 g_wqbT [2 * (size_t)QDIM * QLR];
__device__ hf16 g_wkvbT[2 * (size_t)NH * HDIM * KVLR];
__device__ hf16 g_woT  [2 * (size_t)DMODEL * DMODEL];
__device__ hf16 g_qa   [2 * (size_t)MS * QLR];
__device__ hf16 g_q    [2 * (size_t)MS * QDIM];
__device__ hf16 g_kv   [2 * (size_t)MS * KVD];
__device__ hf16 g_kext [2 * (size_t)MS * KVD];
__device__ hf16 g_kabs [2 * (size_t)BSZ * NH * SEQ * D_NOPE];
__device__ hf16 g_vT   [2 * (size_t)BSZ * NH * D_V * SEQ];
__device__ hf16 g_ohead[2 * (size_t)MS * DMODEL];

// ------------------------------ helpers -------------------------------------
__device__ __forceinline__ void split2(float x, hf16& h, hf16& l) {
    h = __float2half_rn(x);
    l = __float2half_rn(x - __half2float(h));
}
__device__ __forceinline__ float join2(hf16 h, hf16 l) {
    return __half2float(h) + __half2float(l);
}
__device__ __forceinline__ void cp16(uint32_t smem, const void* g, int srcBytes) {
    asm volatile("cp.async.cg.shared.global [%0], [%1], 16, %2;"
                 :: "r"(smem), "l"(g), "r"(srcBytes));
}
__device__ __forceinline__ void cp_commit() { asm volatile("cp.async.commit_group;"); }
__device__ __forceinline__ void cp_wait1()  { asm volatile("cp.async.wait_group 1;"); }

__device__ __forceinline__ void ldsm4(uint32_t* r, uint32_t addr) {
    asm volatile("ldmatrix.sync.aligned.m8n8.x4.shared.b16 {%0,%1,%2,%3}, [%4];"
                 : "=r"(r[0]), "=r"(r[1]), "=r"(r[2]), "=r"(r[3]) : "r"(addr));
}
__device__ __forceinline__ void mma_f32(float* d, const uint32_t* a,
                                        uint32_t b0, uint32_t b1) {
    asm volatile(
        "mma.sync.aligned.m16n8k16.row.col.f32.f16.f16.f32 "
        "{%0,%1,%2,%3}, {%4,%5,%6,%7}, {%8,%9}, {%0,%1,%2,%3};"
        : "+f"(d[0]), "+f"(d[1]), "+f"(d[2]), "+f"(d[3])
        : "r"(a[0]), "r"(a[1]), "r"(a[2]), "r"(a[3]), "r"(b0), "r"(b1));
}

// ----------------------------- GEMM kernel ----------------------------------
// C = A * B^T. A: [M][K] fp16 (hi plane only consumed), row stride lda.
// B: [N][K] planes (hi at B, lo at B+bPS), row stride ldb; bLo=0 -> hi only.
// CTA tile 128x128, K-slab 16, 8 warps, warp tile 64x32.
// outMode 0: fp32 C. outMode 1: fp16 planes C (lo at +cPS).
struct GemmP {
    const hf16 *A, *B; void* C;
    long long bPS, cPS;
    int M, N, K;
    long long lda, ldb, ldc;
    long long aSb, aSh, bSb, bSh, cSb, cSh;
    int nInner, causal, outMode, bLo;
};

// stage: Ah[0,4096) Bh[4096,8192) Bl[8192,12288)
#define STG_BYTES 12288

__global__ __launch_bounds__(256, 2) void gemm_hmma(GemmP p) {
    __shared__ __align__(16) hf16 stg[3][3][128 * 16];   // 36KB

    const int m0 = blockIdx.y * 128;
    const int n0 = blockIdx.x * 128;
    if (p.causal == 1 && n0 >= m0 + 128) return;

    const int z  = blockIdx.z;
    const int zb = z / p.nInner;
    const int zh = z - zb * p.nInner;
    const hf16* A = p.A + zb * p.aSb + zh * p.aSh;
    const hf16* B = p.B + zb * p.bSb + zh * p.bSh;

    int kEnd = p.K;
    if (p.causal == 2) { int km = m0 + 128; if (km < kEnd) kEnd = km; }
    const int nSlab = kEnd >> 4;
    const bool blo = (p.bLo != 0);

    const int tid  = threadIdx.x;
    const int lane = tid & 31;
    const int warp = tid >> 5;
    const int wm   = warp >> 2;    // 0..1
    const int wn   = warp & 3;     // 0..3

    const uint32_t smBase = (uint32_t)__cvta_generic_to_shared(&stg[0][0][0]);

    const int r  = tid >> 1;
    const int cc = tid & 1;
    const uint32_t pOff = (uint32_t)(r * 32 + ((cc ^ ((r >> 2) & 1)) << 4));

    int mr = m0 + r;
    const bool aok = mr < p.M;
    if (!aok) mr = m0;
    const hf16* gA0 = A + (size_t)mr * p.lda + cc * 8;
    const int asz = aok ? 16 : 0;
    int nr = n0 + r;
    const bool bok = nr < p.N;
    if (!bok) nr = n0;
    const hf16* gB0 = B + (size_t)nr * p.ldb + cc * 8;
    const hf16* gB1 = gB0 + p.bPS;
    const int bsz = bok ? 16 : 0;

#define ISSUE(S)                                                               \
    do {                                                                       \
        uint32_t sb = smBase + (uint32_t)(((S) % 3) * STG_BYTES);              \
        const size_t ko = (size_t)(S) * 16;                                    \
        cp16(sb + pOff,        gA0 + ko, asz);                                 \
        cp16(sb + 4096 + pOff, gB0 + ko, bsz);                                 \
        if (blo) cp16(sb + 8192 + pOff, gB1 + ko, bsz);                        \
    } while (0)

    const int rowA = wm * 64 + (lane & 7) + ((lane >> 3) & 1) * 8;
    const int cA   = lane >> 4;
    const uint32_t offA = (uint32_t)(rowA * 32 + ((cA ^ ((rowA >> 2) & 1)) << 4));
    const int rowB = wn * 32 + (lane & 7) + ((lane >> 4) << 3);
    const int cB   = (lane >> 3) & 1;
    const uint32_t offB = (uint32_t)(rowB * 32 + ((cB ^ ((rowB >> 2) & 1)) << 4));

    float acc[4][4][4];
#pragma unroll
    for (int i = 0; i < 4; ++i)
#pragma unroll
        for (int j = 0; j < 4; ++j)
#pragma unroll
            for (int l = 0; l < 4; ++l) acc[i][j][l] = 0.f;

    ISSUE(0); cp_commit();
    if (nSlab > 1) ISSUE(1);
    cp_commit();

    for (int it = 0; it < nSlab; ++it) {
        cp_wait1();
        __syncthreads();

        const uint32_t sb   = smBase + (uint32_t)((it % 3) * STG_BYTES);
        const uint32_t aAdr = sb + offA;
        const uint32_t bAdr = sb + 4096 + offB;

        uint32_t bh[2][4], bl[2][4];
        ldsm4(bh[0], bAdr);
        ldsm4(bh[1], bAdr + 512);
        if (blo) {
            ldsm4(bl[0], bAdr + 4096);
            ldsm4(bl[1], bAdr + 4096 + 512);
        }

#pragma unroll
        for (int mi = 0; mi < 4; ++mi) {
            uint32_t ah[4];
            ldsm4(ah, aAdr + mi * 512);
#pragma unroll
            for (int nt = 0; nt < 4; ++nt) {
                const int np = nt >> 1, hf = (nt & 1) * 2;
                mma_f32(acc[mi][nt], ah, bh[np][hf], bh[np][hf + 1]);
                if (blo) mma_f32(acc[mi][nt], ah, bl[np][hf], bl[np][hf + 1]);
            }
        }

        if (it + 2 < nSlab) ISSUE(it + 2);
        cp_commit();
    }
#undef ISSUE

    const int g = lane >> 2;
    const int c = lane & 3;
    if (p.outMode == 0) {
        float* C = (float*)p.C + zb * p.cSb + zh * p.cSh;
#pragma unroll
        for (int mi = 0; mi < 4; ++mi) {
            const int gm = m0 + wm * 64 + mi * 16 + g;
            if (gm >= p.M) continue;
            float* r0 = C + (long long)gm * p.ldc;
            float* r1 = r0 + 8 * p.ldc;
#pragma unroll
            for (int nt = 0; nt < 4; ++nt) {
                const int gn = n0 + wn * 32 + nt * 8 + 2 * c;
                if (gn < p.N) {
                    *(float2*)(r0 + gn) = make_float2(acc[mi][nt][0], acc[mi][nt][1]);
                    *(float2*)(r1 + gn) = make_float2(acc[mi][nt][2], acc[mi][nt][3]);
                }
            }
        }
    } else {
        hf16* Ch = (hf16*)p.C + zb * p.cSb + zh * p.cSh;
        hf16* Cl = Ch + p.cPS;
#pragma unroll
        for (int mi = 0; mi < 4; ++mi) {
            const int gm = m0 + wm * 64 + mi * 16 + g;
            if (gm >= p.M) continue;
            const long long ro0 = (long long)gm * p.ldc;
            const long long ro1 = ro0 + 8 * p.ldc;
#pragma unroll
            for (int nt = 0; nt < 4; ++nt) {
                const int gn = n0 + wn * 32 + nt * 8 + 2 * c;
                if (gn < p.N) {
                    hf16 h0, l0, h1, l1;
                    split2(acc[mi][nt][0], h0, l0);
                    split2(acc[mi][nt][1], h1, l1);
                    *(__half2*)(Ch + ro0 + gn) = __halves2half2(h0, h1);
                    *(__half2*)(Cl + ro0 + gn) = __halves2half2(l0, l1);
                    split2(acc[mi][nt][2], h0, l0);
                    split2(acc[mi][nt][3], h1, l1);
                    *(__half2*)(Ch + ro1 + gn) = __halves2half2(h0, h1);
                    *(__half2*)(Cl + ro1 + gn) = __halves2half2(l0, l1);
                }
            }
        }
    }
}

// --------------------------- flash attention --------------------------------
// TM=64 q-rows per CTA, 2 CTAs/SM. grid (32 q-blocks, 32 bh).
// Q and P are fp16 (hi only); K/V sides keep hi/lo planes.
// smem layout (bytes):
//   Qh 0..25600                      (64 rows x 400B, 192 cols used)
//   Ph 25600..43008                  (64 rows x 272B, 128 cols used)
//   stages 43008 + s*8192 (Bh 4KB, Bl 4KB), 3 stages -> 67584
//   RED 67584..68608 (float[4][64])
#define FL_SMEM 68608

__global__ __launch_bounds__(256, 2) void flash_k(
    const hf16* __restrict__ q, const hf16* __restrict__ kabs,
    const hf16* __restrict__ kext, const hf16* __restrict__ vT,
    hf16* __restrict__ ohead, float s2) {
    extern __shared__ __align__(16) char dyn[];
    const int tid = threadIdx.x, lane = tid & 31, warp = tid >> 5;
    const int wm = warp >> 2, wn = warp & 3, g = lane >> 2, c = lane & 3;
    const int iq = 31 - blockIdx.x;       // heavy blocks first
    const int bh = blockIdx.y, b = bh >> 4, h = bh & 15;
    const int m0 = iq * 64;
    const int nkv = (iq >> 1) + 1;
    const long long psKA = (long long)BSZ * NH * SEQ * D_NOPE;
    const long long psKV = (long long)MS * KVD;
    const long long psVT = (long long)BSZ * NH * D_V * SEQ;
    const long long psOH = (long long)MS * DMODEL;

    const uint32_t smb = (uint32_t)__cvta_generic_to_shared(dyn);
    const uint32_t smQ = smb;
    const uint32_t smP = smb + 25600;
    const uint32_t smS = smb + 43008;
    float* RED = (float*)(dyn + 67584);

    // ---- Q block load: 64 rows, hi plane only; 4 threads/row, 6 chunks each
    {
        const int r = tid >> 2, sub = tid & 3;
        const hf16* src = q + ((size_t)(b * SEQ + m0 + r)) * QDIM + h * D_QK + sub * 48;
        const uint32_t d0 = smQ + (uint32_t)(r * 400 + sub * 96);
#pragma unroll
        for (int ch = 0; ch < 6; ++ch) cp16(d0 + ch * 16, src + ch * 8, 16);
        cp_commit();
    }

    const int prow = tid >> 1, pcc = tid & 1;
    const uint32_t pOff = (uint32_t)(prow * 32 + ((pcc ^ ((prow >> 2) & 1)) << 4));
    const hf16* ka = kabs + (size_t)bh * SEQ * D_NOPE;
    const hf16* ke = kext + (size_t)b * SEQ * KVD;
    const hf16* vt = vT + (size_t)bh * D_V * SEQ;
    const int u_total = 20 * nkv;

    // slab u -> (kv block j = u/20, s = u%20):
    //   s<8: K-nope from kabs; s in 8..11: pe from kext; s>=12: V-slab
#define FL_ISSUE(U)                                                            \
    do {                                                                       \
        const int _j = (U) / 20, _s = (U) % 20;                                \
        uint32_t _sb = smS + (uint32_t)(((U) % 3) * 8192);                     \
        const hf16* _s0; long long _ps;                                        \
        if (_s < 8) {                                                          \
            _s0 = ka + ((size_t)(_j * 128 + prow)) * D_NOPE + _s * 16 + pcc * 8; \
            _ps = psKA;                                                        \
        } else if (_s < 12) {                                                  \
            _s0 = ke + ((size_t)(_j * 128 + prow)) * KVD + KVLR                \
                     + (_s - 8) * 16 + pcc * 8;                                \
            _ps = psKV;                                                        \
        } else {                                                               \
            _s0 = vt + (size_t)prow * SEQ + _j * 128 + (_s - 12) * 16 + pcc * 8; \
            _ps = psVT;                                                        \
        }                                                                      \
        cp16(_sb + pOff, _s0, 16);                                             \
        cp16(_sb + 4096 + pOff, _s0 + _ps, 16);                                \
    } while (0)

    FL_ISSUE(0); cp_commit();
    FL_ISSUE(1); cp_commit();

    // consumer fragment offsets
    const int rowA = wm * 32 + (lane & 7) + ((lane >> 3) & 1) * 8;
    const int cA   = lane >> 4;
    const uint32_t offAq = (uint32_t)(rowA * 400 + cA * 16);
    const uint32_t offAp = (uint32_t)(rowA * 272 + cA * 16);
    const int rowB = wn * 32 + (lane & 7) + ((lane >> 4) << 3);
    const int cB   = (lane >> 3) & 1;
    const uint32_t offB = (uint32_t)(rowB * 32 + ((cB ^ ((rowB >> 2) & 1)) << 4));

    float oacc[2][4][4];
    float m_r[2][2], l_r[2][2];
#pragma unroll
    for (int mi = 0; mi < 2; ++mi) {
#pragma unroll
        for (int nt = 0; nt < 4; ++nt)
#pragma unroll
            for (int k = 0; k < 4; ++k) oacc[mi][nt][k] = 0.f;
        m_r[mi][0] = m_r[mi][1] = -1e30f;
        l_r[mi][0] = l_r[mi][1] = 0.f;
    }

    int u = 0;
    for (int j = 0; j < nkv; ++j) {
        float sacc[2][4][4];
#pragma unroll
        for (int mi = 0; mi < 2; ++mi)
#pragma unroll
            for (int nt = 0; nt < 4; ++nt)
#pragma unroll
                for (int k = 0; k < 4; ++k) sacc[mi][nt][k] = 0.f;

        // ---- S phase: 12 K-slabs (K=192) ----
        for (int s = 0; s < 12; ++s) {
            cp_wait1(); __syncthreads();
            const uint32_t sb = smS + (uint32_t)((u % 3) * 8192);
            uint32_t bh4[2][4], bl4[2][4];
            ldsm4(bh4[0], sb + offB); ldsm4(bh4[1], sb + offB + 512);
            ldsm4(bl4[0], sb + 4096 + offB); ldsm4(bl4[1], sb + 4096 + offB + 512);
#pragma unroll
            for (int mi = 0; mi < 2; ++mi) {
                uint32_t ah[4];
                ldsm4(ah, smQ + offAq + mi * 6400 + s * 32);
#pragma unroll
                for (int nt = 0; nt < 4; ++nt) {
                    const int np = nt >> 1, hf2 = (nt & 1) * 2;
                    mma_f32(sacc[mi][nt], ah, bh4[np][hf2], bh4[np][hf2 + 1]);
                    mma_f32(sacc[mi][nt], ah, bl4[np][hf2], bl4[np][hf2 + 1]);
                }
            }
            if (u + 2 < u_total) FL_ISSUE(u + 2);
            cp_commit(); ++u;
        }

        // ---- causal mask on last kv block ----
        if (j == nkv - 1) {
#pragma unroll
            for (int mi = 0; mi < 2; ++mi)
#pragma unroll
                for (int nt = 0; nt < 4; ++nt)
#pragma unroll
                    for (int k = 0; k < 4; ++k) {
                        const int rl = m0 + wm * 32 + mi * 16 + g + (k >> 1) * 8;
                        const int cl = j * 128 + wn * 32 + nt * 8 + 2 * c + (k & 1);
                        if (cl > rl) sacc[mi][nt][k] = -1e30f;
                    }
        }

        // ---- online softmax ----
        float alpha[2][2];
#pragma unroll
        for (int mi = 0; mi < 2; ++mi)
#pragma unroll
            for (int h2 = 0; h2 < 2; ++h2) {
                float v = fmaxf(fmaxf(sacc[mi][0][h2 * 2], sacc[mi][0][h2 * 2 + 1]),
                                fmaxf(sacc[mi][1][h2 * 2], sacc[mi][1][h2 * 2 + 1]));
                v = fmaxf(v, fmaxf(fmaxf(sacc[mi][2][h2 * 2], sacc[mi][2][h2 * 2 + 1]),
                                   fmaxf(sacc[mi][3][h2 * 2], sacc[mi][3][h2 * 2 + 1])));
                v = fmaxf(v, __shfl_xor_sync(0xffffffffu, v, 1));
                v = fmaxf(v, __shfl_xor_sync(0xffffffffu, v, 2));
                if (c == 0) RED[wn * 64 + wm * 32 + mi * 16 + g + h2 * 8] = v;
            }
        __syncthreads();
#pragma unroll
        for (int mi = 0; mi < 2; ++mi)
#pragma unroll
            for (int h2 = 0; h2 < 2; ++h2) {
                const int row = wm * 32 + mi * 16 + g + h2 * 8;
                float mrow = fmaxf(fmaxf(RED[row], RED[64 + row]),
                                   fmaxf(RED[128 + row], RED[192 + row]));
                float mnew = fmaxf(m_r[mi][h2], mrow);
                alpha[mi][h2] = exp2f((m_r[mi][h2] - mnew) * s2);
                m_r[mi][h2] = mnew;
            }
        __syncthreads();   // RED reads done before sum-round rewrite
#pragma unroll
        for (int mi = 0; mi < 2; ++mi)
#pragma unroll
            for (int h2 = 0; h2 < 2; ++h2) {
                const float mn = m_r[mi][h2];
                const float a = alpha[mi][h2];
                float sum = 0.f;
#pragma unroll
                for (int nt = 0; nt < 4; ++nt) {
                    float p0 = exp2f((sacc[mi][nt][h2 * 2] - mn) * s2);
                    float p1 = exp2f((sacc[mi][nt][h2 * 2 + 1] - mn) * s2);
                    sacc[mi][nt][h2 * 2] = p0;
                    sacc[mi][nt][h2 * 2 + 1] = p1;
                    oacc[mi][nt][h2 * 2] *= a;
                    oacc[mi][nt][h2 * 2 + 1] *= a;
                    sum += p0 + p1;
                }
                sum += __shfl_xor_sync(0xffffffffu, sum, 1);
                sum += __shfl_xor_sync(0xffffffffu, sum, 2);
                if (c == 0) RED[wn * 64 + wm * 32 + mi * 16 + g + h2 * 8] = sum;
            }
        // write P (hi plane only) to smem
#pragma unroll
        for (int mi = 0; mi < 2; ++mi)
#pragma unroll
            for (int nt = 0; nt < 4; ++nt) {
                const int r0 = wm * 32 + mi * 16 + g;
                const int cb = wn * 32 + nt * 8 + 2 * c;
                *(__half2*)(dyn + 25600 + r0 * 272 + cb * 2) =
                    __halves2half2(__float2half_rn(sacc[mi][nt][0]),
                                   __float2half_rn(sacc[mi][nt][1]));
                *(__half2*)(dyn + 25600 + (r0 + 8) * 272 + cb * 2) =
                    __halves2half2(__float2half_rn(sacc[mi][nt][2]),
                                   __float2half_rn(sacc[mi][nt][3]));
            }
        __syncthreads();   // P + sums visible
#pragma unroll
        for (int mi = 0; mi < 2; ++mi)
#pragma unroll
            for (int h2 = 0; h2 < 2; ++h2) {
                const int row = wm * 32 + mi * 16 + g + h2 * 8;
                const float ls = RED[row] + RED[64 + row] + RED[128 + row] + RED[192 + row];
                l_r[mi][h2] = l_r[mi][h2] * alpha[mi][h2] + ls;
            }

        // ---- PV phase: 8 V-slabs (K=128 over t) ----
        for (int s = 0; s < 8; ++s) {
            cp_wait1(); __syncthreads();
            const uint32_t sb = smS + (uint32_t)((u % 3) * 8192);
            uint32_t vh4[2][4], vl4[2][4];
            ldsm4(vh4[0], sb + offB); ldsm4(vh4[1], sb + offB + 512);
            ldsm4(vl4[0], sb + 4096 + offB); ldsm4(vl4[1], sb + 4096 + offB + 512);
#pragma unroll
            for (int mi = 0; mi < 2; ++mi) {
                uint32_t ph[4];
                ldsm4(ph, smP + offAp + mi * 4352 + s * 32);
#pragma unroll
                for (int nt = 0; nt < 4; ++nt) {
                    const int np = nt >> 1, hf2 = (nt & 1) * 2;
                    mma_f32(oacc[mi][nt], ph, vh4[np][hf2], vh4[np][hf2 + 1]);
                    mma_f32(oacc[mi][nt], ph, vl4[np][hf2], vl4[np][hf2 + 1]);
                }
            }
            if (u + 2 < u_total) FL_ISSUE(u + 2);
            cp_commit(); ++u;
        }
    }
#undef FL_ISSUE

    // ---- epilogue: O / l -> ohead planes ----
    hf16* Cb = ohead + (size_t)(b * SEQ + m0) * DMODEL + h * D_V;
#pragma unroll
    for (int mi = 0; mi < 2; ++mi) {
        const int r0 = wm * 32 + mi * 16 + g;
        const float i0 = 1.f / l_r[mi][0], i1 = 1.f / l_r[mi][1];
#pragma unroll
        for (int nt = 0; nt < 4; ++nt) {
            const int cb = wn * 32 + nt * 8 + 2 * c;
            hf16 h0, l0, h1, l1;
            split2(oacc[mi][nt][0] * i0, h0, l0);
            split2(oacc[mi][nt][1] * i0, h1, l1);
            hf16* p = Cb + (size_t)r0 * DMODEL + cb;
            *(__half2*)p = __halves2half2(h0, h1);
            *(__half2*)(p + psOH) = __halves2half2(l0, l1);
            split2(oacc[mi][nt][2] * i1, h0, l0);
            split2(oacc[mi][nt][3] * i1, h1, l1);
            p = Cb + (size_t)(r0 + 8) * DMODEL + cb;
            *(__half2*)p = __halves2half2(h0, h1);
            *(__half2*)(p + psOH) = __halves2half2(l0, l1);
        }
    }
}

// ---------------------------- block reduction ------------------------------
__device__ __forceinline__ float blockReduce(float v, bool isMax) {
    __shared__ float sh[32];
    const int lane = threadIdx.x & 31, wid = threadIdx.x >> 5;
    __syncthreads();
#pragma unroll
    for (int o = 16; o > 0; o >>= 1) {
        float t = __shfl_down_sync(0xffffffffu, v, o);
        v = isMax ? fmaxf(v, t) : (v + t);
    }
    if (lane == 0) sh[wid] = v;
    __syncthreads();
    const int nw = blockDim.x >> 5;
    if (wid == 0) {
        v = (lane < nw) ? sh[lane] : (isMax ? -1e30f : 0.f);
#pragma unroll
        for (int o = 16; o > 0; o >>= 1) {
            float t = __shfl_down_sync(0xffffffffu, v, o);
            v = isMax ? fmaxf(v, t) : (v + t);
        }
        if (lane == 0) sh[0] = v;
    }
    __syncthreads();
    return sh[0];
}

// ------------------------------ aux kernels --------------------------------
__global__ void pack2_k(const float* __restrict__ in, hf16* __restrict__ out,
                        long long ps, int n) {
    for (int i = blockIdx.x * blockDim.x + threadIdx.x; i < n; i += gridDim.x * blockDim.x) {
        hf16 h, l; split2(in[i], h, l);
        out[i] = h; out[i + ps] = l;
    }
}

// fp32 [R][C] -> planes [C][R]
__global__ void packT2_k(const float* __restrict__ in, hf16* __restrict__ out,
                         long long ps, int R, int C) {
    __shared__ float t[32][33];
    const int c0 = blockIdx.x * 32, r0 = blockIdx.y * 32;
#pragma unroll
    for (int i = threadIdx.y; i < 32; i += 8)
        t[i][threadIdx.x] = in[(long long)(r0 + i) * C + c0 + threadIdx.x];
    __syncthreads();
#pragma unroll
    for (int i = threadIdx.y; i < 32; i += 8) {
        hf16 h, l; split2(t[threadIdx.x][i], h, l);
        long long o = (long long)(c0 + i) * R + r0 + threadIdx.x;
        out[o] = h; out[o + ps] = l;
    }
}

__global__ void rmsnorm_rows_k(hf16* x, long long ps, const float* __restrict__ w, int n) {
    long long base = (long long)blockIdx.x * n;
    float ss = 0.f;
    for (int i = threadIdx.x; i < n; i += blockDim.x) {
        float v = join2(x[base + i], x[base + i + ps]); ss += v * v;
    }
    ss = blockReduce(ss, false);
    float rn = rsqrtf(ss / (float)n + EPSF);
    for (int i = threadIdx.x; i < n; i += blockDim.x) {
        float v = join2(x[base + i], x[base + i + ps]) * rn * w[i];
        hf16 h, l; split2(v, h, l);
        x[base + i] = h; x[base + i + ps] = l;
    }
}

__global__ void kv_process_k(const hf16* __restrict__ kv, hf16* __restrict__ kext,
                             const float* __restrict__ w, const float* __restrict__ freqs) {
    const long long psKV = (long long)MS * KVD;
    const int m = blockIdx.x;
    const int s = m & (SEQ - 1);
    const hf16* kr = kv   + (long long)m * KVD;
    hf16*       ke = kext + (long long)m * KVD;
    float ss = 0.f;
    for (int i = threadIdx.x; i < KVLR; i += blockDim.x) {
        float v = join2(kr[i], kr[i + psKV]); ss += v * v;
    }
    ss = blockReduce(ss, false);
    float rn = rsqrtf(ss / (float)KVLR + EPSF);
    for (int i = threadIdx.x; i < KVLR; i += blockDim.x) {
        float v = join2(kr[i], kr[i + psKV]) * rn * w[i];
        hf16 h, l; split2(v, h, l);
        ke[i] = h; ke[i + psKV] = l;
    }
    if (threadIdx.x < 32) {
        const int i = threadIdx.x;
        float th = freqs[s * 32 + i];
        float co, sn; sincosf(th, &sn, &co);
        float x0 = join2(kr[KVLR + 2 * i], kr[KVLR + 2 * i + psKV]);
        float x1 = join2(kr[KVLR + 2 * i + 1], kr[KVLR + 2 * i + 1 + psKV]);
        hf16 h, l;
        split2(x0 * co - x1 * sn, h, l);
        ke[KVLR + 2 * i] = h; ke[KVLR + 2 * i + psKV] = l;
        split2(x0 * sn + x1 * co, h, l);
        ke[KVLR + 2 * i + 1] = h; ke[KVLR + 2 * i + 1 + psKV] = l;
    }
}

// rope q_pe in place inside g_q planes ([m][h*192+128 .. +191])
__global__ void rope_q_k(hf16* q, const float* __restrict__ freqs) {
    const long long psQ = (long long)MS * QDIM;
    const int m = blockIdx.x;
    const int s = m & (SEQ - 1);
    const int h = threadIdx.x >> 5;
    const int i = threadIdx.x & 31;
    float th = freqs[s * 32 + i];
    float co, sn; sincosf(th, &sn, &co);
    hf16* qr = q + (long long)m * QDIM + h * D_QK + D_NOPE;
    float x0 = join2(qr[2 * i], qr[2 * i + psQ]);
    float x1 = join2(qr[2 * i + 1], qr[2 * i + 1 + psQ]);
    hf16 hh, ll;
    split2(x0 * co - x1 * sn, hh, ll);
    qr[2 * i] = hh; qr[2 * i + psQ] = ll;
    split2(x0 * sn + x1 * co, hh, ll);
    qr[2 * i + 1] = hh; qr[2 * i + 1 + psQ] = ll;
}

// ------------------------------- host side ---------------------------------
static void launchGemm(const hf16* A, const hf16* B, long long bPS,
                       void* C, long long cPS,
                       int M, int N, int K,
                       long long lda, long long ldb, long long ldc,
                       int nb, int nInner,
                       long long aSb, long long aSh,
                       long long bSb, long long bSh,
                       long long cSb, long long cSh,
                       int causal, int outMode, int bLo) {
    GemmP p;
    p.A = A; p.B = B; p.C = C;
    p.bPS = bPS; p.cPS = cPS;
    p.M = M; p.N = N; p.K = K;
    p.lda = lda; p.ldb = ldb; p.ldc = ldc;
    p.aSb = aSb; p.aSh = aSh; p.bSb = bSb; p.bSh = bSh; p.cSb = cSb; p.cSh = cSh;
    p.nInner = nInner; p.causal = causal; p.outMode = outMode; p.bLo = bLo;
    dim3 grid((N + 127) / 128, (M + 127) / 128, nb);
    gemm_hmma<<<grid, 256>>>(p);
}

extern "C" void kernel_launch(void* const* d_in, const int* in_sizes, int n_in,
                              void* d_out, int out_size) {
    const float* x         = (const float*)d_in[0];
    const float* freqs     = (const float*)d_in[1];
    const float* wq_a      = (const float*)d_in[3];
    const float* q_norm_w  = (const float*)d_in[4];
    const float* wq_b      = (const float*)d_in[5];
    const float* wkv_a     = (const float*)d_in[6];
    const float* kv_norm_w = (const float*)d_in[7];
    const float* wkv_b     = (const float*)d_in[8];
    const float* wo        = (const float*)d_in[9];
    float* out = (float*)d_out;

    cudaFuncSetAttribute(flash_k, cudaFuncAttributeMaxDynamicSharedMemorySize, FL_SMEM);

    hf16 *xp, *wqaT, *wkvaT, *wqbT, *wkvbT, *woT;
    hf16 *qa, *q, *kv, *kext, *kabs, *vT, *ohead;
    cudaGetSymbolAddress((void**)&xp,     g_xp);
    cudaGetSymbolAddress((void**)&wqaT,   g_wqaT);
    cudaGetSymbolAddress((void**)&wkvaT,  g_wkvaT);
    cudaGetSymbolAddress((void**)&wqbT,   g_wqbT);
    cudaGetSymbolAddress((void**)&wkvbT,  g_wkvbT);
    cudaGetSymbolAddress((void**)&woT,    g_woT);
    cudaGetSymbolAddress((void**)&qa,     g_qa);
    cudaGetSymbolAddress((void**)&q,      g_q);
    cudaGetSymbolAddress((void**)&kv,     g_kv);
    cudaGetSymbolAddress((void**)&kext,   g_kext);
    cudaGetSymbolAddress((void**)&kabs,   g_kabs);
    cudaGetSymbolAddress((void**)&vT,     g_vT);
    cudaGetSymbolAddress((void**)&ohead,  g_ohead);

    const float scale = 1.0f / sqrtf((float)D_QK);
    const float s2 = scale * 1.4426950408889634f;   // scale * log2(e)

    // plane strides
    const long long psX   = (long long)MS * DMODEL;
    const long long psWQA = (long long)QLR * DMODEL;
    const long long psWKA = (long long)KVD * DMODEL;
    const long long psWQB = (long long)QDIM * QLR;
    const long long psWBT = (long long)NH * HDIM * KVLR;
    const long long psWO  = (long long)DMODEL * DMODEL;
    const long long psQA  = (long long)MS * QLR;
    const long long psQ   = (long long)MS * QDIM;
    const long long psKV  = (long long)MS * KVD;
    const long long psKA  = (long long)BSZ * NH * SEQ * D_NOPE;
    const long long psVT  = (long long)BSZ * NH * D_V * SEQ;
    const long long psOH  = (long long)MS * DMODEL;

    // ---- pack inputs into planes ----
    pack2_k<<<512, 256>>>(x, xp, psX, MS * DMODEL);
    packT2_k<<<dim3(QLR / 32, DMODEL / 32), dim3(32, 8)>>>(wq_a, wqaT, psWQA, DMODEL, QLR);
    packT2_k<<<dim3(KVD / 32, DMODEL / 32), dim3(32, 8)>>>(wkv_a, wkvaT, psWKA, DMODEL, KVD);
    packT2_k<<<dim3(QDIM / 32, QLR / 32), dim3(32, 8)>>>(wq_b, wqbT, psWQB, QLR, QDIM);
    packT2_k<<<dim3((NH * HDIM) / 32, KVLR / 32), dim3(32, 8)>>>(wkv_b, wkvbT, psWBT, KVLR, NH * HDIM);
    packT2_k<<<dim3(DMODEL / 32, DMODEL / 32), dim3(32, 8)>>>(wo, woT, psWO, DMODEL, DMODEL);

    // 1. qa = x @ wq_a   (B hi only)
    launchGemm(xp, wqaT, psWQA, qa, psQA, MS, QLR, DMODEL,
               DMODEL, DMODEL, QLR, 1, 1, 0, 0, 0, 0, 0, 0, 0, 1, 0);
    // 2. kv = x @ wkv_a (N=576, B planes)
    launchGemm(xp, wkvaT, psWKA, kv, psKV, MS, KVD, DMODEL,
               DMODEL, DMODEL, KVD, 1, 1, 0, 0, 0, 0, 0, 0, 0, 1, 1);
    // 3. rmsnorm(qa)
    rmsnorm_rows_k<<<MS, 256>>>(qa, psQA, q_norm_w, QLR);
    // 4. kext = [rmsnorm(latent), rope(k_pe)]
    kv_process_k<<<MS, 256>>>(kv, kext, kv_norm_w, freqs);
    // 5. q = qa @ wq_b (B planes)
    launchGemm(qa, wqbT, psWQB, q, psQ, MS, QDIM, QLR,
               QLR, QLR, QDIM, 1, 1, 0, 0, 0, 0, 0, 0, 0, 1, 1);
    // 6. rope q_pe in place
    rope_q_k<<<MS, NH * 32>>>(q, freqs);
    // 7. k_abs[b,h,s,0:128] = kv_cache @ Wuk[h]^T (B planes)
    launchGemm(kext, wkvbT, psWBT, kabs, psKA,
               SEQ, D_NOPE, KVLR,
               KVD, KVLR, D_NOPE,
               BSZ * NH, NH,
               (long long)SEQ * KVD, 0,
               0, (long long)HDIM * KVLR,
               (long long)NH * SEQ * D_NOPE, (long long)SEQ * D_NOPE,
               0, 1, 1);
    // 8. vT[b,h,d,t] = Wuv[h] @ kv_cache^T (B = kext planes)
    launchGemm(wkvbT + (long long)D_NOPE * KVLR, kext, psKV, vT, psVT,
               D_V, SEQ, KVLR,
               KVLR, KVD, SEQ,
               BSZ * NH, NH,
               0, (long long)HDIM * KVLR,
               (long long)SEQ * KVD, 0,
               (long long)NH * D_V * SEQ, (long long)D_V * SEQ,
               0, 1, 1);
    // 9. fused flash attention -> ohead planes
    flash_k<<<dim3(32, BSZ * NH), 256, FL_SMEM>>>(q, kabs, kext, vT, ohead, s2);
    // 10. out = ohead @ wo (fp32 out, B hi only)
    launchGemm(ohead, woT, psWO, out, 0, MS, DMODEL, DMODEL,
               DMODEL, DMODEL, DMODEL, 1, 1, 0, 0, 0, 0, 0, 0, 0, 0, 0);
}

// round 14
// speedup vs baseline: 1.5627x; 1.1182x over previous
#include <cuda_runtime.h>
#include <cuda_fp16.h>
#include <math.h>
#include <stdint.h>

// ---------------------------------------------------------------------------
// MLA forward, per-head expanded attention + fused flash attention.
// GEMMs: fp16x2 emulated fp32: D = Ah*(Bh + Bl), f32 accumulate, K-slab 32
// (dynamic smem, 64B rows, 2-bit XOR swizzle). B lo plane kept only where it
// matters (kv, kabs, vT, flash K/V); qa, q, wo use plain fp16 B.
// ---------------------------------------------------------------------------

#define BSZ    2
#define SEQ    2048
#define DMODEL 2048
#define NH     16
#define QLR    1536
#define KVLR   512
#define D_NOPE 128
#define D_ROPE 64
#define D_QK   192
#define D_V    128
#define MS     (BSZ*SEQ)          /* 4096 */
#define QDIM   (NH*D_QK)          /* 3072 */
#define KVD    (KVLR + D_ROPE)    /* 576  */
#define HDIM   (D_NOPE + D_V)     /* 256  */
#define EPSF   1e-6f

typedef __half hf16;

// ---------------- scratch: every tensor is [2][elems] fp16 planes ----------
__device__ hf16 g_xp   [2 * (size_t)MS * DMODEL];
__device__ hf16 g_wqaT [2 * (size_t)QLR * DMODEL];
__device__ hf16 g_wkvaT[2 * (size_t)KVD * DMODEL];
__device__ hf16 g_wqbT [2 * (size_t)QDIM * QLR];
__device__ hf16 g_wkvbT[2 * (size_t)NH * HDIM * KVLR];
__device__ hf16 g_woT  [2 * (size_t)DMODEL * DMODEL];
__device__ hf16 g_qa   [2 * (size_t)MS * QLR];
__device__ hf16 g_q    [2 * (size_t)MS * QDIM];
__device__ hf16 g_kv   [2 * (size_t)MS * KVD];
__device__ hf16 g_kext [2 * (size_t)MS * KVD];
__device__ hf16 g_kabs [2 * (size_t)BSZ * NH * SEQ * D_NOPE];
__device__ hf16 g_vT   [2 * (size_t)BSZ * NH * D_V * SEQ];
__device__ hf16 g_ohead[2 * (size_t)MS * DMODEL];

// ------------------------------ helpers -------------------------------------
__device__ __forceinline__ void split2(float x, hf16& h, hf16& l) {
    h = __float2half_rn(x);
    l = __float2half_rn(x - __half2float(h));
}
__device__ __forceinline__ float join2(hf16 h, hf16 l) {
    return __half2float(h) + __half2float(l);
}
__device__ __forceinline__ void cp16(uint32_t smem, const void* g, int srcBytes) {
    asm volatile("cp.async.cg.shared.global [%0], [%1], 16, %2;"
                 :: "r"(smem), "l"(g), "r"(srcBytes));
}
__device__ __forceinline__ void cp_commit() { asm volatile("cp.async.commit_group;"); }
__device__ __forceinline__ void cp_wait1()  { asm volatile("cp.async.wait_group 1;"); }

__device__ __forceinline__ void ldsm4(uint32_t* r, uint32_t addr) {
    asm volatile("ldmatrix.sync.aligned.m8n8.x4.shared.b16 {%0,%1,%2,%3}, [%4];"
                 : "=r"(r[0]), "=r"(r[1]), "=r"(r[2]), "=r"(r[3]) : "r"(addr));
}
__device__ __forceinline__ void mma_f32(float* d, const uint32_t* a,
                                        uint32_t b0, uint32_t b1) {
    asm volatile(
        "mma.sync.aligned.m16n8k16.row.col.f32.f16.f16.f32 "
        "{%0,%1,%2,%3}, {%4,%5,%6,%7}, {%8,%9}, {%0,%1,%2,%3};"
        : "+f"(d[0]), "+f"(d[1]), "+f"(d[2]), "+f"(d[3])
        : "r"(a[0]), "r"(a[1]), "r"(a[2]), "r"(a[3]), "r"(b0), "r"(b1));
}

// ----------------------------- GEMM kernel ----------------------------------
// C = A * B^T. A: [M][K] fp16 (hi plane only), row stride lda.
// B: [N][K] planes (hi at B, lo at B+bPS), row stride ldb; bLo=0 -> hi only.
// CTA tile 128x128, K-slab 32 (two k16 sub-steps/stage), 8 warps, 64x32 warp
// tile. Dyn smem: 3 stages x (A 8KB + Bh 8KB [+ Bl 8KB]). 64B rows with
// 2-bit XOR swizzle: physical chunk = logical ^ ((row>>1)&3).
// outMode 0: fp32 C. outMode 1: fp16 planes C (lo at +cPS).
struct GemmP {
    const hf16 *A, *B; void* C;
    long long bPS, cPS;
    int M, N, K;
    long long lda, ldb, ldc;
    long long aSb, aSh, bSb, bSh, cSb, cSh;
    int nInner, causal, outMode, bLo;
};

#define GEMM_DYN_MAX 73728

__global__ __launch_bounds__(256, 2) void gemm_hmma(GemmP p) {
    extern __shared__ __align__(16) unsigned char dynsm[];

    const int m0 = blockIdx.y * 128;
    const int n0 = blockIdx.x * 128;
    if (p.causal == 1 && n0 >= m0 + 128) return;

    const int z  = blockIdx.z;
    const int zb = z / p.nInner;
    const int zh = z - zb * p.nInner;
    const hf16* A = p.A + zb * p.aSb + zh * p.aSh;
    const hf16* B = p.B + zb * p.bSb + zh * p.bSh;

    int kEnd = p.K;
    if (p.causal == 2) { int km = m0 + 128; if (km < kEnd) kEnd = km; }
    const int nSlab = kEnd >> 5;
    const bool blo = (p.bLo != 0);
    const uint32_t stg = blo ? 24576u : 16384u;

    const int tid  = threadIdx.x;
    const int lane = tid & 31;
    const int warp = tid >> 5;
    const int wm   = warp >> 2;    // 0..1
    const int wn   = warp & 3;     // 0..3

    const uint32_t smBase = (uint32_t)__cvta_generic_to_shared(dynsm);

    // producer: row r (128), logical chunks cc and cc+2 (4 x 16B per 64B row)
    const int r  = tid >> 1;
    const int cc = tid & 1;
    const int xr = (r >> 1) & 3;
    const uint32_t po0 = (uint32_t)(r * 64 + (((cc)     ^ xr) << 4));
    const uint32_t po1 = (uint32_t)(r * 64 + (((cc + 2) ^ xr) << 4));

    int mr = m0 + r;
    const bool aok = mr < p.M;
    if (!aok) mr = m0;
    const hf16* gA0 = A + (size_t)mr * p.lda + cc * 8;
    const int asz = aok ? 16 : 0;
    int nr = n0 + r;
    const bool bok = nr < p.N;
    if (!bok) nr = n0;
    const hf16* gB0 = B + (size_t)nr * p.ldb + cc * 8;
    const hf16* gB1 = gB0 + p.bPS;
    const int bsz = bok ? 16 : 0;

#define ISSUE(S)                                                               \
    do {                                                                       \
        uint32_t sb = smBase + (uint32_t)((S) % 3) * stg;                      \
        const size_t ko = (size_t)(S) * 32;                                    \
        cp16(sb + po0,        gA0 + ko,      asz);                             \
        cp16(sb + po1,        gA0 + ko + 16, asz);                             \
        cp16(sb + 8192 + po0, gB0 + ko,      bsz);                             \
        cp16(sb + 8192 + po1, gB0 + ko + 16, bsz);                             \
        if (blo) {                                                             \
            cp16(sb + 16384 + po0, gB1 + ko,      bsz);                        \
            cp16(sb + 16384 + po1, gB1 + ko + 16, bsz);                        \
        }                                                                      \
    } while (0)

    // consumer fragment offsets (per k16 sub-step)
    const int rowA = wm * 64 + (lane & 15);
    const int cA   = lane >> 4;
    const int xrA  = (rowA >> 1) & 3;
    const uint32_t offA0 = (uint32_t)(rowA * 64 + (((cA)     ^ xrA) << 4));
    const uint32_t offA1 = (uint32_t)(rowA * 64 + (((cA + 2) ^ xrA) << 4));
    const int rowB = wn * 32 + (lane & 7) + ((lane >> 4) << 3);
    const int cB   = (lane >> 3) & 1;
    const int xrB  = (rowB >> 1) & 3;
    const uint32_t offB0 = (uint32_t)(rowB * 64 + (((cB)     ^ xrB) << 4));
    const uint32_t offB1 = (uint32_t)(rowB * 64 + (((cB + 2) ^ xrB) << 4));

    float acc[4][4][4];
#pragma unroll
    for (int i = 0; i < 4; ++i)
#pragma unroll
        for (int j = 0; j < 4; ++j)
#pragma unroll
            for (int l = 0; l < 4; ++l) acc[i][j][l] = 0.f;

    ISSUE(0); cp_commit();
    if (nSlab > 1) ISSUE(1);
    cp_commit();

    for (int it = 0; it < nSlab; ++it) {
        cp_wait1();
        __syncthreads();

        const uint32_t sb = smBase + (uint32_t)(it % 3) * stg;

#pragma unroll
        for (int sub = 0; sub < 2; ++sub) {
            const uint32_t aAdr = sb + (sub ? offA1 : offA0);
            const uint32_t bAdr = sb + 8192 + (sub ? offB1 : offB0);

            uint32_t bh[2][4], bl[2][4];
            ldsm4(bh[0], bAdr);
            ldsm4(bh[1], bAdr + 1024);          // +16 rows * 64B
            if (blo) {
                ldsm4(bl[0], bAdr + 8192);
                ldsm4(bl[1], bAdr + 8192 + 1024);
            }

#pragma unroll
            for (int mi = 0; mi < 4; ++mi) {
                uint32_t ah[4];
                ldsm4(ah, aAdr + mi * 1024);    // +16 rows * 64B
#pragma unroll
                for (int nt = 0; nt < 4; ++nt) {
                    const int np = nt >> 1, hf = (nt & 1) * 2;
                    mma_f32(acc[mi][nt], ah, bh[np][hf], bh[np][hf + 1]);
                    if (blo) mma_f32(acc[mi][nt], ah, bl[np][hf], bl[np][hf + 1]);
                }
            }
        }

        if (it + 2 < nSlab) ISSUE(it + 2);
        cp_commit();
    }
#undef ISSUE

    const int g = lane >> 2;
    const int c = lane & 3;
    if (p.outMode == 0) {
        float* C = (float*)p.C + zb * p.cSb + zh * p.cSh;
#pragma unroll
        for (int mi = 0; mi < 4; ++mi) {
            const int gm = m0 + wm * 64 + mi * 16 + g;
            if (gm >= p.M) continue;
            float* r0 = C + (long long)gm * p.ldc;
            float* r1 = r0 + 8 * p.ldc;
#pragma unroll
            for (int nt = 0; nt < 4; ++nt) {
                const int gn = n0 + wn * 32 + nt * 8 + 2 * c;
                if (gn < p.N) {
                    *(float2*)(r0 + gn) = make_float2(acc[mi][nt][0], acc[mi][nt][1]);
                    *(float2*)(r1 + gn) = make_float2(acc[mi][nt][2], acc[mi][nt][3]);
                }
            }
        }
    } else {
        hf16* Ch = (hf16*)p.C + zb * p.cSb + zh * p.cSh;
        hf16* Cl = Ch + p.cPS;
#pragma unroll
        for (int mi = 0; mi < 4; ++mi) {
            const int gm = m0 + wm * 64 + mi * 16 + g;
            if (gm >= p.M) continue;
            const long long ro0 = (long long)gm * p.ldc;
            const long long ro1 = ro0 + 8 * p.ldc;
#pragma unroll
            for (int nt = 0; nt < 4; ++nt) {
                const int gn = n0 + wn * 32 + nt * 8 + 2 * c;
                if (gn < p.N) {
                    hf16 h0, l0, h1, l1;
                    split2(acc[mi][nt][0], h0, l0);
                    split2(acc[mi][nt][1], h1, l1);
                    *(__half2*)(Ch + ro0 + gn) = __halves2half2(h0, h1);
                    *(__half2*)(Cl + ro0 + gn) = __halves2half2(l0, l1);
                    split2(acc[mi][nt][2], h0, l0);
                    split2(acc[mi][nt][3], h1, l1);
                    *(__half2*)(Ch + ro1 + gn) = __halves2half2(h0, h1);
                    *(__half2*)(Cl + ro1 + gn) = __halves2half2(l0, l1);
                }
            }
        }
    }
}

// --------------------------- flash attention --------------------------------
// TM=64 q-rows per CTA, 2 CTAs/SM. grid (32 q-blocks, 32 bh).
// Q and P are fp16 (hi only); K/V sides keep hi/lo planes.
// smem layout (bytes):
//   Qh 0..25600                      (64 rows x 400B, 192 cols used)
//   Ph 25600..43008                  (64 rows x 272B, 128 cols used)
//   stages 43008 + s*8192 (Bh 4KB, Bl 4KB), 3 stages -> 67584
//   RED 67584..68608 (float[4][64])
#define FL_SMEM 68608

__global__ __launch_bounds__(256, 2) void flash_k(
    const hf16* __restrict__ q, const hf16* __restrict__ kabs,
    const hf16* __restrict__ kext, const hf16* __restrict__ vT,
    hf16* __restrict__ ohead, float s2) {
    extern __shared__ __align__(16) char dyn[];
    const int tid = threadIdx.x, lane = tid & 31, warp = tid >> 5;
    const int wm = warp >> 2, wn = warp & 3, g = lane >> 2, c = lane & 3;
    const int iq = 31 - blockIdx.x;       // heavy blocks first
    const int bh = blockIdx.y, b = bh >> 4, h = bh & 15;
    const int m0 = iq * 64;
    const int nkv = (iq >> 1) + 1;
    const long long psKA = (long long)BSZ * NH * SEQ * D_NOPE;
    const long long psKV = (long long)MS * KVD;
    const long long psVT = (long long)BSZ * NH * D_V * SEQ;
    const long long psOH = (long long)MS * DMODEL;

    const uint32_t smb = (uint32_t)__cvta_generic_to_shared(dyn);
    const uint32_t smQ = smb;
    const uint32_t smP = smb + 25600;
    const uint32_t smS = smb + 43008;
    float* RED = (float*)(dyn + 67584);

    // ---- Q block load: 64 rows, hi plane only; 4 threads/row, 6 chunks each
    {
        const int r = tid >> 2, sub = tid & 3;
        const hf16* src = q + ((size_t)(b * SEQ + m0 + r)) * QDIM + h * D_QK + sub * 48;
        const uint32_t d0 = smQ + (uint32_t)(r * 400 + sub * 96);
#pragma unroll
        for (int ch = 0; ch < 6; ++ch) cp16(d0 + ch * 16, src + ch * 8, 16);
        cp_commit();
    }

    const int prow = tid >> 1, pcc = tid & 1;
    const uint32_t pOff = (uint32_t)(prow * 32 + ((pcc ^ ((prow >> 2) & 1)) << 4));
    const hf16* ka = kabs + (size_t)bh * SEQ * D_NOPE;
    const hf16* ke = kext + (size_t)b * SEQ * KVD;
    const hf16* vt = vT + (size_t)bh * D_V * SEQ;
    const int u_total = 20 * nkv;

    // slab u -> (kv block j = u/20, s = u%20):
    //   s<8: K-nope from kabs; s in 8..11: pe from kext; s>=12: V-slab
#define FL_ISSUE(U)                                                            \
    do {                                                                       \
        const int _j = (U) / 20, _s = (U) % 20;                                \
        uint32_t _sb = smS + (uint32_t)(((U) % 3) * 8192);                     \
        const hf16* _s0; long long _ps;                                        \
        if (_s < 8) {                                                          \
            _s0 = ka + ((size_t)(_j * 128 + prow)) * D_NOPE + _s * 16 + pcc * 8; \
            _ps = psKA;                                                        \
        } else if (_s < 12) {                                                  \
            _s0 = ke + ((size_t)(_j * 128 + prow)) * KVD + KVLR                \
                     + (_s - 8) * 16 + pcc * 8;                                \
            _ps = psKV;                                                        \
        } else {                                                               \
            _s0 = vt + (size_t)prow * SEQ + _j * 128 + (_s - 12) * 16 + pcc * 8; \
            _ps = psVT;                                                        \
        }                                                                      \
        cp16(_sb + pOff, _s0, 16);                                             \
        cp16(_sb + 4096 + pOff, _s0 + _ps, 16);                                \
    } while (0)

    FL_ISSUE(0); cp_commit();
    FL_ISSUE(1); cp_commit();

    // consumer fragment offsets
    const int rowA = wm * 32 + (lane & 7) + ((lane >> 3) & 1) * 8;
    const int cA   = lane >> 4;
    const uint32_t offAq = (uint32_t)(rowA * 400 + cA * 16);
    const uint32_t offAp = (uint32_t)(rowA * 272 + cA * 16);
    const int rowB = wn * 32 + (lane & 7) + ((lane >> 4) << 3);
    const int cB   = (lane >> 3) & 1;
    const uint32_t offB = (uint32_t)(rowB * 32 + ((cB ^ ((rowB >> 2) & 1)) << 4));

    float oacc[2][4][4];
    float m_r[2][2], l_r[2][2];
#pragma unroll
    for (int mi = 0; mi < 2; ++mi) {
#pragma unroll
        for (int nt = 0; nt < 4; ++nt)
#pragma unroll
            for (int k = 0; k < 4; ++k) oacc[mi][nt][k] = 0.f;
        m_r[mi][0] = m_r[mi][1] = -1e30f;
        l_r[mi][0] = l_r[mi][1] = 0.f;
    }

    int u = 0;
    for (int j = 0; j < nkv; ++j) {
        float sacc[2][4][4];
#pragma unroll
        for (int mi = 0; mi < 2; ++mi)
#pragma unroll
            for (int nt = 0; nt < 4; ++nt)
#pragma unroll
                for (int k = 0; k < 4; ++k) sacc[mi][nt][k] = 0.f;

        // ---- S phase: 12 K-slabs (K=192) ----
        for (int s = 0; s < 12; ++s) {
            cp_wait1(); __syncthreads();
            const uint32_t sb = smS + (uint32_t)((u % 3) * 8192);
            uint32_t bh4[2][4], bl4[2][4];
            ldsm4(bh4[0], sb + offB); ldsm4(bh4[1], sb + offB + 512);
            ldsm4(bl4[0], sb + 4096 + offB); ldsm4(bl4[1], sb + 4096 + offB + 512);
#pragma unroll
            for (int mi = 0; mi < 2; ++mi) {
                uint32_t ah[4];
                ldsm4(ah, smQ + offAq + mi * 6400 + s * 32);
#pragma unroll
                for (int nt = 0; nt < 4; ++nt) {
                    const int np = nt >> 1, hf2 = (nt & 1) * 2;
                    mma_f32(sacc[mi][nt], ah, bh4[np][hf2], bh4[np][hf2 + 1]);
                    mma_f32(sacc[mi][nt], ah, bl4[np][hf2], bl4[np][hf2 + 1]);
                }
            }
            if (u + 2 < u_total) FL_ISSUE(u + 2);
            cp_commit(); ++u;
        }

        // ---- causal mask on last kv block ----
        if (j == nkv - 1) {
#pragma unroll
            for (int mi = 0; mi < 2; ++mi)
#pragma unroll
                for (int nt = 0; nt < 4; ++nt)
#pragma unroll
                    for (int k = 0; k < 4; ++k) {
                        const int rl = m0 + wm * 32 + mi * 16 + g + (k >> 1) * 8;
                        const int cl = j * 128 + wn * 32 + nt * 8 + 2 * c + (k & 1);
                        if (cl > rl) sacc[mi][nt][k] = -1e30f;
                    }
        }

        // ---- online softmax ----
        float alpha[2][2];
#pragma unroll
        for (int mi = 0; mi < 2; ++mi)
#pragma unroll
            for (int h2 = 0; h2 < 2; ++h2) {
                float v = fmaxf(fmaxf(sacc[mi][0][h2 * 2], sacc[mi][0][h2 * 2 + 1]),
                                fmaxf(sacc[mi][1][h2 * 2], sacc[mi][1][h2 * 2 + 1]));
                v = fmaxf(v, fmaxf(fmaxf(sacc[mi][2][h2 * 2], sacc[mi][2][h2 * 2 + 1]),
                                   fmaxf(sacc[mi][3][h2 * 2], sacc[mi][3][h2 * 2 + 1])));
                v = fmaxf(v, __shfl_xor_sync(0xffffffffu, v, 1));
                v = fmaxf(v, __shfl_xor_sync(0xffffffffu, v, 2));
                if (c == 0) RED[wn * 64 + wm * 32 + mi * 16 + g + h2 * 8] = v;
            }
        __syncthreads();
#pragma unroll
        for (int mi = 0; mi < 2; ++mi)
#pragma unroll
            for (int h2 = 0; h2 < 2; ++h2) {
                const int row = wm * 32 + mi * 16 + g + h2 * 8;
                float mrow = fmaxf(fmaxf(RED[row], RED[64 + row]),
                                   fmaxf(RED[128 + row], RED[192 + row]));
                float mnew = fmaxf(m_r[mi][h2], mrow);
                alpha[mi][h2] = exp2f((m_r[mi][h2] - mnew) * s2);
                m_r[mi][h2] = mnew;
            }
        __syncthreads();   // RED reads done before sum-round rewrite
#pragma unroll
        for (int mi = 0; mi < 2; ++mi)
#pragma unroll
            for (int h2 = 0; h2 < 2; ++h2) {
                const float mn = m_r[mi][h2];
                const float a = alpha[mi][h2];
                float sum = 0.f;
#pragma unroll
                for (int nt = 0; nt < 4; ++nt) {
                    float p0 = exp2f((sacc[mi][nt][h2 * 2] - mn) * s2);
                    float p1 = exp2f((sacc[mi][nt][h2 * 2 + 1] - mn) * s2);
                    sacc[mi][nt][h2 * 2] = p0;
                    sacc[mi][nt][h2 * 2 + 1] = p1;
                    oacc[mi][nt][h2 * 2] *= a;
                    oacc[mi][nt][h2 * 2 + 1] *= a;
                    sum += p0 + p1;
                }
                sum += __shfl_xor_sync(0xffffffffu, sum, 1);
                sum += __shfl_xor_sync(0xffffffffu, sum, 2);
                if (c == 0) RED[wn * 64 + wm * 32 + mi * 16 + g + h2 * 8] = sum;
            }
        // write P (hi plane only) to smem
#pragma unroll
        for (int mi = 0; mi < 2; ++mi)
#pragma unroll
            for (int nt = 0; nt < 4; ++nt) {
                const int r0 = wm * 32 + mi * 16 + g;
                const int cb = wn * 32 + nt * 8 + 2 * c;
                *(__half2*)(dyn + 25600 + r0 * 272 + cb * 2) =
                    __halves2half2(__float2half_rn(sacc[mi][nt][0]),
                                   __float2half_rn(sacc[mi][nt][1]));
                *(__half2*)(dyn + 25600 + (r0 + 8) * 272 + cb * 2) =
                    __halves2half2(__float2half_rn(sacc[mi][nt][2]),
                                   __float2half_rn(sacc[mi][nt][3]));
            }
        __syncthreads();   // P + sums visible
#pragma unroll
        for (int mi = 0; mi < 2; ++mi)
#pragma unroll
            for (int h2 = 0; h2 < 2; ++h2) {
                const int row = wm * 32 + mi * 16 + g + h2 * 8;
                const float ls = RED[row] + RED[64 + row] + RED[128 + row] + RED[192 + row];
                l_r[mi][h2] = l_r[mi][h2] * alpha[mi][h2] + ls;
            }

        // ---- PV phase: 8 V-slabs (K=128 over t) ----
        for (int s = 0; s < 8; ++s) {
            cp_wait1(); __syncthreads();
            const uint32_t sb = smS + (uint32_t)((u % 3) * 8192);
            uint32_t vh4[2][4], vl4[2][4];
            ldsm4(vh4[0], sb + offB); ldsm4(vh4[1], sb + offB + 512);
            ldsm4(vl4[0], sb + 4096 + offB); ldsm4(vl4[1], sb + 4096 + offB + 512);
#pragma unroll
            for (int mi = 0; mi < 2; ++mi) {
                uint32_t ph[4];
                ldsm4(ph, smP + offAp + mi * 4352 + s * 32);
#pragma unroll
                for (int nt = 0; nt < 4; ++nt) {
                    const int np = nt >> 1, hf2 = (nt & 1) * 2;
                    mma_f32(oacc[mi][nt], ph, vh4[np][hf2], vh4[np][hf2 + 1]);
                    mma_f32(oacc[mi][nt], ph, vl4[np][hf2], vl4[np][hf2 + 1]);
                }
            }
            if (u + 2 < u_total) FL_ISSUE(u + 2);
            cp_commit(); ++u;
        }
    }
#undef FL_ISSUE

    // ---- epilogue: O / l -> ohead planes ----
    hf16* Cb = ohead + (size_t)(b * SEQ + m0) * DMODEL + h * D_V;
#pragma unroll
    for (int mi = 0; mi < 2; ++mi) {
        const int r0 = wm * 32 + mi * 16 + g;
        const float i0 = 1.f / l_r[mi][0], i1 = 1.f / l_r[mi][1];
#pragma unroll
        for (int nt = 0; nt < 4; ++nt) {
            const int cb = wn * 32 + nt * 8 + 2 * c;
            hf16 h0, l0, h1, l1;
            split2(oacc[mi][nt][0] * i0, h0, l0);
            split2(oacc[mi][nt][1] * i0, h1, l1);
            hf16* p = Cb + (size_t)r0 * DMODEL + cb;
            *(__half2*)p = __halves2half2(h0, h1);
            *(__half2*)(p + psOH) = __halves2half2(l0, l1);
            split2(oacc[mi][nt][2] * i1, h0, l0);
            split2(oacc[mi][nt][3] * i1, h1, l1);
            p = Cb + (size_t)(r0 + 8) * DMODEL + cb;
            *(__half2*)p = __halves2half2(h0, h1);
            *(__half2*)(p + psOH) = __halves2half2(l0, l1);
        }
    }
}

// ---------------------------- block reduction ------------------------------
__device__ __forceinline__ float blockReduce(float v, bool isMax) {
    __shared__ float sh[32];
    const int lane = threadIdx.x & 31, wid = threadIdx.x >> 5;
    __syncthreads();
#pragma unroll
    for (int o = 16; o > 0; o >>= 1) {
        float t = __shfl_down_sync(0xffffffffu, v, o);
        v = isMax ? fmaxf(v, t) : (v + t);
    }
    if (lane == 0) sh[wid] = v;
    __syncthreads();
    const int nw = blockDim.x >> 5;
    if (wid == 0) {
        v = (lane < nw) ? sh[lane] : (isMax ? -1e30f : 0.f);
#pragma unroll
        for (int o = 16; o > 0; o >>= 1) {
            float t = __shfl_down_sync(0xffffffffu, v, o);
            v = isMax ? fmaxf(v, t) : (v + t);
        }
        if (lane == 0) sh[0] = v;
    }
    __syncthreads();
    return sh[0];
}

// ------------------------------ aux kernels --------------------------------
__global__ void pack2_k(const float* __restrict__ in, hf16* __restrict__ out,
                        long long ps, int n) {
    for (int i = blockIdx.x * blockDim.x + threadIdx.x; i < n; i += gridDim.x * blockDim.x) {
        hf16 h, l; split2(in[i], h, l);
        out[i] = h; out[i + ps] = l;
    }
}

// fp32 [R][C] -> planes [C][R]
__global__ void packT2_k(const float* __restrict__ in, hf16* __restrict__ out,
                         long long ps, int R, int C) {
    __shared__ float t[32][33];
    const int c0 = blockIdx.x * 32, r0 = blockIdx.y * 32;
#pragma unroll
    for (int i = threadIdx.y; i < 32; i += 8)
        t[i][threadIdx.x] = in[(long long)(r0 + i) * C + c0 + threadIdx.x];
    __syncthreads();
#pragma unroll
    for (int i = threadIdx.y; i < 32; i += 8) {
        hf16 h, l; split2(t[threadIdx.x][i], h, l);
        long long o = (long long)(c0 + i) * R + r0 + threadIdx.x;
        out[o] = h; out[o + ps] = l;
    }
}

__global__ void rmsnorm_rows_k(hf16* x, long long ps, const float* __restrict__ w, int n) {
    long long base = (long long)blockIdx.x * n;
    float ss = 0.f;
    for (int i = threadIdx.x; i < n; i += blockDim.x) {
        float v = join2(x[base + i], x[base + i + ps]); ss += v * v;
    }
    ss = blockReduce(ss, false);
    float rn = rsqrtf(ss / (float)n + EPSF);
    for (int i = threadIdx.x; i < n; i += blockDim.x) {
        float v = join2(x[base + i], x[base + i + ps]) * rn * w[i];
        hf16 h, l; split2(v, h, l);
        x[base + i] = h; x[base + i + ps] = l;
    }
}

__global__ void kv_process_k(const hf16* __restrict__ kv, hf16* __restrict__ kext,
                             const float* __restrict__ w, const float* __restrict__ freqs) {
    const long long psKV = (long long)MS * KVD;
    const int m = blockIdx.x;
    const int s = m & (SEQ - 1);
    const hf16* kr = kv   + (long long)m * KVD;
    hf16*       ke = kext + (long long)m * KVD;
    float ss = 0.f;
    for (int i = threadIdx.x; i < KVLR; i += blockDim.x) {
        float v = join2(kr[i], kr[i + psKV]); ss += v * v;
    }
    ss = blockReduce(ss, false);
    float rn = rsqrtf(ss / (float)KVLR + EPSF);
    for (int i = threadIdx.x; i < KVLR; i += blockDim.x) {
        float v = join2(kr[i], kr[i + psKV]) * rn * w[i];
        hf16 h, l; split2(v, h, l);
        ke[i] = h; ke[i + psKV] = l;
    }
    if (threadIdx.x < 32) {
        const int i = threadIdx.x;
        float th = freqs[s * 32 + i];
        float co, sn; sincosf(th, &sn, &co);
        float x0 = join2(kr[KVLR + 2 * i], kr[KVLR + 2 * i + psKV]);
        float x1 = join2(kr[KVLR + 2 * i + 1], kr[KVLR + 2 * i + 1 + psKV]);
        hf16 h, l;
        split2(x0 * co - x1 * sn, h, l);
        ke[KVLR + 2 * i] = h; ke[KVLR + 2 * i + psKV] = l;
        split2(x0 * sn + x1 * co, h, l);
        ke[KVLR + 2 * i + 1] = h; ke[KVLR + 2 * i + 1 + psKV] = l;
    }
}

// rope q_pe in place inside g_q planes ([m][h*192+128 .. +191])
__global__ void rope_q_k(hf16* q, const float* __restrict__ freqs) {
    const long long psQ = (long long)MS * QDIM;
    const int m = blockIdx.x;
    const int s = m & (SEQ - 1);
    const int h = threadIdx.x >> 5;
    const int i = threadIdx.x & 31;
    float th = freqs[s * 32 + i];
    float co, sn; sincosf(th, &sn, &co);
    hf16* qr = q + (long long)m * QDIM + h * D_QK + D_NOPE;
    float x0 = join2(qr[2 * i], qr[2 * i + psQ]);
    float x1 = join2(qr[2 * i + 1], qr[2 * i + 1 + psQ]);
    hf16 hh, ll;
    split2(x0 * co - x1 * sn, hh, ll);
    qr[2 * i] = hh; qr[2 * i + psQ] = ll;
    split2(x0 * sn + x1 * co, hh, ll);
    qr[2 * i + 1] = hh; qr[2 * i + 1 + psQ] = ll;
}

// ------------------------------- host side ---------------------------------
static void launchGemm(const hf16* A, const hf16* B, long long bPS,
                       void* C, long long cPS,
                       int M, int N, int K,
                       long long lda, long long ldb, long long ldc,
                       int nb, int nInner,
                       long long aSb, long long aSh,
                       long long bSb, long long bSh,
                       long long cSb, long long cSh,
                       int causal, int outMode, int bLo) {
    GemmP p;
    p.A = A; p.B = B; p.C = C;
    p.bPS = bPS; p.cPS = cPS;
    p.M = M; p.N = N; p.K = K;
    p.lda = lda; p.ldb = ldb; p.ldc = ldc;
    p.aSb = aSb; p.aSh = aSh; p.bSb = bSb; p.bSh = bSh; p.cSb = cSb; p.cSh = cSh;
    p.nInner = nInner; p.causal = causal; p.outMode = outMode; p.bLo = bLo;
    dim3 grid((N + 127) / 128, (M + 127) / 128, nb);
    const int dynBytes = bLo ? 73728 : 49152;
    gemm_hmma<<<grid, 256, dynBytes>>>(p);
}

extern "C" void kernel_launch(void* const* d_in, const int* in_sizes, int n_in,
                              void* d_out, int out_size) {
    const float* x         = (const float*)d_in[0];
    const float* freqs     = (const float*)d_in[1];
    const float* wq_a      = (const float*)d_in[3];
    const float* q_norm_w  = (const float*)d_in[4];
    const float* wq_b      = (const float*)d_in[5];
    const float* wkv_a     = (const float*)d_in[6];
    const float* kv_norm_w = (const float*)d_in[7];
    const float* wkv_b     = (const float*)d_in[8];
    const float* wo        = (const float*)d_in[9];
    float* out = (float*)d_out;

    cudaFuncSetAttribute(flash_k, cudaFuncAttributeMaxDynamicSharedMemorySize, FL_SMEM);
    cudaFuncSetAttribute(gemm_hmma, cudaFuncAttributeMaxDynamicSharedMemorySize, GEMM_DYN_MAX);

    hf16 *xp, *wqaT, *wkvaT, *wqbT, *wkvbT, *woT;
    hf16 *qa, *q, *kv, *kext, *kabs, *vT, *ohead;
    cudaGetSymbolAddress((void**)&xp,     g_xp);
    cudaGetSymbolAddress((void**)&wqaT,   g_wqaT);
    cudaGetSymbolAddress((void**)&wkvaT,  g_wkvaT);
    cudaGetSymbolAddress((void**)&wqbT,   g_wqbT);
    cudaGetSymbolAddress((void**)&wkvbT,  g_wkvbT);
    cudaGetSymbolAddress((void**)&woT,    g_woT);
    cudaGetSymbolAddress((void**)&qa,     g_qa);
    cudaGetSymbolAddress((void**)&q,      g_q);
    cudaGetSymbolAddress((void**)&kv,     g_kv);
    cudaGetSymbolAddress((void**)&kext,   g_kext);
    cudaGetSymbolAddress((void**)&kabs,   g_kabs);
    cudaGetSymbolAddress((void**)&vT,     g_vT);
    cudaGetSymbolAddress((void**)&ohead,  g_ohead);

    const float scale = 1.0f / sqrtf((float)D_QK);
    const float s2 = scale * 1.4426950408889634f;   // scale * log2(e)

    // plane strides
    const long long psX   = (long long)MS * DMODEL;
    const long long psWQA = (long long)QLR * DMODEL;
    const long long psWKA = (long long)KVD * DMODEL;
    const long long psWQB = (long long)QDIM * QLR;
    const long long psWBT = (long long)NH * HDIM * KVLR;
    const long long psWO  = (long long)DMODEL * DMODEL;
    const long long psQA  = (long long)MS * QLR;
    const long long psQ   = (long long)MS * QDIM;
    const long long psKV  = (long long)MS * KVD;
    const long long psKA  = (long long)BSZ * NH * SEQ * D_NOPE;
    const long long psVT  = (long long)BSZ * NH * D_V * SEQ;
    const long long psOH  = (long long)MS * DMODEL;

    // ---- pack inputs into planes ----
    pack2_k<<<512, 256>>>(x, xp, psX, MS * DMODEL);
    packT2_k<<<dim3(QLR / 32, DMODEL / 32), dim3(32, 8)>>>(wq_a, wqaT, psWQA, DMODEL, QLR);
    packT2_k<<<dim3(KVD / 32, DMODEL / 32), dim3(32, 8)>>>(wkv_a, wkvaT, psWKA, DMODEL, KVD);
    packT2_k<<<dim3(QDIM / 32, QLR / 32), dim3(32, 8)>>>(wq_b, wqbT, psWQB, QLR, QDIM);
    packT2_k<<<dim3((NH * HDIM) / 32, KVLR / 32), dim3(32, 8)>>>(wkv_b, wkvbT, psWBT, KVLR, NH * HDIM);
    packT2_k<<<dim3(DMODEL / 32, DMODEL / 32), dim3(32, 8)>>>(wo, woT, psWO, DMODEL, DMODEL);

    // 1. qa = x @ wq_a   (B hi only)
    launchGemm(xp, wqaT, psWQA, qa, psQA, MS, QLR, DMODEL,
               DMODEL, DMODEL, QLR, 1, 1, 0, 0, 0, 0, 0, 0, 0, 1, 0);
    // 2. kv = x @ wkv_a (N=576, B planes)
    launchGemm(xp, wkvaT, psWKA, kv, psKV, MS, KVD, DMODEL,
               DMODEL, DMODEL, KVD, 1, 1, 0, 0, 0, 0, 0, 0, 0, 1, 1);
    // 3. rmsnorm(qa)
    rmsnorm_rows_k<<<MS, 256>>>(qa, psQA, q_norm_w, QLR);
    // 4. kext = [rmsnorm(latent), rope(k_pe)]
    kv_process_k<<<MS, 256>>>(kv, kext, kv_norm_w, freqs);
    // 5. q = qa @ wq_b (B hi only)
    launchGemm(qa, wqbT, psWQB, q, psQ, MS, QDIM, QLR,
               QLR, QLR, QDIM, 1, 1, 0, 0, 0, 0, 0, 0, 0, 1, 0);
    // 6. rope q_pe in place
    rope_q_k<<<MS, NH * 32>>>(q, freqs);
    // 7. k_abs[b,h,s,0:128] = kv_cache @ Wuk[h]^T (B planes)
    launchGemm(kext, wkvbT, psWBT, kabs, psKA,
               SEQ, D_NOPE, KVLR,
               KVD, KVLR, D_NOPE,
               BSZ * NH, NH,
               (long long)SEQ * KVD, 0,
               0, (long long)HDIM * KVLR,
               (long long)NH * SEQ * D_NOPE, (long long)SEQ * D_NOPE,
               0, 1, 1);
    // 8. vT[b,h,d,t] = Wuv[h] @ kv_cache^T (B = kext planes)
    launchGemm(wkvbT + (long long)D_NOPE * KVLR, kext, psKV, vT, psVT,
               D_V, SEQ, KVLR,
               KVLR, KVD, SEQ,
               BSZ * NH, NH,
               0, (long long)HDIM * KVLR,
               (long long)SEQ * KVD, 0,
               (long long)NH * D_V * SEQ, (long long)D_V * SEQ,
               0, 1, 1);
    // 9. fused flash attention -> ohead planes
    flash_k<<<dim3(32, BSZ * NH), 256, FL_SMEM>>>(q, kabs, kext, vT, ohead, s2);
    // 10. out = ohead @ wo (fp32 out, B hi only)
    launchGemm(ohead, woT, psWO, out, 0, MS, DMODEL, DMODEL,
               DMODEL, DMODEL, DMODEL, 1, 1, 0, 0, 0, 0, 0, 0, 0, 0, 0);
}

// round 15
// speedup vs baseline: 1.8071x; 1.1564x over previous
#include <cuda_runtime.h>
#include <cuda_fp16.h>
#include <math.h>
#include <stdint.h>

// ---------------------------------------------------------------------------
// MLA forward, per-head expanded attention + fused flash attention.
// GEMMs: fp16x2 emulated fp32: D = Ah*(Bh + Bl), f32 accumulate, K-slab 32.
// B lo plane kept for kv, kabs, vT GEMMs; qa, q, wo and the ENTIRE flash
// kernel use plain fp16 operands (flash: 1 MMA per k16, k32 slabs).
// ---------------------------------------------------------------------------

#define BSZ    2
#define SEQ    2048
#define DMODEL 2048
#define NH     16
#define QLR    1536
#define KVLR   512
#define D_NOPE 128
#define D_ROPE 64
#define D_QK   192
#define D_V    128
#define MS     (BSZ*SEQ)          /* 4096 */
#define QDIM   (NH*D_QK)          /* 3072 */
#define KVD    (KVLR + D_ROPE)    /* 576  */
#define HDIM   (D_NOPE + D_V)     /* 256  */
#define EPSF   1e-6f

typedef __half hf16;

// ---------------- scratch: every tensor is [2][elems] fp16 planes ----------
__device__ hf16 g_xp   [2 * (size_t)MS * DMODEL];
__device__ hf16 g_wqaT [2 * (size_t)QLR * DMODEL];
__device__ hf16 g_wkvaT[2 * (size_t)KVD * DMODEL];
__device__ hf16 g_wqbT [2 * (size_t)QDIM * QLR];
__device__ hf16 g_wkvbT[2 * (size_t)NH * HDIM * KVLR];
__device__ hf16 g_woT  [2 * (size_t)DMODEL * DMODEL];
__device__ hf16 g_qa   [2 * (size_t)MS * QLR];
__device__ hf16 g_q    [2 * (size_t)MS * QDIM];
__device__ hf16 g_kv   [2 * (size_t)MS * KVD];
__device__ hf16 g_kext [2 * (size_t)MS * KVD];
__device__ hf16 g_kabs [2 * (size_t)BSZ * NH * SEQ * D_NOPE];
__device__ hf16 g_vT   [2 * (size_t)BSZ * NH * D_V * SEQ];
__device__ hf16 g_ohead[2 * (size_t)MS * DMODEL];

// ------------------------------ helpers -------------------------------------
__device__ __forceinline__ void split2(float x, hf16& h, hf16& l) {
    h = __float2half_rn(x);
    l = __float2half_rn(x - __half2float(h));
}
__device__ __forceinline__ float join2(hf16 h, hf16 l) {
    return __half2float(h) + __half2float(l);
}
__device__ __forceinline__ void cp16(uint32_t smem, const void* g, int srcBytes) {
    asm volatile("cp.async.cg.shared.global [%0], [%1], 16, %2;"
                 :: "r"(smem), "l"(g), "r"(srcBytes));
}
__device__ __forceinline__ void cp_commit() { asm volatile("cp.async.commit_group;"); }
__device__ __forceinline__ void cp_wait1()  { asm volatile("cp.async.wait_group 1;"); }

__device__ __forceinline__ void ldsm4(uint32_t* r, uint32_t addr) {
    asm volatile("ldmatrix.sync.aligned.m8n8.x4.shared.b16 {%0,%1,%2,%3}, [%4];"
                 : "=r"(r[0]), "=r"(r[1]), "=r"(r[2]), "=r"(r[3]) : "r"(addr));
}
__device__ __forceinline__ void mma_f32(float* d, const uint32_t* a,
                                        uint32_t b0, uint32_t b1) {
    asm volatile(
        "mma.sync.aligned.m16n8k16.row.col.f32.f16.f16.f32 "
        "{%0,%1,%2,%3}, {%4,%5,%6,%7}, {%8,%9}, {%0,%1,%2,%3};"
        : "+f"(d[0]), "+f"(d[1]), "+f"(d[2]), "+f"(d[3])
        : "r"(a[0]), "r"(a[1]), "r"(a[2]), "r"(a[3]), "r"(b0), "r"(b1));
}

// ----------------------------- GEMM kernel ----------------------------------
// C = A * B^T. A: [M][K] fp16 (hi plane only), row stride lda.
// B: [N][K] planes (hi at B, lo at B+bPS), row stride ldb; bLo=0 -> hi only.
// CTA tile 128x128, K-slab 32 (two k16 sub-steps/stage), 8 warps, 64x32 warp
// tile. Dyn smem: 3 stages x (A 8KB + Bh 8KB [+ Bl 8KB]). 64B rows with
// 2-bit XOR swizzle: physical chunk = logical ^ ((row>>1)&3).
// outMode 0: fp32 C. outMode 1: fp16 planes C (lo at +cPS).
struct GemmP {
    const hf16 *A, *B; void* C;
    long long bPS, cPS;
    int M, N, K;
    long long lda, ldb, ldc;
    long long aSb, aSh, bSb, bSh, cSb, cSh;
    int nInner, causal, outMode, bLo;
};

#define GEMM_DYN_MAX 73728

__global__ __launch_bounds__(256, 2) void gemm_hmma(GemmP p) {
    extern __shared__ __align__(16) unsigned char dynsm[];

    const int m0 = blockIdx.y * 128;
    const int n0 = blockIdx.x * 128;
    if (p.causal == 1 && n0 >= m0 + 128) return;

    const int z  = blockIdx.z;
    const int zb = z / p.nInner;
    const int zh = z - zb * p.nInner;
    const hf16* A = p.A + zb * p.aSb + zh * p.aSh;
    const hf16* B = p.B + zb * p.bSb + zh * p.bSh;

    int kEnd = p.K;
    if (p.causal == 2) { int km = m0 + 128; if (km < kEnd) kEnd = km; }
    const int nSlab = kEnd >> 5;
    const bool blo = (p.bLo != 0);
    const uint32_t stg = blo ? 24576u : 16384u;

    const int tid  = threadIdx.x;
    const int lane = tid & 31;
    const int warp = tid >> 5;
    const int wm   = warp >> 2;    // 0..1
    const int wn   = warp & 3;     // 0..3

    const uint32_t smBase = (uint32_t)__cvta_generic_to_shared(dynsm);

    // producer: row r (128), logical chunks cc and cc+2 (4 x 16B per 64B row)
    const int r  = tid >> 1;
    const int cc = tid & 1;
    const int xr = (r >> 1) & 3;
    const uint32_t po0 = (uint32_t)(r * 64 + (((cc)     ^ xr) << 4));
    const uint32_t po1 = (uint32_t)(r * 64 + (((cc + 2) ^ xr) << 4));

    int mr = m0 + r;
    const bool aok = mr < p.M;
    if (!aok) mr = m0;
    const hf16* gA0 = A + (size_t)mr * p.lda + cc * 8;
    const int asz = aok ? 16 : 0;
    int nr = n0 + r;
    const bool bok = nr < p.N;
    if (!bok) nr = n0;
    const hf16* gB0 = B + (size_t)nr * p.ldb + cc * 8;
    const hf16* gB1 = gB0 + p.bPS;
    const int bsz = bok ? 16 : 0;

#define ISSUE(S)                                                               \
    do {                                                                       \
        uint32_t sb = smBase + (uint32_t)((S) % 3) * stg;                      \
        const size_t ko = (size_t)(S) * 32;                                    \
        cp16(sb + po0,        gA0 + ko,      asz);                             \
        cp16(sb + po1,        gA0 + ko + 16, asz);                             \
        cp16(sb + 8192 + po0, gB0 + ko,      bsz);                             \
        cp16(sb + 8192 + po1, gB0 + ko + 16, bsz);                             \
        if (blo) {                                                             \
            cp16(sb + 16384 + po0, gB1 + ko,      bsz);                        \
            cp16(sb + 16384 + po1, gB1 + ko + 16, bsz);                        \
        }                                                                      \
    } while (0)

    // consumer fragment offsets (per k16 sub-step)
    const int rowA = wm * 64 + (lane & 15);
    const int cA   = lane >> 4;
    const int xrA  = (rowA >> 1) & 3;
    const uint32_t offA0 = (uint32_t)(rowA * 64 + (((cA)     ^ xrA) << 4));
    const uint32_t offA1 = (uint32_t)(rowA * 64 + (((cA + 2) ^ xrA) << 4));
    const int rowB = wn * 32 + (lane & 7) + ((lane >> 4) << 3);
    const int cB   = (lane >> 3) & 1;
    const int xrB  = (rowB >> 1) & 3;
    const uint32_t offB0 = (uint32_t)(rowB * 64 + (((cB)     ^ xrB) << 4));
    const uint32_t offB1 = (uint32_t)(rowB * 64 + (((cB + 2) ^ xrB) << 4));

    float acc[4][4][4];
#pragma unroll
    for (int i = 0; i < 4; ++i)
#pragma unroll
        for (int j = 0; j < 4; ++j)
#pragma unroll
            for (int l = 0; l < 4; ++l) acc[i][j][l] = 0.f;

    ISSUE(0); cp_commit();
    if (nSlab > 1) ISSUE(1);
    cp_commit();

    for (int it = 0; it < nSlab; ++it) {
        cp_wait1();
        __syncthreads();

        const uint32_t sb = smBase + (uint32_t)(it % 3) * stg;

#pragma unroll
        for (int sub = 0; sub < 2; ++sub) {
            const uint32_t aAdr = sb + (sub ? offA1 : offA0);
            const uint32_t bAdr = sb + 8192 + (sub ? offB1 : offB0);

            uint32_t bh[2][4], bl[2][4];
            ldsm4(bh[0], bAdr);
            ldsm4(bh[1], bAdr + 1024);          // +16 rows * 64B
            if (blo) {
                ldsm4(bl[0], bAdr + 8192);
                ldsm4(bl[1], bAdr + 8192 + 1024);
            }

#pragma unroll
            for (int mi = 0; mi < 4; ++mi) {
                uint32_t ah[4];
                ldsm4(ah, aAdr + mi * 1024);    // +16 rows * 64B
#pragma unroll
                for (int nt = 0; nt < 4; ++nt) {
                    const int np = nt >> 1, hf = (nt & 1) * 2;
                    mma_f32(acc[mi][nt], ah, bh[np][hf], bh[np][hf + 1]);
                    if (blo) mma_f32(acc[mi][nt], ah, bl[np][hf], bl[np][hf + 1]);
                }
            }
        }

        if (it + 2 < nSlab) ISSUE(it + 2);
        cp_commit();
    }
#undef ISSUE

    const int g = lane >> 2;
    const int c = lane & 3;
    if (p.outMode == 0) {
        float* C = (float*)p.C + zb * p.cSb + zh * p.cSh;
#pragma unroll
        for (int mi = 0; mi < 4; ++mi) {
            const int gm = m0 + wm * 64 + mi * 16 + g;
            if (gm >= p.M) continue;
            float* r0 = C + (long long)gm * p.ldc;
            float* r1 = r0 + 8 * p.ldc;
#pragma unroll
            for (int nt = 0; nt < 4; ++nt) {
                const int gn = n0 + wn * 32 + nt * 8 + 2 * c;
                if (gn < p.N) {
                    *(float2*)(r0 + gn) = make_float2(acc[mi][nt][0], acc[mi][nt][1]);
                    *(float2*)(r1 + gn) = make_float2(acc[mi][nt][2], acc[mi][nt][3]);
                }
            }
        }
    } else {
        hf16* Ch = (hf16*)p.C + zb * p.cSb + zh * p.cSh;
        hf16* Cl = Ch + p.cPS;
#pragma unroll
        for (int mi = 0; mi < 4; ++mi) {
            const int gm = m0 + wm * 64 + mi * 16 + g;
            if (gm >= p.M) continue;
            const long long ro0 = (long long)gm * p.ldc;
            const long long ro1 = ro0 + 8 * p.ldc;
#pragma unroll
            for (int nt = 0; nt < 4; ++nt) {
                const int gn = n0 + wn * 32 + nt * 8 + 2 * c;
                if (gn < p.N) {
                    hf16 h0, l0, h1, l1;
                    split2(acc[mi][nt][0], h0, l0);
                    split2(acc[mi][nt][1], h1, l1);
                    *(__half2*)(Ch + ro0 + gn) = __halves2half2(h0, h1);
                    *(__half2*)(Cl + ro0 + gn) = __halves2half2(l0, l1);
                    split2(acc[mi][nt][2], h0, l0);
                    split2(acc[mi][nt][3], h1, l1);
                    *(__half2*)(Ch + ro1 + gn) = __halves2half2(h0, h1);
                    *(__half2*)(Cl + ro1 + gn) = __halves2half2(l0, l1);
                }
            }
        }
    }
}

// --------------------------- flash attention --------------------------------
// TM=64 q-rows per CTA, 2 CTAs/SM. grid (32 q-blocks, 32 bh).
// ALL operands fp16 (hi planes only). K-slab 32 (two k16 sub-steps).
// smem layout (bytes):
//   Qh 0..25600                      (64 rows x 400B, 192 cols used)
//   Ph 25600..43008                  (64 rows x 272B, 128 cols used)
//   stages 43008 + s*8192 (128 rows x 64B, XOR swizzle), 3 stages -> 67584
//   RED 67584..68608 (float[4][64])
#define FL_SMEM 68608

__global__ __launch_bounds__(256, 2) void flash_k(
    const hf16* __restrict__ q, const hf16* __restrict__ kabs,
    const hf16* __restrict__ kext, const hf16* __restrict__ vT,
    hf16* __restrict__ ohead, float s2) {
    extern __shared__ __align__(16) char dyn[];
    const int tid = threadIdx.x, lane = tid & 31, warp = tid >> 5;
    const int wm = warp >> 2, wn = warp & 3, g = lane >> 2, c = lane & 3;
    const int iq = 31 - blockIdx.x;       // heavy blocks first
    const int bh = blockIdx.y, b = bh >> 4, h = bh & 15;
    const int m0 = iq * 64;
    const int nkv = (iq >> 1) + 1;
    const long long psOH = (long long)MS * DMODEL;

    const uint32_t smb = (uint32_t)__cvta_generic_to_shared(dyn);
    const uint32_t smQ = smb;
    const uint32_t smP = smb + 25600;
    const uint32_t smS = smb + 43008;
    float* RED = (float*)(dyn + 67584);

    // ---- Q block load: 64 rows, hi plane only; 4 threads/row, 6 chunks each
    {
        const int r = tid >> 2, sub = tid & 3;
        const hf16* src = q + ((size_t)(b * SEQ + m0 + r)) * QDIM + h * D_QK + sub * 48;
        const uint32_t d0 = smQ + (uint32_t)(r * 400 + sub * 96);
#pragma unroll
        for (int ch = 0; ch < 6; ++ch) cp16(d0 + ch * 16, src + ch * 8, 16);
        cp_commit();
    }

    // producer: row prow (128), logical chunks pcc and pcc+2, 64B rows
    const int prow = tid >> 1, pcc = tid & 1;
    const int pxr = (prow >> 1) & 3;
    const uint32_t po0 = (uint32_t)(prow * 64 + (((pcc)     ^ pxr) << 4));
    const uint32_t po1 = (uint32_t)(prow * 64 + (((pcc + 2) ^ pxr) << 4));
    const hf16* ka = kabs + (size_t)bh * SEQ * D_NOPE;
    const hf16* ke = kext + (size_t)b * SEQ * KVD;
    const hf16* vt = vT + (size_t)bh * D_V * SEQ;
    const int u_total = 10 * nkv;

    // slab u -> (kv block j = u/10, s = u%10), each slab = 32 k-cols:
    //   s<4: K-nope from kabs; s in 4..5: pe from kext; s>=6: V-slab
#define FL_ISSUE(U)                                                            \
    do {                                                                       \
        const int _j = (U) / 10, _s = (U) % 10;                                \
        uint32_t _sb = smS + (uint32_t)(((U) % 3) * 8192);                     \
        const hf16* _s0;                                                       \
        if (_s < 4) {                                                          \
            _s0 = ka + ((size_t)(_j * 128 + prow)) * D_NOPE + _s * 32 + pcc * 8; \
        } else if (_s < 6) {                                                   \
            _s0 = ke + ((size_t)(_j * 128 + prow)) * KVD + KVLR                \
                     + (_s - 4) * 32 + pcc * 8;                                \
        } else {                                                               \
            _s0 = vt + (size_t)prow * SEQ + _j * 128 + (_s - 6) * 32 + pcc * 8; \
        }                                                                      \
        cp16(_sb + po0, _s0, 16);                                              \
        cp16(_sb + po1, _s0 + 16, 16);                                         \
    } while (0)

    FL_ISSUE(0); cp_commit();
    FL_ISSUE(1); cp_commit();

    // consumer fragment offsets
    const int rowA = wm * 32 + (lane & 7) + ((lane >> 3) & 1) * 8;
    const int cA   = lane >> 4;
    const uint32_t offAq = (uint32_t)(rowA * 400 + cA * 16);
    const uint32_t offAp = (uint32_t)(rowA * 272 + cA * 16);
    const int rowB = wn * 32 + (lane & 7) + ((lane >> 4) << 3);
    const int cB   = (lane >> 3) & 1;
    const int xrB  = (rowB >> 1) & 3;
    const uint32_t offB0 = (uint32_t)(rowB * 64 + (((cB)     ^ xrB) << 4));
    const uint32_t offB1 = (uint32_t)(rowB * 64 + (((cB + 2) ^ xrB) << 4));

    float oacc[2][4][4];
    float m_r[2][2], l_r[2][2];
#pragma unroll
    for (int mi = 0; mi < 2; ++mi) {
#pragma unroll
        for (int nt = 0; nt < 4; ++nt)
#pragma unroll
            for (int k = 0; k < 4; ++k) oacc[mi][nt][k] = 0.f;
        m_r[mi][0] = m_r[mi][1] = -1e30f;
        l_r[mi][0] = l_r[mi][1] = 0.f;
    }

    int u = 0;
    for (int j = 0; j < nkv; ++j) {
        float sacc[2][4][4];
#pragma unroll
        for (int mi = 0; mi < 2; ++mi)
#pragma unroll
            for (int nt = 0; nt < 4; ++nt)
#pragma unroll
                for (int k = 0; k < 4; ++k) sacc[mi][nt][k] = 0.f;

        // ---- S phase: 6 k32 slabs (K=192) ----
        for (int s = 0; s < 6; ++s) {
            cp_wait1(); __syncthreads();
            const uint32_t sb = smS + (uint32_t)((u % 3) * 8192);
#pragma unroll
            for (int sub = 0; sub < 2; ++sub) {
                const uint32_t bAdr = sb + (sub ? offB1 : offB0);
                uint32_t bh4[2][4];
                ldsm4(bh4[0], bAdr);
                ldsm4(bh4[1], bAdr + 1024);
                const int k16 = s * 2 + sub;
#pragma unroll
                for (int mi = 0; mi < 2; ++mi) {
                    uint32_t ah[4];
                    ldsm4(ah, smQ + offAq + mi * 6400 + k16 * 32);
#pragma unroll
                    for (int nt = 0; nt < 4; ++nt) {
                        const int np = nt >> 1, hf2 = (nt & 1) * 2;
                        mma_f32(sacc[mi][nt], ah, bh4[np][hf2], bh4[np][hf2 + 1]);
                    }
                }
            }
            if (u + 2 < u_total) FL_ISSUE(u + 2);
            cp_commit(); ++u;
        }

        // ---- causal mask on last kv block ----
        if (j == nkv - 1) {
#pragma unroll
            for (int mi = 0; mi < 2; ++mi)
#pragma unroll
                for (int nt = 0; nt < 4; ++nt)
#pragma unroll
                    for (int k = 0; k < 4; ++k) {
                        const int rl = m0 + wm * 32 + mi * 16 + g + (k >> 1) * 8;
                        const int cl = j * 128 + wn * 32 + nt * 8 + 2 * c + (k & 1);
                        if (cl > rl) sacc[mi][nt][k] = -1e30f;
                    }
        }

        // ---- online softmax ----
        float alpha[2][2];
#pragma unroll
        for (int mi = 0; mi < 2; ++mi)
#pragma unroll
            for (int h2 = 0; h2 < 2; ++h2) {
                float v = fmaxf(fmaxf(sacc[mi][0][h2 * 2], sacc[mi][0][h2 * 2 + 1]),
                                fmaxf(sacc[mi][1][h2 * 2], sacc[mi][1][h2 * 2 + 1]));
                v = fmaxf(v, fmaxf(fmaxf(sacc[mi][2][h2 * 2], sacc[mi][2][h2 * 2 + 1]),
                                   fmaxf(sacc[mi][3][h2 * 2], sacc[mi][3][h2 * 2 + 1])));
                v = fmaxf(v, __shfl_xor_sync(0xffffffffu, v, 1));
                v = fmaxf(v, __shfl_xor_sync(0xffffffffu, v, 2));
                if (c == 0) RED[wn * 64 + wm * 32 + mi * 16 + g + h2 * 8] = v;
            }
        __syncthreads();
#pragma unroll
        for (int mi = 0; mi < 2; ++mi)
#pragma unroll
            for (int h2 = 0; h2 < 2; ++h2) {
                const int row = wm * 32 + mi * 16 + g + h2 * 8;
                float mrow = fmaxf(fmaxf(RED[row], RED[64 + row]),
                                   fmaxf(RED[128 + row], RED[192 + row]));
                float mnew = fmaxf(m_r[mi][h2], mrow);
                alpha[mi][h2] = exp2f((m_r[mi][h2] - mnew) * s2);
                m_r[mi][h2] = mnew;
            }
        __syncthreads();   // RED reads done before sum-round rewrite
#pragma unroll
        for (int mi = 0; mi < 2; ++mi)
#pragma unroll
            for (int h2 = 0; h2 < 2; ++h2) {
                const float mn = m_r[mi][h2];
                const float a = alpha[mi][h2];
                float sum = 0.f;
#pragma unroll
                for (int nt = 0; nt < 4; ++nt) {
                    float p0 = exp2f((sacc[mi][nt][h2 * 2] - mn) * s2);
                    float p1 = exp2f((sacc[mi][nt][h2 * 2 + 1] - mn) * s2);
                    sacc[mi][nt][h2 * 2] = p0;
                    sacc[mi][nt][h2 * 2 + 1] = p1;
                    oacc[mi][nt][h2 * 2] *= a;
                    oacc[mi][nt][h2 * 2 + 1] *= a;
                    sum += p0 + p1;
                }
                sum += __shfl_xor_sync(0xffffffffu, sum, 1);
                sum += __shfl_xor_sync(0xffffffffu, sum, 2);
                if (c == 0) RED[wn * 64 + wm * 32 + mi * 16 + g + h2 * 8] = sum;
            }
        // write P (hi plane only) to smem
#pragma unroll
        for (int mi = 0; mi < 2; ++mi)
#pragma unroll
            for (int nt = 0; nt < 4; ++nt) {
                const int r0 = wm * 32 + mi * 16 + g;
                const int cb = wn * 32 + nt * 8 + 2 * c;
                *(__half2*)(dyn + 25600 + r0 * 272 + cb * 2) =
                    __halves2half2(__float2half_rn(sacc[mi][nt][0]),
                                   __float2half_rn(sacc[mi][nt][1]));
                *(__half2*)(dyn + 25600 + (r0 + 8) * 272 + cb * 2) =
                    __halves2half2(__float2half_rn(sacc[mi][nt][2]),
                                   __float2half_rn(sacc[mi][nt][3]));
            }
        __syncthreads();   // P + sums visible
#pragma unroll
        for (int mi = 0; mi < 2; ++mi)
#pragma unroll
            for (int h2 = 0; h2 < 2; ++h2) {
                const int row = wm * 32 + mi * 16 + g + h2 * 8;
                const float ls = RED[row] + RED[64 + row] + RED[128 + row] + RED[192 + row];
                l_r[mi][h2] = l_r[mi][h2] * alpha[mi][h2] + ls;
            }

        // ---- PV phase: 4 k32 slabs (K=128 over t) ----
        for (int s = 0; s < 4; ++s) {
            cp_wait1(); __syncthreads();
            const uint32_t sb = smS + (uint32_t)((u % 3) * 8192);
#pragma unroll
            for (int sub = 0; sub < 2; ++sub) {
                const uint32_t bAdr = sb + (sub ? offB1 : offB0);
                uint32_t vh4[2][4];
                ldsm4(vh4[0], bAdr);
                ldsm4(vh4[1], bAdr + 1024);
                const int k16 = s * 2 + sub;
#pragma unroll
                for (int mi = 0; mi < 2; ++mi) {
                    uint32_t ph[4];
                    ldsm4(ph, smP + offAp + mi * 4352 + k16 * 32);
#pragma unroll
                    for (int nt = 0; nt < 4; ++nt) {
                        const int np = nt >> 1, hf2 = (nt & 1) * 2;
                        mma_f32(oacc[mi][nt], ph, vh4[np][hf2], vh4[np][hf2 + 1]);
                    }
                }
            }
            if (u + 2 < u_total) FL_ISSUE(u + 2);
            cp_commit(); ++u;
        }
    }
#undef FL_ISSUE

    // ---- epilogue: O / l -> ohead planes ----
    hf16* Cb = ohead + (size_t)(b * SEQ + m0) * DMODEL + h * D_V;
#pragma unroll
    for (int mi = 0; mi < 2; ++mi) {
        const int r0 = wm * 32 + mi * 16 + g;
        const float i0 = 1.f / l_r[mi][0], i1 = 1.f / l_r[mi][1];
#pragma unroll
        for (int nt = 0; nt < 4; ++nt) {
            const int cb = wn * 32 + nt * 8 + 2 * c;
            hf16 h0, l0, h1, l1;
            split2(oacc[mi][nt][0] * i0, h0, l0);
            split2(oacc[mi][nt][1] * i0, h1, l1);
            hf16* p = Cb + (size_t)r0 * DMODEL + cb;
            *(__half2*)p = __halves2half2(h0, h1);
            *(__half2*)(p + psOH) = __halves2half2(l0, l1);
            split2(oacc[mi][nt][2] * i1, h0, l0);
            split2(oacc[mi][nt][3] * i1, h1, l1);
            p = Cb + (size_t)(r0 + 8) * DMODEL + cb;
            *(__half2*)p = __halves2half2(h0, h1);
            *(__half2*)(p + psOH) = __halves2half2(l0, l1);
        }
    }
}

// ---------------------------- block reduction ------------------------------
__device__ __forceinline__ float blockReduce(float v, bool isMax) {
    __shared__ float sh[32];
    const int lane = threadIdx.x & 31, wid = threadIdx.x >> 5;
    __syncthreads();
#pragma unroll
    for (int o = 16; o > 0; o >>= 1) {
        float t = __shfl_down_sync(0xffffffffu, v, o);
        v = isMax ? fmaxf(v, t) : (v + t);
    }
    if (lane == 0) sh[wid] = v;
    __syncthreads();
    const int nw = blockDim.x >> 5;
    if (wid == 0) {
        v = (lane < nw) ? sh[lane] : (isMax ? -1e30f : 0.f);
#pragma unroll
        for (int o = 16; o > 0; o >>= 1) {
            float t = __shfl_down_sync(0xffffffffu, v, o);
            v = isMax ? fmaxf(v, t) : (v + t);
        }
        if (lane == 0) sh[0] = v;
    }
    __syncthreads();
    return sh[0];
}

// ------------------------------ aux kernels --------------------------------
__global__ void pack2_k(const float* __restrict__ in, hf16* __restrict__ out,
                        long long ps, int n) {
    for (int i = blockIdx.x * blockDim.x + threadIdx.x; i < n; i += gridDim.x * blockDim.x) {
        hf16 h, l; split2(in[i], h, l);
        out[i] = h; out[i + ps] = l;
    }
}

// fp32 [R][C] -> planes [C][R]
__global__ void packT2_k(const float* __restrict__ in, hf16* __restrict__ out,
                         long long ps, int R, int C) {
    __shared__ float t[32][33];
    const int c0 = blockIdx.x * 32, r0 = blockIdx.y * 32;
#pragma unroll
    for (int i = threadIdx.y; i < 32; i += 8)
        t[i][threadIdx.x] = in[(long long)(r0 + i) * C + c0 + threadIdx.x];
    __syncthreads();
#pragma unroll
    for (int i = threadIdx.y; i < 32; i += 8) {
        hf16 h, l; split2(t[threadIdx.x][i], h, l);
        long long o = (long long)(c0 + i) * R + r0 + threadIdx.x;
        out[o] = h; out[o + ps] = l;
    }
}

__global__ void rmsnorm_rows_k(hf16* x, long long ps, const float* __restrict__ w, int n) {
    long long base = (long long)blockIdx.x * n;
    float ss = 0.f;
    for (int i = threadIdx.x; i < n; i += blockDim.x) {
        float v = join2(x[base + i], x[base + i + ps]); ss += v * v;
    }
    ss = blockReduce(ss, false);
    float rn = rsqrtf(ss / (float)n + EPSF);
    for (int i = threadIdx.x; i < n; i += blockDim.x) {
        float v = join2(x[base + i], x[base + i + ps]) * rn * w[i];
        hf16 h, l; split2(v, h, l);
        x[base + i] = h; x[base + i + ps] = l;
    }
}

__global__ void kv_process_k(const hf16* __restrict__ kv, hf16* __restrict__ kext,
                             const float* __restrict__ w, const float* __restrict__ freqs) {
    const long long psKV = (long long)MS * KVD;
    const int m = blockIdx.x;
    const int s = m & (SEQ - 1);
    const hf16* kr = kv   + (long long)m * KVD;
    hf16*       ke = kext + (long long)m * KVD;
    float ss = 0.f;
    for (int i = threadIdx.x; i < KVLR; i += blockDim.x) {
        float v = join2(kr[i], kr[i + psKV]); ss += v * v;
    }
    ss = blockReduce(ss, false);
    float rn = rsqrtf(ss / (float)KVLR + EPSF);
    for (int i = threadIdx.x; i < KVLR; i += blockDim.x) {
        float v = join2(kr[i], kr[i + psKV]) * rn * w[i];
        hf16 h, l; split2(v, h, l);
        ke[i] = h; ke[i + psKV] = l;
    }
    if (threadIdx.x < 32) {
        const int i = threadIdx.x;
        float th = freqs[s * 32 + i];
        float co, sn; sincosf(th, &sn, &co);
        float x0 = join2(kr[KVLR + 2 * i], kr[KVLR + 2 * i + psKV]);
        float x1 = join2(kr[KVLR + 2 * i + 1], kr[KVLR + 2 * i + 1 + psKV]);
        hf16 h, l;
        split2(x0 * co - x1 * sn, h, l);
        ke[KVLR + 2 * i] = h; ke[KVLR + 2 * i + psKV] = l;
        split2(x0 * sn + x1 * co, h, l);
        ke[KVLR + 2 * i + 1] = h; ke[KVLR + 2 * i + 1 + psKV] = l;
    }
}

// rope q_pe in place inside g_q planes ([m][h*192+128 .. +191])
__global__ void rope_q_k(hf16* q, const float* __restrict__ freqs) {
    const long long psQ = (long long)MS * QDIM;
    const int m = blockIdx.x;
    const int s = m & (SEQ - 1);
    const int h = threadIdx.x >> 5;
    const int i = threadIdx.x & 31;
    float th = freqs[s * 32 + i];
    float co, sn; sincosf(th, &sn, &co);
    hf16* qr = q + (long long)m * QDIM + h * D_QK + D_NOPE;
    float x0 = join2(qr[2 * i], qr[2 * i + psQ]);
    float x1 = join2(qr[2 * i + 1], qr[2 * i + 1 + psQ]);
    hf16 hh, ll;
    split2(x0 * co - x1 * sn, hh, ll);
    qr[2 * i] = hh; qr[2 * i + psQ] = ll;
    split2(x0 * sn + x1 * co, hh, ll);
    qr[2 * i + 1] = hh; qr[2 * i + 1 + psQ] = ll;
}

// ------------------------------- host side ---------------------------------
static void launchGemm(const hf16* A, const hf16* B, long long bPS,
                       void* C, long long cPS,
                       int M, int N, int K,
                       long long lda, long long ldb, long long ldc,
                       int nb, int nInner,
                       long long aSb, long long aSh,
                       long long bSb, long long bSh,
                       long long cSb, long long cSh,
                       int causal, int outMode, int bLo) {
    GemmP p;
    p.A = A; p.B = B; p.C = C;
    p.bPS = bPS; p.cPS = cPS;
    p.M = M; p.N = N; p.K = K;
    p.lda = lda; p.ldb = ldb; p.ldc = ldc;
    p.aSb = aSb; p.aSh = aSh; p.bSb = bSb; p.bSh = bSh; p.cSb = cSb; p.cSh = cSh;
    p.nInner = nInner; p.causal = causal; p.outMode = outMode; p.bLo = bLo;
    dim3 grid((N + 127) / 128, (M + 127) / 128, nb);
    const int dynBytes = bLo ? 73728 : 49152;
    gemm_hmma<<<grid, 256, dynBytes>>>(p);
}

extern "C" void kernel_launch(void* const* d_in, const int* in_sizes, int n_in,
                              void* d_out, int out_size) {
    const float* x         = (const float*)d_in[0];
    const float* freqs     = (const float*)d_in[1];
    const float* wq_a      = (const float*)d_in[3];
    const float* q_norm_w  = (const float*)d_in[4];
    const float* wq_b      = (const float*)d_in[5];
    const float* wkv_a     = (const float*)d_in[6];
    const float* kv_norm_w = (const float*)d_in[7];
    const float* wkv_b     = (const float*)d_in[8];
    const float* wo        = (const float*)d_in[9];
    float* out = (float*)d_out;

    cudaFuncSetAttribute(flash_k, cudaFuncAttributeMaxDynamicSharedMemorySize, FL_SMEM);
    cudaFuncSetAttribute(gemm_hmma, cudaFuncAttributeMaxDynamicSharedMemorySize, GEMM_DYN_MAX);

    hf16 *xp, *wqaT, *wkvaT, *wqbT, *wkvbT, *woT;
    hf16 *qa, *q, *kv, *kext, *kabs, *vT, *ohead;
    cudaGetSymbolAddress((void**)&xp,     g_xp);
    cudaGetSymbolAddress((void**)&wqaT,   g_wqaT);
    cudaGetSymbolAddress((void**)&wkvaT,  g_wkvaT);
    cudaGetSymbolAddress((void**)&wqbT,   g_wqbT);
    cudaGetSymbolAddress((void**)&wkvbT,  g_wkvbT);
    cudaGetSymbolAddress((void**)&woT,    g_woT);
    cudaGetSymbolAddress((void**)&qa,     g_qa);
    cudaGetSymbolAddress((void**)&q,      g_q);
    cudaGetSymbolAddress((void**)&kv,     g_kv);
    cudaGetSymbolAddress((void**)&kext,   g_kext);
    cudaGetSymbolAddress((void**)&kabs,   g_kabs);
    cudaGetSymbolAddress((void**)&vT,     g_vT);
    cudaGetSymbolAddress((void**)&ohead,  g_ohead);

    const float scale = 1.0f / sqrtf((float)D_QK);
    const float s2 = scale * 1.4426950408889634f;   // scale * log2(e)

    // plane strides
    const long long psX   = (long long)MS * DMODEL;
    const long long psWQA = (long long)QLR * DMODEL;
    const long long psWKA = (long long)KVD * DMODEL;
    const long long psWQB = (long long)QDIM * QLR;
    const long long psWBT = (long long)NH * HDIM * KVLR;
    const long long psWO  = (long long)DMODEL * DMODEL;
    const long long psQA  = (long long)MS * QLR;
    const long long psQ   = (long long)MS * QDIM;
    const long long psKV  = (long long)MS * KVD;
    const long long psKA  = (long long)BSZ * NH * SEQ * D_NOPE;
    const long long psVT  = (long long)BSZ * NH * D_V * SEQ;
    const long long psOH  = (long long)MS * DMODEL;

    // ---- pack inputs into planes ----
    pack2_k<<<512, 256>>>(x, xp, psX, MS * DMODEL);
    packT2_k<<<dim3(QLR / 32, DMODEL / 32), dim3(32, 8)>>>(wq_a, wqaT, psWQA, DMODEL, QLR);
    packT2_k<<<dim3(KVD / 32, DMODEL / 32), dim3(32, 8)>>>(wkv_a, wkvaT, psWKA, DMODEL, KVD);
    packT2_k<<<dim3(QDIM / 32, QLR / 32), dim3(32, 8)>>>(wq_b, wqbT, psWQB, QLR, QDIM);
    packT2_k<<<dim3((NH * HDIM) / 32, KVLR / 32), dim3(32, 8)>>>(wkv_b, wkvbT, psWBT, KVLR, NH * HDIM);
    packT2_k<<<dim3(DMODEL / 32, DMODEL / 32), dim3(32, 8)>>>(wo, woT, psWO, DMODEL, DMODEL);

    // 1. qa = x @ wq_a   (B hi only)
    launchGemm(xp, wqaT, psWQA, qa, psQA, MS, QLR, DMODEL,
               DMODEL, DMODEL, QLR, 1, 1, 0, 0, 0, 0, 0, 0, 0, 1, 0);
    // 2. kv = x @ wkv_a (N=576, B planes)
    launchGemm(xp, wkvaT, psWKA, kv, psKV, MS, KVD, DMODEL,
               DMODEL, DMODEL, KVD, 1, 1, 0, 0, 0, 0, 0, 0, 0, 1, 1);
    // 3. rmsnorm(qa)
    rmsnorm_rows_k<<<MS, 256>>>(qa, psQA, q_norm_w, QLR);
    // 4. kext = [rmsnorm(latent), rope(k_pe)]
    kv_process_k<<<MS, 256>>>(kv, kext, kv_norm_w, freqs);
    // 5. q = qa @ wq_b (B hi only)
    launchGemm(qa, wqbT, psWQB, q, psQ, MS, QDIM, QLR,
               QLR, QLR, QDIM, 1, 1, 0, 0, 0, 0, 0, 0, 0, 1, 0);
    // 6. rope q_pe in place
    rope_q_k<<<MS, NH * 32>>>(q, freqs);
    // 7. k_abs[b,h,s,0:128] = kv_cache @ Wuk[h]^T (B planes)
    launchGemm(kext, wkvbT, psWBT, kabs, psKA,
               SEQ, D_NOPE, KVLR,
               KVD, KVLR, D_NOPE,
               BSZ * NH, NH,
               (long long)SEQ * KVD, 0,
               0, (long long)HDIM * KVLR,
               (long long)NH * SEQ * D_NOPE, (long long)SEQ * D_NOPE,
               0, 1, 1);
    // 8. vT[b,h,d,t] = Wuv[h] @ kv_cache^T (B = kext planes)
    launchGemm(wkvbT + (long long)D_NOPE * KVLR, kext, psKV, vT, psVT,
               D_V, SEQ, KVLR,
               KVLR, KVD, SEQ,
               BSZ * NH, NH,
               0, (long long)HDIM * KVLR,
               (long long)SEQ * KVD, 0,
               (long long)NH * D_V * SEQ, (long long)D_V * SEQ,
               0, 1, 1);
    // 9. fused flash attention (all-fp16 operands) -> ohead planes
    flash_k<<<dim3(32, BSZ * NH), 256, FL_SMEM>>>(q, kabs, kext, vT, ohead, s2);
    // 10. out = ohead @ wo (fp32 out, B hi only)
    launchGemm(ohead, woT, psWO, out, 0, MS, DMODEL, DMODEL,
               DMODEL, DMODEL, DMODEL, 1, 1, 0, 0, 0, 0, 0, 0, 0, 0, 0);
}

// round 16
// speedup vs baseline: 2.2865x; 1.2653x over previous
#include <cuda_runtime.h>
#include <cuda_fp16.h>
#include <math.h>
#include <stdint.h>

// ---------------------------------------------------------------------------
// MLA forward, per-head expanded attention + fused flash attention.
// All GEMM/MMA operands are plain fp16 (1 MMA per k16, K-slab 32).
// fp32 is carried only through: f32 accumulators everywhere, and two-plane
// (hi/lo) storage for the qa / q / kv / kext intermediates feeding rmsnorm
// and rope (reconstructed to f32 there, re-split after).
// ---------------------------------------------------------------------------

#define BSZ    2
#define SEQ    2048
#define DMODEL 2048
#define NH     16
#define QLR    1536
#define KVLR   512
#define D_NOPE 128
#define D_ROPE 64
#define D_QK   192
#define D_V    128
#define MS     (BSZ*SEQ)          /* 4096 */
#define QDIM   (NH*D_QK)          /* 3072 */
#define KVD    (KVLR + D_ROPE)    /* 576  */
#define HDIM   (D_NOPE + D_V)     /* 256  */
#define EPSF   1e-6f

typedef __half hf16;

// ------------------------- scratch -------------------------
__device__ hf16 g_xp   [(size_t)MS * DMODEL];
__device__ hf16 g_wqaT [(size_t)QLR * DMODEL];
__device__ hf16 g_wkvaT[(size_t)KVD * DMODEL];
__device__ hf16 g_wqbT [(size_t)QDIM * QLR];
__device__ hf16 g_wkvbT[(size_t)NH * HDIM * KVLR];
__device__ hf16 g_woT  [(size_t)DMODEL * DMODEL];
__device__ hf16 g_qa   [2 * (size_t)MS * QLR];
__device__ hf16 g_q    [2 * (size_t)MS * QDIM];
__device__ hf16 g_kv   [2 * (size_t)MS * KVD];
__device__ hf16 g_kext [2 * (size_t)MS * KVD];
__device__ hf16 g_kabs [(size_t)BSZ * NH * SEQ * D_NOPE];
__device__ hf16 g_vT   [(size_t)BSZ * NH * D_V * SEQ];
__device__ hf16 g_ohead[(size_t)MS * DMODEL];

// ------------------------------ helpers -------------------------------------
__device__ __forceinline__ void split2(float x, hf16& h, hf16& l) {
    h = __float2half_rn(x);
    l = __float2half_rn(x - __half2float(h));
}
__device__ __forceinline__ float join2(hf16 h, hf16 l) {
    return __half2float(h) + __half2float(l);
}
__device__ __forceinline__ void cp16(uint32_t smem, const void* g, int srcBytes) {
    asm volatile("cp.async.cg.shared.global [%0], [%1], 16, %2;"
                 :: "r"(smem), "l"(g), "r"(srcBytes));
}
__device__ __forceinline__ void cp_commit() { asm volatile("cp.async.commit_group;"); }
__device__ __forceinline__ void cp_wait1()  { asm volatile("cp.async.wait_group 1;"); }

__device__ __forceinline__ void ldsm4(uint32_t* r, uint32_t addr) {
    asm volatile("ldmatrix.sync.aligned.m8n8.x4.shared.b16 {%0,%1,%2,%3}, [%4];"
                 : "=r"(r[0]), "=r"(r[1]), "=r"(r[2]), "=r"(r[3]) : "r"(addr));
}
__device__ __forceinline__ void mma_f32(float* d, const uint32_t* a,
                                        uint32_t b0, uint32_t b1) {
    asm volatile(
        "mma.sync.aligned.m16n8k16.row.col.f32.f16.f16.f32 "
        "{%0,%1,%2,%3}, {%4,%5,%6,%7}, {%8,%9}, {%0,%1,%2,%3};"
        : "+f"(d[0]), "+f"(d[1]), "+f"(d[2]), "+f"(d[3])
        : "r"(a[0]), "r"(a[1]), "r"(a[2]), "r"(a[3]), "r"(b0), "r"(b1));
}

// ----------------------------- GEMM kernel ----------------------------------
// C = A * B^T, all operands fp16. A: [M][K] row stride lda; B: [N][K] row
// stride ldb. CTA tile 128x128, K-slab 32 (two k16 sub-steps), 8 warps,
// 64x32 warp tile. Dyn smem: 3 stages x (A 8KB + B 8KB) = 48KB. 64B rows,
// 2-bit XOR swizzle: physical chunk = logical ^ ((row>>1)&3).
// outMode 0: fp32 C. 1: fp16 planes C (lo at +cPS). 2: fp16 hi only.
struct GemmP {
    const hf16 *A, *B; void* C;
    long long cPS;
    int M, N, K;
    long long lda, ldb, ldc;
    long long aSb, aSh, bSb, bSh, cSb, cSh;
    int nInner, causal, outMode;
};

#define GEMM_DYN 49152

__global__ __launch_bounds__(256, 2) void gemm_hmma(GemmP p) {
    extern __shared__ __align__(16) unsigned char dynsm[];

    const int m0 = blockIdx.y * 128;
    const int n0 = blockIdx.x * 128;
    if (p.causal == 1 && n0 >= m0 + 128) return;

    const int z  = blockIdx.z;
    const int zb = z / p.nInner;
    const int zh = z - zb * p.nInner;
    const hf16* A = p.A + zb * p.aSb + zh * p.aSh;
    const hf16* B = p.B + zb * p.bSb + zh * p.bSh;

    int kEnd = p.K;
    if (p.causal == 2) { int km = m0 + 128; if (km < kEnd) kEnd = km; }
    const int nSlab = kEnd >> 5;

    const int tid  = threadIdx.x;
    const int lane = tid & 31;
    const int warp = tid >> 5;
    const int wm   = warp >> 2;    // 0..1
    const int wn   = warp & 3;     // 0..3

    const uint32_t smBase = (uint32_t)__cvta_generic_to_shared(dynsm);

    // producer: row r (128), logical chunks cc and cc+2 (4 x 16B per 64B row)
    const int r  = tid >> 1;
    const int cc = tid & 1;
    const int xr = (r >> 1) & 3;
    const uint32_t po0 = (uint32_t)(r * 64 + (((cc)     ^ xr) << 4));
    const uint32_t po1 = (uint32_t)(r * 64 + (((cc + 2) ^ xr) << 4));

    int mr = m0 + r;
    const bool aok = mr < p.M;
    if (!aok) mr = m0;
    const hf16* gA0 = A + (size_t)mr * p.lda + cc * 8;
    const int asz = aok ? 16 : 0;
    int nr = n0 + r;
    const bool bok = nr < p.N;
    if (!bok) nr = n0;
    const hf16* gB0 = B + (size_t)nr * p.ldb + cc * 8;
    const int bsz = bok ? 16 : 0;

#define ISSUE(S)                                                               \
    do {                                                                       \
        uint32_t sb = smBase + (uint32_t)((S) % 3) * 16384u;                   \
        const size_t ko = (size_t)(S) * 32;                                    \
        cp16(sb + po0,        gA0 + ko,      asz);                             \
        cp16(sb + po1,        gA0 + ko + 16, asz);                             \
        cp16(sb + 8192 + po0, gB0 + ko,      bsz);                             \
        cp16(sb + 8192 + po1, gB0 + ko + 16, bsz);                             \
    } while (0)

    // consumer fragment offsets (per k16 sub-step)
    const int rowA = wm * 64 + (lane & 15);
    const int cA   = lane >> 4;
    const int xrA  = (rowA >> 1) & 3;
    const uint32_t offA0 = (uint32_t)(rowA * 64 + (((cA)     ^ xrA) << 4));
    const uint32_t offA1 = (uint32_t)(rowA * 64 + (((cA + 2) ^ xrA) << 4));
    const int rowB = wn * 32 + (lane & 7) + ((lane >> 4) << 3);
    const int cB   = (lane >> 3) & 1;
    const int xrB  = (rowB >> 1) & 3;
    const uint32_t offB0 = (uint32_t)(rowB * 64 + (((cB)     ^ xrB) << 4));
    const uint32_t offB1 = (uint32_t)(rowB * 64 + (((cB + 2) ^ xrB) << 4));

    float acc[4][4][4];
#pragma unroll
    for (int i = 0; i < 4; ++i)
#pragma unroll
        for (int j = 0; j < 4; ++j)
#pragma unroll
            for (int l = 0; l < 4; ++l) acc[i][j][l] = 0.f;

    ISSUE(0); cp_commit();
    if (nSlab > 1) ISSUE(1);
    cp_commit();

    for (int it = 0; it < nSlab; ++it) {
        cp_wait1();
        __syncthreads();

        const uint32_t sb = smBase + (uint32_t)(it % 3) * 16384u;

#pragma unroll
        for (int sub = 0; sub < 2; ++sub) {
            const uint32_t aAdr = sb + (sub ? offA1 : offA0);
            const uint32_t bAdr = sb + 8192 + (sub ? offB1 : offB0);

            uint32_t bh[2][4];
            ldsm4(bh[0], bAdr);
            ldsm4(bh[1], bAdr + 1024);          // +16 rows * 64B

#pragma unroll
            for (int mi = 0; mi < 4; ++mi) {
                uint32_t ah[4];
                ldsm4(ah, aAdr + mi * 1024);    // +16 rows * 64B
#pragma unroll
                for (int nt = 0; nt < 4; ++nt) {
                    const int np = nt >> 1, hf = (nt & 1) * 2;
                    mma_f32(acc[mi][nt], ah, bh[np][hf], bh[np][hf + 1]);
                }
            }
        }

        if (it + 2 < nSlab) ISSUE(it + 2);
        cp_commit();
    }
#undef ISSUE

    const int g = lane >> 2;
    const int c = lane & 3;
    if (p.outMode == 0) {
        float* C = (float*)p.C + zb * p.cSb + zh * p.cSh;
#pragma unroll
        for (int mi = 0; mi < 4; ++mi) {
            const int gm = m0 + wm * 64 + mi * 16 + g;
            if (gm >= p.M) continue;
            float* r0 = C + (long long)gm * p.ldc;
            float* r1 = r0 + 8 * p.ldc;
#pragma unroll
            for (int nt = 0; nt < 4; ++nt) {
                const int gn = n0 + wn * 32 + nt * 8 + 2 * c;
                if (gn < p.N) {
                    *(float2*)(r0 + gn) = make_float2(acc[mi][nt][0], acc[mi][nt][1]);
                    *(float2*)(r1 + gn) = make_float2(acc[mi][nt][2], acc[mi][nt][3]);
                }
            }
        }
    } else if (p.outMode == 1) {
        hf16* Ch = (hf16*)p.C + zb * p.cSb + zh * p.cSh;
        hf16* Cl = Ch + p.cPS;
#pragma unroll
        for (int mi = 0; mi < 4; ++mi) {
            const int gm = m0 + wm * 64 + mi * 16 + g;
            if (gm >= p.M) continue;
            const long long ro0 = (long long)gm * p.ldc;
            const long long ro1 = ro0 + 8 * p.ldc;
#pragma unroll
            for (int nt = 0; nt < 4; ++nt) {
                const int gn = n0 + wn * 32 + nt * 8 + 2 * c;
                if (gn < p.N) {
                    hf16 h0, l0, h1, l1;
                    split2(acc[mi][nt][0], h0, l0);
                    split2(acc[mi][nt][1], h1, l1);
                    *(__half2*)(Ch + ro0 + gn) = __halves2half2(h0, h1);
                    *(__half2*)(Cl + ro0 + gn) = __halves2half2(l0, l1);
                    split2(acc[mi][nt][2], h0, l0);
                    split2(acc[mi][nt][3], h1, l1);
                    *(__half2*)(Ch + ro1 + gn) = __halves2half2(h0, h1);
                    *(__half2*)(Cl + ro1 + gn) = __halves2half2(l0, l1);
                }
            }
        }
    } else {
        hf16* Ch = (hf16*)p.C + zb * p.cSb + zh * p.cSh;
#pragma unroll
        for (int mi = 0; mi < 4; ++mi) {
            const int gm = m0 + wm * 64 + mi * 16 + g;
            if (gm >= p.M) continue;
            const long long ro0 = (long long)gm * p.ldc;
            const long long ro1 = ro0 + 8 * p.ldc;
#pragma unroll
            for (int nt = 0; nt < 4; ++nt) {
                const int gn = n0 + wn * 32 + nt * 8 + 2 * c;
                if (gn < p.N) {
                    *(__half2*)(Ch + ro0 + gn) =
                        __halves2half2(__float2half_rn(acc[mi][nt][0]),
                                       __float2half_rn(acc[mi][nt][1]));
                    *(__half2*)(Ch + ro1 + gn) =
                        __halves2half2(__float2half_rn(acc[mi][nt][2]),
                                       __float2half_rn(acc[mi][nt][3]));
                }
            }
        }
    }
}

// --------------------------- flash attention --------------------------------
// TM=64 q-rows per CTA, 2 CTAs/SM. grid (32 q-blocks, 32 bh).
// ALL operands fp16. K-slab 32 (two k16 sub-steps).
// smem layout (bytes):
//   Qh 0..25600                      (64 rows x 400B, 192 cols used)
//   Ph 25600..43008                  (64 rows x 272B, 128 cols used)
//   stages 43008 + s*8192 (128 rows x 64B, XOR swizzle), 3 stages -> 67584
//   RED 67584..68608 (float[4][64])
#define FL_SMEM 68608

__global__ __launch_bounds__(256, 2) void flash_k(
    const hf16* __restrict__ q, const hf16* __restrict__ kabs,
    const hf16* __restrict__ kext, const hf16* __restrict__ vT,
    hf16* __restrict__ ohead, float s2) {
    extern __shared__ __align__(16) char dyn[];
    const int tid = threadIdx.x, lane = tid & 31, warp = tid >> 5;
    const int wm = warp >> 2, wn = warp & 3, g = lane >> 2, c = lane & 3;
    const int iq = 31 - blockIdx.x;       // heavy blocks first
    const int bh = blockIdx.y, b = bh >> 4, h = bh & 15;
    const int m0 = iq * 64;
    const int nkv = (iq >> 1) + 1;

    const uint32_t smb = (uint32_t)__cvta_generic_to_shared(dyn);
    const uint32_t smQ = smb;
    const uint32_t smP = smb + 25600;
    const uint32_t smS = smb + 43008;
    float* RED = (float*)(dyn + 67584);

    // ---- Q block load: 64 rows, hi plane; 4 threads/row, 6 chunks each ----
    {
        const int r = tid >> 2, sub = tid & 3;
        const hf16* src = q + ((size_t)(b * SEQ + m0 + r)) * QDIM + h * D_QK + sub * 48;
        const uint32_t d0 = smQ + (uint32_t)(r * 400 + sub * 96);
#pragma unroll
        for (int ch = 0; ch < 6; ++ch) cp16(d0 + ch * 16, src + ch * 8, 16);
        cp_commit();
    }

    // producer: row prow (128), logical chunks pcc and pcc+2, 64B rows
    const int prow = tid >> 1, pcc = tid & 1;
    const int pxr = (prow >> 1) & 3;
    const uint32_t po0 = (uint32_t)(prow * 64 + (((pcc)     ^ pxr) << 4));
    const uint32_t po1 = (uint32_t)(prow * 64 + (((pcc + 2) ^ pxr) << 4));
    const hf16* ka = kabs + (size_t)bh * SEQ * D_NOPE;
    const hf16* ke = kext + (size_t)b * SEQ * KVD;
    const hf16* vt = vT + (size_t)bh * D_V * SEQ;
    const int u_total = 10 * nkv;

    // slab u -> (kv block j = u/10, s = u%10), each slab = 32 k-cols:
    //   s<4: K-nope from kabs; s in 4..5: pe from kext; s>=6: V-slab
#define FL_ISSUE(U)                                                            \
    do {                                                                       \
        const int _j = (U) / 10, _s = (U) % 10;                                \
        uint32_t _sb = smS + (uint32_t)(((U) % 3) * 8192);                     \
        const hf16* _s0;                                                       \
        if (_s < 4) {                                                          \
            _s0 = ka + ((size_t)(_j * 128 + prow)) * D_NOPE + _s * 32 + pcc * 8; \
        } else if (_s < 6) {                                                   \
            _s0 = ke + ((size_t)(_j * 128 + prow)) * KVD + KVLR                \
                     + (_s - 4) * 32 + pcc * 8;                                \
        } else {                                                               \
            _s0 = vt + (size_t)prow * SEQ + _j * 128 + (_s - 6) * 32 + pcc * 8; \
        }                                                                      \
        cp16(_sb + po0, _s0, 16);                                              \
        cp16(_sb + po1, _s0 + 16, 16);                                         \
    } while (0)

    FL_ISSUE(0); cp_commit();
    FL_ISSUE(1); cp_commit();

    // consumer fragment offsets
    const int rowA = wm * 32 + (lane & 7) + ((lane >> 3) & 1) * 8;
    const int cA   = lane >> 4;
    const uint32_t offAq = (uint32_t)(rowA * 400 + cA * 16);
    const uint32_t offAp = (uint32_t)(rowA * 272 + cA * 16);
    const int rowB = wn * 32 + (lane & 7) + ((lane >> 4) << 3);
    const int cB   = (lane >> 3) & 1;
    const int xrB  = (rowB >> 1) & 3;
    const uint32_t offB0 = (uint32_t)(rowB * 64 + (((cB)     ^ xrB) << 4));
    const uint32_t offB1 = (uint32_t)(rowB * 64 + (((cB + 2) ^ xrB) << 4));

    float oacc[2][4][4];
    float m_r[2][2], l_r[2][2];
#pragma unroll
    for (int mi = 0; mi < 2; ++mi) {
#pragma unroll
        for (int nt = 0; nt < 4; ++nt)
#pragma unroll
            for (int k = 0; k < 4; ++k) oacc[mi][nt][k] = 0.f;
        m_r[mi][0] = m_r[mi][1] = -1e30f;
        l_r[mi][0] = l_r[mi][1] = 0.f;
    }

    int u = 0;
    for (int j = 0; j < nkv; ++j) {
        float sacc[2][4][4];
#pragma unroll
        for (int mi = 0; mi < 2; ++mi)
#pragma unroll
            for (int nt = 0; nt < 4; ++nt)
#pragma unroll
                for (int k = 0; k < 4; ++k) sacc[mi][nt][k] = 0.f;

        // ---- S phase: 6 k32 slabs (K=192) ----
        for (int s = 0; s < 6; ++s) {
            cp_wait1(); __syncthreads();
            const uint32_t sb = smS + (uint32_t)((u % 3) * 8192);
#pragma unroll
            for (int sub = 0; sub < 2; ++sub) {
                const uint32_t bAdr = sb + (sub ? offB1 : offB0);
                uint32_t bh4[2][4];
                ldsm4(bh4[0], bAdr);
                ldsm4(bh4[1], bAdr + 1024);
                const int k16 = s * 2 + sub;
#pragma unroll
                for (int mi = 0; mi < 2; ++mi) {
                    uint32_t ah[4];
                    ldsm4(ah, smQ + offAq + mi * 6400 + k16 * 32);
#pragma unroll
                    for (int nt = 0; nt < 4; ++nt) {
                        const int np = nt >> 1, hf2 = (nt & 1) * 2;
                        mma_f32(sacc[mi][nt], ah, bh4[np][hf2], bh4[np][hf2 + 1]);
                    }
                }
            }
            if (u + 2 < u_total) FL_ISSUE(u + 2);
            cp_commit(); ++u;
        }

        // ---- causal mask on last kv block ----
        if (j == nkv - 1) {
#pragma unroll
            for (int mi = 0; mi < 2; ++mi)
#pragma unroll
                for (int nt = 0; nt < 4; ++nt)
#pragma unroll
                    for (int k = 0; k < 4; ++k) {
                        const int rl = m0 + wm * 32 + mi * 16 + g + (k >> 1) * 8;
                        const int cl = j * 128 + wn * 32 + nt * 8 + 2 * c + (k & 1);
                        if (cl > rl) sacc[mi][nt][k] = -1e30f;
                    }
        }

        // ---- online softmax ----
        float alpha[2][2];
#pragma unroll
        for (int mi = 0; mi < 2; ++mi)
#pragma unroll
            for (int h2 = 0; h2 < 2; ++h2) {
                float v = fmaxf(fmaxf(sacc[mi][0][h2 * 2], sacc[mi][0][h2 * 2 + 1]),
                                fmaxf(sacc[mi][1][h2 * 2], sacc[mi][1][h2 * 2 + 1]));
                v = fmaxf(v, fmaxf(fmaxf(sacc[mi][2][h2 * 2], sacc[mi][2][h2 * 2 + 1]),
                                   fmaxf(sacc[mi][3][h2 * 2], sacc[mi][3][h2 * 2 + 1])));
                v = fmaxf(v, __shfl_xor_sync(0xffffffffu, v, 1));
                v = fmaxf(v, __shfl_xor_sync(0xffffffffu, v, 2));
                if (c == 0) RED[wn * 64 + wm * 32 + mi * 16 + g + h2 * 8] = v;
            }
        __syncthreads();
#pragma unroll
        for (int mi = 0; mi < 2; ++mi)
#pragma unroll
            for (int h2 = 0; h2 < 2; ++h2) {
                const int row = wm * 32 + mi * 16 + g + h2 * 8;
                float mrow = fmaxf(fmaxf(RED[row], RED[64 + row]),
                                   fmaxf(RED[128 + row], RED[192 + row]));
                float mnew = fmaxf(m_r[mi][h2], mrow);
                alpha[mi][h2] = exp2f((m_r[mi][h2] - mnew) * s2);
                m_r[mi][h2] = mnew;
            }
        __syncthreads();   // RED reads done before sum-round rewrite
#pragma unroll
        for (int mi = 0; mi < 2; ++mi)
#pragma unroll
            for (int h2 = 0; h2 < 2; ++h2) {
                const float mn = m_r[mi][h2];
                const float a = alpha[mi][h2];
                float sum = 0.f;
#pragma unroll
                for (int nt = 0; nt < 4; ++nt) {
                    float p0 = exp2f((sacc[mi][nt][h2 * 2] - mn) * s2);
                    float p1 = exp2f((sacc[mi][nt][h2 * 2 + 1] - mn) * s2);
                    sacc[mi][nt][h2 * 2] = p0;
                    sacc[mi][nt][h2 * 2 + 1] = p1;
                    oacc[mi][nt][h2 * 2] *= a;
                    oacc[mi][nt][h2 * 2 + 1] *= a;
                    sum += p0 + p1;
                }
                sum += __shfl_xor_sync(0xffffffffu, sum, 1);
                sum += __shfl_xor_sync(0xffffffffu, sum, 2);
                if (c == 0) RED[wn * 64 + wm * 32 + mi * 16 + g + h2 * 8] = sum;
            }
        // write P to smem
#pragma unroll
        for (int mi = 0; mi < 2; ++mi)
#pragma unroll
            for (int nt = 0; nt < 4; ++nt) {
                const int r0 = wm * 32 + mi * 16 + g;
                const int cb = wn * 32 + nt * 8 + 2 * c;
                *(__half2*)(dyn + 25600 + r0 * 272 + cb * 2) =
                    __halves2half2(__float2half_rn(sacc[mi][nt][0]),
                                   __float2half_rn(sacc[mi][nt][1]));
                *(__half2*)(dyn + 25600 + (r0 + 8) * 272 + cb * 2) =
                    __halves2half2(__float2half_rn(sacc[mi][nt][2]),
                                   __float2half_rn(sacc[mi][nt][3]));
            }
        __syncthreads();   // P + sums visible
#pragma unroll
        for (int mi = 0; mi < 2; ++mi)
#pragma unroll
            for (int h2 = 0; h2 < 2; ++h2) {
                const int row = wm * 32 + mi * 16 + g + h2 * 8;
                const float ls = RED[row] + RED[64 + row] + RED[128 + row] + RED[192 + row];
                l_r[mi][h2] = l_r[mi][h2] * alpha[mi][h2] + ls;
            }

        // ---- PV phase: 4 k32 slabs (K=128 over t) ----
        for (int s = 0; s < 4; ++s) {
            cp_wait1(); __syncthreads();
            const uint32_t sb = smS + (uint32_t)((u % 3) * 8192);
#pragma unroll
            for (int sub = 0; sub < 2; ++sub) {
                const uint32_t bAdr = sb + (sub ? offB1 : offB0);
                uint32_t vh4[2][4];
                ldsm4(vh4[0], bAdr);
                ldsm4(vh4[1], bAdr + 1024);
                const int k16 = s * 2 + sub;
#pragma unroll
                for (int mi = 0; mi < 2; ++mi) {
                    uint32_t ph[4];
                    ldsm4(ph, smP + offAp + mi * 4352 + k16 * 32);
#pragma unroll
                    for (int nt = 0; nt < 4; ++nt) {
                        const int np = nt >> 1, hf2 = (nt & 1) * 2;
                        mma_f32(oacc[mi][nt], ph, vh4[np][hf2], vh4[np][hf2 + 1]);
                    }
                }
            }
            if (u + 2 < u_total) FL_ISSUE(u + 2);
            cp_commit(); ++u;
        }
    }
#undef FL_ISSUE

    // ---- epilogue: O / l -> ohead (fp16) ----
    hf16* Cb = ohead + (size_t)(b * SEQ + m0) * DMODEL + h * D_V;
#pragma unroll
    for (int mi = 0; mi < 2; ++mi) {
        const int r0 = wm * 32 + mi * 16 + g;
        const float i0 = 1.f / l_r[mi][0], i1 = 1.f / l_r[mi][1];
#pragma unroll
        for (int nt = 0; nt < 4; ++nt) {
            const int cb = wn * 32 + nt * 8 + 2 * c;
            hf16* p = Cb + (size_t)r0 * DMODEL + cb;
            *(__half2*)p = __halves2half2(__float2half_rn(oacc[mi][nt][0] * i0),
                                          __float2half_rn(oacc[mi][nt][1] * i0));
            p = Cb + (size_t)(r0 + 8) * DMODEL + cb;
            *(__half2*)p = __halves2half2(__float2half_rn(oacc[mi][nt][2] * i1),
                                          __float2half_rn(oacc[mi][nt][3] * i1));
        }
    }
}

// ---------------------------- block reduction ------------------------------
__device__ __forceinline__ float blockReduce(float v, bool isMax) {
    __shared__ float sh[32];
    const int lane = threadIdx.x & 31, wid = threadIdx.x >> 5;
    __syncthreads();
#pragma unroll
    for (int o = 16; o > 0; o >>= 1) {
        float t = __shfl_down_sync(0xffffffffu, v, o);
        v = isMax ? fmaxf(v, t) : (v + t);
    }
    if (lane == 0) sh[wid] = v;
    __syncthreads();
    const int nw = blockDim.x >> 5;
    if (wid == 0) {
        v = (lane < nw) ? sh[lane] : (isMax ? -1e30f : 0.f);
#pragma unroll
        for (int o = 16; o > 0; o >>= 1) {
            float t = __shfl_down_sync(0xffffffffu, v, o);
            v = isMax ? fmaxf(v, t) : (v + t);
        }
        if (lane == 0) sh[0] = v;
    }
    __syncthreads();
    return sh[0];
}

// ------------------------------ aux kernels --------------------------------
__global__ void pack1_k(const float* __restrict__ in, hf16* __restrict__ out, int n) {
    for (int i = blockIdx.x * blockDim.x + threadIdx.x; i < n; i += gridDim.x * blockDim.x)
        out[i] = __float2half_rn(in[i]);
}

// fp32 [R][C] -> fp16 [C][R] (hi only)
__global__ void packT1_k(const float* __restrict__ in, hf16* __restrict__ out,
                         int R, int C) {
    __shared__ float t[32][33];
    const int c0 = blockIdx.x * 32, r0 = blockIdx.y * 32;
#pragma unroll
    for (int i = threadIdx.y; i < 32; i += 8)
        t[i][threadIdx.x] = in[(long long)(r0 + i) * C + c0 + threadIdx.x];
    __syncthreads();
#pragma unroll
    for (int i = threadIdx.y; i < 32; i += 8)
        out[(long long)(c0 + i) * R + r0 + threadIdx.x] = __float2half_rn(t[threadIdx.x][i]);
}

__global__ void rmsnorm_rows_k(hf16* x, long long ps, const float* __restrict__ w, int n) {
    long long base = (long long)blockIdx.x * n;
    float ss = 0.f;
    for (int i = threadIdx.x; i < n; i += blockDim.x) {
        float v = join2(x[base + i], x[base + i + ps]); ss += v * v;
    }
    ss = blockReduce(ss, false);
    float rn = rsqrtf(ss / (float)n + EPSF);
    for (int i = threadIdx.x; i < n; i += blockDim.x) {
        float v = join2(x[base + i], x[base + i + ps]) * rn * w[i];
        hf16 h, l; split2(v, h, l);
        x[base + i] = h; x[base + i + ps] = l;
    }
}

__global__ void kv_process_k(const hf16* __restrict__ kv, hf16* __restrict__ kext,
                             const float* __restrict__ w, const float* __restrict__ freqs) {
    const long long psKV = (long long)MS * KVD;
    const int m = blockIdx.x;
    const int s = m & (SEQ - 1);
    const hf16* kr = kv   + (long long)m * KVD;
    hf16*       ke = kext + (long long)m * KVD;
    float ss = 0.f;
    for (int i = threadIdx.x; i < KVLR; i += blockDim.x) {
        float v = join2(kr[i], kr[i + psKV]); ss += v * v;
    }
    ss = blockReduce(ss, false);
    float rn = rsqrtf(ss / (float)KVLR + EPSF);
    for (int i = threadIdx.x; i < KVLR; i += blockDim.x) {
        float v = join2(kr[i], kr[i + psKV]) * rn * w[i];
        hf16 h, l; split2(v, h, l);
        ke[i] = h; ke[i + psKV] = l;
    }
    if (threadIdx.x < 32) {
        const int i = threadIdx.x;
        float th = freqs[s * 32 + i];
        float co, sn; sincosf(th, &sn, &co);
        float x0 = join2(kr[KVLR + 2 * i], kr[KVLR + 2 * i + psKV]);
        float x1 = join2(kr[KVLR + 2 * i + 1], kr[KVLR + 2 * i + 1 + psKV]);
        hf16 h, l;
        split2(x0 * co - x1 * sn, h, l);
        ke[KVLR + 2 * i] = h; ke[KVLR + 2 * i + psKV] = l;
        split2(x0 * sn + x1 * co, h, l);
        ke[KVLR + 2 * i + 1] = h; ke[KVLR + 2 * i + 1 + psKV] = l;
    }
}

// rope q_pe in place inside g_q planes ([m][h*192+128 .. +191])
__global__ void rope_q_k(hf16* q, const float* __restrict__ freqs) {
    const long long psQ = (long long)MS * QDIM;
    const int m = blockIdx.x;
    const int s = m & (SEQ - 1);
    const int h = threadIdx.x >> 5;
    const int i = threadIdx.x & 31;
    float th = freqs[s * 32 + i];
    float co, sn; sincosf(th, &sn, &co);
    hf16* qr = q + (long long)m * QDIM + h * D_QK + D_NOPE;
    float x0 = join2(qr[2 * i], qr[2 * i + psQ]);
    float x1 = join2(qr[2 * i + 1], qr[2 * i + 1 + psQ]);
    hf16 hh, ll;
    split2(x0 * co - x1 * sn, hh, ll);
    qr[2 * i] = hh; qr[2 * i + psQ] = ll;
    split2(x0 * sn + x1 * co, hh, ll);
    qr[2 * i + 1] = hh; qr[2 * i + 1 + psQ] = ll;
}

// ------------------------------- host side ---------------------------------
static void launchGemm(const hf16* A, const hf16* B,
                       void* C, long long cPS,
                       int M, int N, int K,
                       long long lda, long long ldb, long long ldc,
                       int nb, int nInner,
                       long long aSb, long long aSh,
                       long long bSb, long long bSh,
                       long long cSb, long long cSh,
                       int causal, int outMode) {
    GemmP p;
    p.A = A; p.B = B; p.C = C;
    p.cPS = cPS;
    p.M = M; p.N = N; p.K = K;
    p.lda = lda; p.ldb = ldb; p.ldc = ldc;
    p.aSb = aSb; p.aSh = aSh; p.bSb = bSb; p.bSh = bSh; p.cSb = cSb; p.cSh = cSh;
    p.nInner = nInner; p.causal = causal; p.outMode = outMode;
    dim3 grid((N + 127) / 128, (M + 127) / 128, nb);
    gemm_hmma<<<grid, 256, GEMM_DYN>>>(p);
}

extern "C" void kernel_launch(void* const* d_in, const int* in_sizes, int n_in,
                              void* d_out, int out_size) {
    const float* x         = (const float*)d_in[0];
    const float* freqs     = (const float*)d_in[1];
    const float* wq_a      = (const float*)d_in[3];
    const float* q_norm_w  = (const float*)d_in[4];
    const float* wq_b      = (const float*)d_in[5];
    const float* wkv_a     = (const float*)d_in[6];
    const float* kv_norm_w = (const float*)d_in[7];
    const float* wkv_b     = (const float*)d_in[8];
    const float* wo        = (const float*)d_in[9];
    float* out = (float*)d_out;

    cudaFuncSetAttribute(flash_k, cudaFuncAttributeMaxDynamicSharedMemorySize, FL_SMEM);
    cudaFuncSetAttribute(gemm_hmma, cudaFuncAttributeMaxDynamicSharedMemorySize, GEMM_DYN);

    hf16 *xp, *wqaT, *wkvaT, *wqbT, *wkvbT, *woT;
    hf16 *qa, *q, *kv, *kext, *kabs, *vT, *ohead;
    cudaGetSymbolAddress((void**)&xp,     g_xp);
    cudaGetSymbolAddress((void**)&wqaT,   g_wqaT);
    cudaGetSymbolAddress((void**)&wkvaT,  g_wkvaT);
    cudaGetSymbolAddress((void**)&wqbT,   g_wqbT);
    cudaGetSymbolAddress((void**)&wkvbT,  g_wkvbT);
    cudaGetSymbolAddress((void**)&woT,    g_woT);
    cudaGetSymbolAddress((void**)&qa,     g_qa);
    cudaGetSymbolAddress((void**)&q,      g_q);
    cudaGetSymbolAddress((void**)&kv,     g_kv);
    cudaGetSymbolAddress((void**)&kext,   g_kext);
    cudaGetSymbolAddress((void**)&kabs,   g_kabs);
    cudaGetSymbolAddress((void**)&vT,     g_vT);
    cudaGetSymbolAddress((void**)&ohead,  g_ohead);

    const float scale = 1.0f / sqrtf((float)D_QK);
    const float s2 = scale * 1.4426950408889634f;   // scale * log2(e)

    // plane strides (two-plane intermediates only)
    const long long psQA = (long long)MS * QLR;
    const long long psQ  = (long long)MS * QDIM;
    const long long psKV = (long long)MS * KVD;

    // ---- pack inputs (fp16, hi only) ----
    pack1_k<<<512, 256>>>(x, xp, MS * DMODEL);
    packT1_k<<<dim3(QLR / 32, DMODEL / 32), dim3(32, 8)>>>(wq_a, wqaT, DMODEL, QLR);
    packT1_k<<<dim3(KVD / 32, DMODEL / 32), dim3(32, 8)>>>(wkv_a, wkvaT, DMODEL, KVD);
    packT1_k<<<dim3(QDIM / 32, QLR / 32), dim3(32, 8)>>>(wq_b, wqbT, QLR, QDIM);
    packT1_k<<<dim3((NH * HDIM) / 32, KVLR / 32), dim3(32, 8)>>>(wkv_b, wkvbT, KVLR, NH * HDIM);
    packT1_k<<<dim3(DMODEL / 32, DMODEL / 32), dim3(32, 8)>>>(wo, woT, DMODEL, DMODEL);

    // 1. qa = x @ wq_a  (planes out: rmsnorm consumes f32 reconstruction)
    launchGemm(xp, wqaT, qa, psQA, MS, QLR, DMODEL,
               DMODEL, DMODEL, QLR, 1, 1, 0, 0, 0, 0, 0, 0, 0, 1);
    // 2. kv = x @ wkv_a (N=576, planes out)
    launchGemm(xp, wkvaT, kv, psKV, MS, KVD, DMODEL,
               DMODEL, DMODEL, KVD, 1, 1, 0, 0, 0, 0, 0, 0, 0, 1);
    // 3. rmsnorm(qa)
    rmsnorm_rows_k<<<MS, 256>>>(qa, psQA, q_norm_w, QLR);
    // 4. kext = [rmsnorm(latent), rope(k_pe)]
    kv_process_k<<<MS, 256>>>(kv, kext, kv_norm_w, freqs);
    // 5. q = qa @ wq_b  (planes out: rope consumes f32 reconstruction)
    launchGemm(qa, wqbT, q, psQ, MS, QDIM, QLR,
               QLR, QLR, QDIM, 1, 1, 0, 0, 0, 0, 0, 0, 0, 1);
    // 6. rope q_pe in place
    rope_q_k<<<MS, NH * 32>>>(q, freqs);
    // 7. k_abs[b,h,s,0:128] = kv_cache @ Wuk[h]^T  (fp16 out)
    launchGemm(kext, wkvbT, kabs, 0,
               SEQ, D_NOPE, KVLR,
               KVD, KVLR, D_NOPE,
               BSZ * NH, NH,
               (long long)SEQ * KVD, 0,
               0, (long long)HDIM * KVLR,
               (long long)NH * SEQ * D_NOPE, (long long)SEQ * D_NOPE,
               0, 2);
    // 8. vT[b,h,d,t] = Wuv[h] @ kv_cache^T  (fp16 out)
    launchGemm(wkvbT + (long long)D_NOPE * KVLR, kext, vT, 0,
               D_V, SEQ, KVLR,
               KVLR, KVD, SEQ,
               BSZ * NH, NH,
               0, (long long)HDIM * KVLR,
               (long long)SEQ * KVD, 0,
               (long long)NH * D_V * SEQ, (long long)D_V * SEQ,
               0, 2);
    // 9. fused flash attention (all-fp16 operands) -> ohead (fp16)
    flash_k<<<dim3(32, BSZ * NH), 256, FL_SMEM>>>(q, kabs, kext, vT, ohead, s2);
    // 10. out = ohead @ wo (fp32 out)
    launchGemm(ohead, woT, out, 0, MS, DMODEL, DMODEL,
               DMODEL, DMODEL, DMODEL, 1, 1, 0, 0, 0, 0, 0, 0, 0, 0);
}

// round 17
// speedup vs baseline: 2.4042x; 1.0515x over previous
#include <cuda_runtime.h>
#include <cuda_fp16.h>
#include <math.h>
#include <stdint.h>

// ---------------------------------------------------------------------------
// MLA forward, per-head expanded attention + fused flash attention.
// All GEMM/MMA operands plain fp16 (1 MMA per k16), GEMM K-slab 64 (96KB dyn
// smem, 3 stages, 2 CTAs/SM), flash K-slab 32. qa+kv GEMMs merged into one
// launch (combined N=2112). f32 carried via accumulators + hi/lo planes for
// the qakv / q intermediates feeding rmsnorm/rope.
// ---------------------------------------------------------------------------

#define BSZ    2
#define SEQ    2048
#define DMODEL 2048
#define NH     16
#define QLR    1536
#define KVLR   512
#define D_NOPE 128
#define D_ROPE 64
#define D_QK   192
#define D_V    128
#define MS     (BSZ*SEQ)          /* 4096 */
#define QDIM   (NH*D_QK)          /* 3072 */
#define KVD    (KVLR + D_ROPE)    /* 576  */
#define HDIM   (D_NOPE + D_V)     /* 256  */
#define LDQK   (QLR + KVD)        /* 2112 */
#define EPSF   1e-6f

typedef __half hf16;

// ------------------------- scratch -------------------------
__device__ hf16 g_xp    [(size_t)MS * DMODEL];
__device__ hf16 g_wqkT  [(size_t)LDQK * DMODEL];     // [wqaT ; wkvaT]
__device__ hf16 g_wqbT  [(size_t)QDIM * QLR];
__device__ hf16 g_wkvbT [(size_t)NH * HDIM * KVLR];
__device__ hf16 g_woT   [(size_t)DMODEL * DMODEL];
__device__ hf16 g_qakv  [2 * (size_t)MS * LDQK];     // planes
__device__ hf16 g_q     [2 * (size_t)MS * QDIM];     // planes
__device__ hf16 g_kext  [(size_t)MS * KVD];
__device__ hf16 g_kabs  [(size_t)BSZ * NH * SEQ * D_NOPE];
__device__ hf16 g_vT    [(size_t)BSZ * NH * D_V * SEQ];
__device__ hf16 g_ohead [(size_t)MS * DMODEL];

// ------------------------------ helpers -------------------------------------
__device__ __forceinline__ void split2(float x, hf16& h, hf16& l) {
    h = __float2half_rn(x);
    l = __float2half_rn(x - __half2float(h));
}
__device__ __forceinline__ float join2(hf16 h, hf16 l) {
    return __half2float(h) + __half2float(l);
}
__device__ __forceinline__ void cp16(uint32_t smem, const void* g, int srcBytes) {
    asm volatile("cp.async.cg.shared.global [%0], [%1], 16, %2;"
                 :: "r"(smem), "l"(g), "r"(srcBytes));
}
__device__ __forceinline__ void cp_commit() { asm volatile("cp.async.commit_group;"); }
__device__ __forceinline__ void cp_wait1()  { asm volatile("cp.async.wait_group 1;"); }

__device__ __forceinline__ void ldsm4(uint32_t* r, uint32_t addr) {
    asm volatile("ldmatrix.sync.aligned.m8n8.x4.shared.b16 {%0,%1,%2,%3}, [%4];"
                 : "=r"(r[0]), "=r"(r[1]), "=r"(r[2]), "=r"(r[3]) : "r"(addr));
}
__device__ __forceinline__ void mma_f32(float* d, const uint32_t* a,
                                        uint32_t b0, uint32_t b1) {
    asm volatile(
        "mma.sync.aligned.m16n8k16.row.col.f32.f16.f16.f32 "
        "{%0,%1,%2,%3}, {%4,%5,%6,%7}, {%8,%9}, {%0,%1,%2,%3};"
        : "+f"(d[0]), "+f"(d[1]), "+f"(d[2]), "+f"(d[3])
        : "r"(a[0]), "r"(a[1]), "r"(a[2]), "r"(a[3]), "r"(b0), "r"(b1));
}

// ----------------------------- GEMM kernel ----------------------------------
// C = A * B^T, all operands fp16. A: [M][K] row stride lda; B: [N][K] row
// stride ldb. CTA tile 128x128, K-slab 64 (four k16 sub-steps), 8 warps,
// 64x32 warp tile. Dyn smem: 3 stages x (A 16KB + B 16KB) = 96KB. 128B rows,
// 3-bit XOR swizzle: physical 16B-chunk = logical ^ (row & 7).
// outMode 0: fp32 C. 1: fp16 planes C (lo at +cPS). 2: fp16 hi only.
struct GemmP {
    const hf16 *A, *B; void* C;
    long long cPS;
    int M, N, K;
    long long lda, ldb, ldc;
    long long aSb, aSh, bSb, bSh, cSb, cSh;
    int nInner, outMode;
};

#define GEMM_DYN 98304

__global__ __launch_bounds__(256, 2) void gemm_hmma(GemmP p) {
    extern __shared__ __align__(16) unsigned char dynsm[];

    const int m0 = blockIdx.y * 128;
    const int n0 = blockIdx.x * 128;

    const int z  = blockIdx.z;
    const int zb = z / p.nInner;
    const int zh = z - zb * p.nInner;
    const hf16* A = p.A + zb * p.aSb + zh * p.aSh;
    const hf16* B = p.B + zb * p.bSb + zh * p.bSh;

    const int nSlab = p.K >> 6;

    const int tid  = threadIdx.x;
    const int lane = tid & 31;
    const int warp = tid >> 5;
    const int wm   = warp >> 2;    // 0..1
    const int wn   = warp & 3;     // 0..3

    const uint32_t smBase = (uint32_t)__cvta_generic_to_shared(dynsm);

    // producer: row r (128), 4 logical 16B chunks starting at (tid&1)*4
    const int r  = tid >> 1;
    const int c0 = (tid & 1) * 4;
    const int xr = r & 7;
    uint32_t po[4];
#pragma unroll
    for (int j = 0; j < 4; ++j)
        po[j] = (uint32_t)(r * 128 + (((c0 + j) ^ xr) << 4));

    int mr = m0 + r;
    const bool aok = mr < p.M;
    if (!aok) mr = m0;
    const hf16* gA0 = A + (size_t)mr * p.lda + c0 * 8;
    const int asz = aok ? 16 : 0;
    int nr = n0 + r;
    const bool bok = nr < p.N;
    if (!bok) nr = n0;
    const hf16* gB0 = B + (size_t)nr * p.ldb + c0 * 8;
    const int bsz = bok ? 16 : 0;

#define ISSUE(S)                                                               \
    do {                                                                       \
        uint32_t sb = smBase + (uint32_t)((S) % 3) * 32768u;                   \
        const size_t ko = (size_t)(S) * 64;                                    \
        _Pragma("unroll")                                                      \
        for (int j = 0; j < 4; ++j) {                                          \
            cp16(sb + po[j],          gA0 + ko + j * 8, asz);                  \
            cp16(sb + 16384 + po[j],  gB0 + ko + j * 8, bsz);                  \
        }                                                                      \
    } while (0)

    // consumer fragment offsets for the 4 k16 sub-steps
    const int rowA = wm * 64 + (lane & 15);
    const int cA   = lane >> 4;
    const int rowB = wn * 32 + (lane & 7) + ((lane >> 4) << 3);
    const int cB   = (lane >> 3) & 1;
    uint32_t offA[4], offB[4];
#pragma unroll
    for (int s = 0; s < 4; ++s) {
        offA[s] = (uint32_t)(rowA * 128 + (((s * 2 + cA) ^ (rowA & 7)) << 4));
        offB[s] = (uint32_t)(rowB * 128 + (((s * 2 + cB) ^ (rowB & 7)) << 4));
    }

    float acc[4][4][4];
#pragma unroll
    for (int i = 0; i < 4; ++i)
#pragma unroll
        for (int j = 0; j < 4; ++j)
#pragma unroll
            for (int l = 0; l < 4; ++l) acc[i][j][l] = 0.f;

    ISSUE(0); cp_commit();
    if (nSlab > 1) ISSUE(1);
    cp_commit();

    for (int it = 0; it < nSlab; ++it) {
        cp_wait1();
        __syncthreads();

        const uint32_t sb = smBase + (uint32_t)(it % 3) * 32768u;

#pragma unroll
        for (int sub = 0; sub < 4; ++sub) {
            const uint32_t aAdr = sb + offA[sub];
            const uint32_t bAdr = sb + 16384 + offB[sub];

            uint32_t bh[2][4];
            ldsm4(bh[0], bAdr);
            ldsm4(bh[1], bAdr + 2048);          // +16 rows * 128B

#pragma unroll
            for (int mi = 0; mi < 4; ++mi) {
                uint32_t ah[4];
                ldsm4(ah, aAdr + mi * 2048);    // +16 rows * 128B
#pragma unroll
                for (int nt = 0; nt < 4; ++nt) {
                    const int np = nt >> 1, hf = (nt & 1) * 2;
                    mma_f32(acc[mi][nt], ah, bh[np][hf], bh[np][hf + 1]);
                }
            }
        }

        if (it + 2 < nSlab) ISSUE(it + 2);
        cp_commit();
    }
#undef ISSUE

    const int g = lane >> 2;
    const int c = lane & 3;
    if (p.outMode == 0) {
        float* C = (float*)p.C + zb * p.cSb + zh * p.cSh;
#pragma unroll
        for (int mi = 0; mi < 4; ++mi) {
            const int gm = m0 + wm * 64 + mi * 16 + g;
            if (gm >= p.M) continue;
            float* r0 = C + (long long)gm * p.ldc;
            float* r1 = r0 + 8 * p.ldc;
#pragma unroll
            for (int nt = 0; nt < 4; ++nt) {
                const int gn = n0 + wn * 32 + nt * 8 + 2 * c;
                if (gn < p.N) {
                    *(float2*)(r0 + gn) = make_float2(acc[mi][nt][0], acc[mi][nt][1]);
                    *(float2*)(r1 + gn) = make_float2(acc[mi][nt][2], acc[mi][nt][3]);
                }
            }
        }
    } else if (p.outMode == 1) {
        hf16* Ch = (hf16*)p.C + zb * p.cSb + zh * p.cSh;
        hf16* Cl = Ch + p.cPS;
#pragma unroll
        for (int mi = 0; mi < 4; ++mi) {
            const int gm = m0 + wm * 64 + mi * 16 + g;
            if (gm >= p.M) continue;
            const long long ro0 = (long long)gm * p.ldc;
            const long long ro1 = ro0 + 8 * p.ldc;
#pragma unroll
            for (int nt = 0; nt < 4; ++nt) {
                const int gn = n0 + wn * 32 + nt * 8 + 2 * c;
                if (gn < p.N) {
                    hf16 h0, l0, h1, l1;
                    split2(acc[mi][nt][0], h0, l0);
                    split2(acc[mi][nt][1], h1, l1);
                    *(__half2*)(Ch + ro0 + gn) = __halves2half2(h0, h1);
                    *(__half2*)(Cl + ro0 + gn) = __halves2half2(l0, l1);
                    split2(acc[mi][nt][2], h0, l0);
                    split2(acc[mi][nt][3], h1, l1);
                    *(__half2*)(Ch + ro1 + gn) = __halves2half2(h0, h1);
                    *(__half2*)(Cl + ro1 + gn) = __halves2half2(l0, l1);
                }
            }
        }
    } else {
        hf16* Ch = (hf16*)p.C + zb * p.cSb + zh * p.cSh;
#pragma unroll
        for (int mi = 0; mi < 4; ++mi) {
            const int gm = m0 + wm * 64 + mi * 16 + g;
            if (gm >= p.M) continue;
            const long long ro0 = (long long)gm * p.ldc;
            const long long ro1 = ro0 + 8 * p.ldc;
#pragma unroll
            for (int nt = 0; nt < 4; ++nt) {
                const int gn = n0 + wn * 32 + nt * 8 + 2 * c;
                if (gn < p.N) {
                    *(__half2*)(Ch + ro0 + gn) =
                        __halves2half2(__float2half_rn(acc[mi][nt][0]),
                                       __float2half_rn(acc[mi][nt][1]));
                    *(__half2*)(Ch + ro1 + gn) =
                        __halves2half2(__float2half_rn(acc[mi][nt][2]),
                                       __float2half_rn(acc[mi][nt][3]));
                }
            }
        }
    }
}

// --------------------------- flash attention --------------------------------
// TM=64 q-rows per CTA, 2 CTAs/SM. grid (32 q-blocks, 32 bh).
// ALL operands fp16. K-slab 32 (two k16 sub-steps).
// smem layout (bytes):
//   Qh 0..25600                      (64 rows x 400B, 192 cols used)
//   Ph 25600..43008                  (64 rows x 272B, 128 cols used)
//   stages 43008 + s*8192 (128 rows x 64B, XOR swizzle), 3 stages -> 67584
//   RED 67584..68608 (float[4][64])
#define FL_SMEM 68608

__global__ __launch_bounds__(256, 2) void flash_k(
    const hf16* __restrict__ q, const hf16* __restrict__ kabs,
    const hf16* __restrict__ kext, const hf16* __restrict__ vT,
    hf16* __restrict__ ohead, float s2) {
    extern __shared__ __align__(16) char dyn[];
    const int tid = threadIdx.x, lane = tid & 31, warp = tid >> 5;
    const int wm = warp >> 2, wn = warp & 3, g = lane >> 2, c = lane & 3;
    const int iq = 31 - blockIdx.x;       // heavy blocks first
    const int bh = blockIdx.y, b = bh >> 4, h = bh & 15;
    const int m0 = iq * 64;
    const int nkv = (iq >> 1) + 1;

    const uint32_t smb = (uint32_t)__cvta_generic_to_shared(dyn);
    const uint32_t smQ = smb;
    const uint32_t smP = smb + 25600;
    const uint32_t smS = smb + 43008;
    float* RED = (float*)(dyn + 67584);

    // ---- Q block load: 64 rows, hi plane; 4 threads/row, 6 chunks each ----
    {
        const int r = tid >> 2, sub = tid & 3;
        const hf16* src = q + ((size_t)(b * SEQ + m0 + r)) * QDIM + h * D_QK + sub * 48;
        const uint32_t d0 = smQ + (uint32_t)(r * 400 + sub * 96);
#pragma unroll
        for (int ch = 0; ch < 6; ++ch) cp16(d0 + ch * 16, src + ch * 8, 16);
        cp_commit();
    }

    // producer: row prow (128), logical chunks pcc and pcc+2, 64B rows
    const int prow = tid >> 1, pcc = tid & 1;
    const int pxr = (prow >> 1) & 3;
    const uint32_t po0 = (uint32_t)(prow * 64 + (((pcc)     ^ pxr) << 4));
    const uint32_t po1 = (uint32_t)(prow * 64 + (((pcc + 2) ^ pxr) << 4));
    const hf16* ka = kabs + (size_t)bh * SEQ * D_NOPE;
    const hf16* ke = kext + (size_t)b * SEQ * KVD;
    const hf16* vt = vT + (size_t)bh * D_V * SEQ;
    const int u_total = 10 * nkv;

    // slab u -> (kv block j = u/10, s = u%10), each slab = 32 k-cols:
    //   s<4: K-nope from kabs; s in 4..5: pe from kext; s>=6: V-slab
#define FL_ISSUE(U)                                                            \
    do {                                                                       \
        const int _j = (U) / 10, _s = (U) % 10;                                \
        uint32_t _sb = smS + (uint32_t)(((U) % 3) * 8192);                     \
        const hf16* _s0;                                                       \
        if (_s < 4) {                                                          \
            _s0 = ka + ((size_t)(_j * 128 + prow)) * D_NOPE + _s * 32 + pcc * 8; \
        } else if (_s < 6) {                                                   \
            _s0 = ke + ((size_t)(_j * 128 + prow)) * KVD + KVLR                \
                     + (_s - 4) * 32 + pcc * 8;                                \
        } else {                                                               \
            _s0 = vt + (size_t)prow * SEQ + _j * 128 + (_s - 6) * 32 + pcc * 8; \
        }                                                                      \
        cp16(_sb + po0, _s0, 16);                                              \
        cp16(_sb + po1, _s0 + 16, 16);                                         \
    } while (0)

    FL_ISSUE(0); cp_commit();
    FL_ISSUE(1); cp_commit();

    // consumer fragment offsets
    const int rowA = wm * 32 + (lane & 7) + ((lane >> 3) & 1) * 8;
    const int cA   = lane >> 4;
    const uint32_t offAq = (uint32_t)(rowA * 400 + cA * 16);
    const uint32_t offAp = (uint32_t)(rowA * 272 + cA * 16);
    const int rowB = wn * 32 + (lane & 7) + ((lane >> 4) << 3);
    const int cB   = (lane >> 3) & 1;
    const int xrB  = (rowB >> 1) & 3;
    const uint32_t offB0 = (uint32_t)(rowB * 64 + (((cB)     ^ xrB) << 4));
    const uint32_t offB1 = (uint32_t)(rowB * 64 + (((cB + 2) ^ xrB) << 4));

    float oacc[2][4][4];
    float m_r[2][2], l_r[2][2];
#pragma unroll
    for (int mi = 0; mi < 2; ++mi) {
#pragma unroll
        for (int nt = 0; nt < 4; ++nt)
#pragma unroll
            for (int k = 0; k < 4; ++k) oacc[mi][nt][k] = 0.f;
        m_r[mi][0] = m_r[mi][1] = -1e30f;
        l_r[mi][0] = l_r[mi][1] = 0.f;
    }

    int u = 0;
    for (int j = 0; j < nkv; ++j) {
        float sacc[2][4][4];
#pragma unroll
        for (int mi = 0; mi < 2; ++mi)
#pragma unroll
            for (int nt = 0; nt < 4; ++nt)
#pragma unroll
                for (int k = 0; k < 4; ++k) sacc[mi][nt][k] = 0.f;

        // ---- S phase: 6 k32 slabs (K=192) ----
        for (int s = 0; s < 6; ++s) {
            cp_wait1(); __syncthreads();
            const uint32_t sb = smS + (uint32_t)((u % 3) * 8192);
#pragma unroll
            for (int sub = 0; sub < 2; ++sub) {
                const uint32_t bAdr = sb + (sub ? offB1 : offB0);
                uint32_t bh4[2][4];
                ldsm4(bh4[0], bAdr);
                ldsm4(bh4[1], bAdr + 1024);
                const int k16 = s * 2 + sub;
#pragma unroll
                for (int mi = 0; mi < 2; ++mi) {
                    uint32_t ah[4];
                    ldsm4(ah, smQ + offAq + mi * 6400 + k16 * 32);
#pragma unroll
                    for (int nt = 0; nt < 4; ++nt) {
                        const int np = nt >> 1, hf2 = (nt & 1) * 2;
                        mma_f32(sacc[mi][nt], ah, bh4[np][hf2], bh4[np][hf2 + 1]);
                    }
                }
            }
            if (u + 2 < u_total) FL_ISSUE(u + 2);
            cp_commit(); ++u;
        }

        // ---- causal mask on last kv block ----
        if (j == nkv - 1) {
#pragma unroll
            for (int mi = 0; mi < 2; ++mi)
#pragma unroll
                for (int nt = 0; nt < 4; ++nt)
#pragma unroll
                    for (int k = 0; k < 4; ++k) {
                        const int rl = m0 + wm * 32 + mi * 16 + g + (k >> 1) * 8;
                        const int cl = j * 128 + wn * 32 + nt * 8 + 2 * c + (k & 1);
                        if (cl > rl) sacc[mi][nt][k] = -1e30f;
                    }
        }

        // ---- online softmax ----
        float alpha[2][2];
#pragma unroll
        for (int mi = 0; mi < 2; ++mi)
#pragma unroll
            for (int h2 = 0; h2 < 2; ++h2) {
                float v = fmaxf(fmaxf(sacc[mi][0][h2 * 2], sacc[mi][0][h2 * 2 + 1]),
                                fmaxf(sacc[mi][1][h2 * 2], sacc[mi][1][h2 * 2 + 1]));
                v = fmaxf(v, fmaxf(fmaxf(sacc[mi][2][h2 * 2], sacc[mi][2][h2 * 2 + 1]),
                                   fmaxf(sacc[mi][3][h2 * 2], sacc[mi][3][h2 * 2 + 1])));
                v = fmaxf(v, __shfl_xor_sync(0xffffffffu, v, 1));
                v = fmaxf(v, __shfl_xor_sync(0xffffffffu, v, 2));
                if (c == 0) RED[wn * 64 + wm * 32 + mi * 16 + g + h2 * 8] = v;
            }
        __syncthreads();
#pragma unroll
        for (int mi = 0; mi < 2; ++mi)
#pragma unroll
            for (int h2 = 0; h2 < 2; ++h2) {
                const int row = wm * 32 + mi * 16 + g + h2 * 8;
                float mrow = fmaxf(fmaxf(RED[row], RED[64 + row]),
                                   fmaxf(RED[128 + row], RED[192 + row]));
                float mnew = fmaxf(m_r[mi][h2], mrow);
                alpha[mi][h2] = exp2f((m_r[mi][h2] - mnew) * s2);
                m_r[mi][h2] = mnew;
            }
        __syncthreads();   // RED reads done before sum-round rewrite
#pragma unroll
        for (int mi = 0; mi < 2; ++mi)
#pragma unroll
            for (int h2 = 0; h2 < 2; ++h2) {
                const float mn = m_r[mi][h2];
                const float a = alpha[mi][h2];
                float sum = 0.f;
#pragma unroll
                for (int nt = 0; nt < 4; ++nt) {
                    float p0 = exp2f((sacc[mi][nt][h2 * 2] - mn) * s2);
                    float p1 = exp2f((sacc[mi][nt][h2 * 2 + 1] - mn) * s2);
                    sacc[mi][nt][h2 * 2] = p0;
                    sacc[mi][nt][h2 * 2 + 1] = p1;
                    oacc[mi][nt][h2 * 2] *= a;
                    oacc[mi][nt][h2 * 2 + 1] *= a;
                    sum += p0 + p1;
                }
                sum += __shfl_xor_sync(0xffffffffu, sum, 1);
                sum += __shfl_xor_sync(0xffffffffu, sum, 2);
                if (c == 0) RED[wn * 64 + wm * 32 + mi * 16 + g + h2 * 8] = sum;
            }
        // write P to smem
#pragma unroll
        for (int mi = 0; mi < 2; ++mi)
#pragma unroll
            for (int nt = 0; nt < 4; ++nt) {
                const int r0 = wm * 32 + mi * 16 + g;
                const int cb = wn * 32 + nt * 8 + 2 * c;
                *(__half2*)(dyn + 25600 + r0 * 272 + cb * 2) =
                    __halves2half2(__float2half_rn(sacc[mi][nt][0]),
                                   __float2half_rn(sacc[mi][nt][1]));
                *(__half2*)(dyn + 25600 + (r0 + 8) * 272 + cb * 2) =
                    __halves2half2(__float2half_rn(sacc[mi][nt][2]),
                                   __float2half_rn(sacc[mi][nt][3]));
            }
        __syncthreads();   // P + sums visible
#pragma unroll
        for (int mi = 0; mi < 2; ++mi)
#pragma unroll
            for (int h2 = 0; h2 < 2; ++h2) {
                const int row = wm * 32 + mi * 16 + g + h2 * 8;
                const float ls = RED[row] + RED[64 + row] + RED[128 + row] + RED[192 + row];
                l_r[mi][h2] = l_r[mi][h2] * alpha[mi][h2] + ls;
            }

        // ---- PV phase: 4 k32 slabs (K=128 over t) ----
        for (int s = 0; s < 4; ++s) {
            cp_wait1(); __syncthreads();
            const uint32_t sb = smS + (uint32_t)((u % 3) * 8192);
#pragma unroll
            for (int sub = 0; sub < 2; ++sub) {
                const uint32_t bAdr = sb + (sub ? offB1 : offB0);
                uint32_t vh4[2][4];
                ldsm4(vh4[0], bAdr);
                ldsm4(vh4[1], bAdr + 1024);
                const int k16 = s * 2 + sub;
#pragma unroll
                for (int mi = 0; mi < 2; ++mi) {
                    uint32_t ph[4];
                    ldsm4(ph, smP + offAp + mi * 4352 + k16 * 32);
#pragma unroll
                    for (int nt = 0; nt < 4; ++nt) {
                        const int np = nt >> 1, hf2 = (nt & 1) * 2;
                        mma_f32(oacc[mi][nt], ph, vh4[np][hf2], vh4[np][hf2 + 1]);
                    }
                }
            }
            if (u + 2 < u_total) FL_ISSUE(u + 2);
            cp_commit(); ++u;
        }
    }
#undef FL_ISSUE

    // ---- epilogue: O / l -> ohead (fp16) ----
    hf16* Cb = ohead + (size_t)(b * SEQ + m0) * DMODEL + h * D_V;
#pragma unroll
    for (int mi = 0; mi < 2; ++mi) {
        const int r0 = wm * 32 + mi * 16 + g;
        const float i0 = 1.f / l_r[mi][0], i1 = 1.f / l_r[mi][1];
#pragma unroll
        for (int nt = 0; nt < 4; ++nt) {
            const int cb = wn * 32 + nt * 8 + 2 * c;
            hf16* p = Cb + (size_t)r0 * DMODEL + cb;
            *(__half2*)p = __halves2half2(__float2half_rn(oacc[mi][nt][0] * i0),
                                          __float2half_rn(oacc[mi][nt][1] * i0));
            p = Cb + (size_t)(r0 + 8) * DMODEL + cb;
            *(__half2*)p = __halves2half2(__float2half_rn(oacc[mi][nt][2] * i1),
                                          __float2half_rn(oacc[mi][nt][3] * i1));
        }
    }
}

// ---------------------------- block reduction ------------------------------
__device__ __forceinline__ float blockReduce(float v, bool isMax) {
    __shared__ float sh[32];
    const int lane = threadIdx.x & 31, wid = threadIdx.x >> 5;
    __syncthreads();
#pragma unroll
    for (int o = 16; o > 0; o >>= 1) {
        float t = __shfl_down_sync(0xffffffffu, v, o);
        v = isMax ? fmaxf(v, t) : (v + t);
    }
    if (lane == 0) sh[wid] = v;
    __syncthreads();
    const int nw = blockDim.x >> 5;
    if (wid == 0) {
        v = (lane < nw) ? sh[lane] : (isMax ? -1e30f : 0.f);
#pragma unroll
        for (int o = 16; o > 0; o >>= 1) {
            float t = __shfl_down_sync(0xffffffffu, v, o);
            v = isMax ? fmaxf(v, t) : (v + t);
        }
        if (lane == 0) sh[0] = v;
    }
    __syncthreads();
    return sh[0];
}

// ------------------------------ aux kernels --------------------------------
__global__ void pack1_k(const float* __restrict__ in, hf16* __restrict__ out, int n) {
    for (int i = blockIdx.x * blockDim.x + threadIdx.x; i < n; i += gridDim.x * blockDim.x)
        out[i] = __float2half_rn(in[i]);
}

// fp32 [R][C] -> fp16 [C][R] (hi only)
__global__ void packT1_k(const float* __restrict__ in, hf16* __restrict__ out,
                         int R, int C) {
    __shared__ float t[32][33];
    const int c0 = blockIdx.x * 32, r0 = blockIdx.y * 32;
#pragma unroll
    for (int i = threadIdx.y; i < 32; i += 8)
        t[i][threadIdx.x] = in[(long long)(r0 + i) * C + c0 + threadIdx.x];
    __syncthreads();
#pragma unroll
    for (int i = threadIdx.y; i < 32; i += 8)
        out[(long long)(c0 + i) * R + r0 + threadIdx.x] = __float2half_rn(t[threadIdx.x][i]);
}

// rmsnorm over first n cols of rows with stride ld (planes at +ps)
__global__ void rmsnorm_rows_k(hf16* x, long long ps, const float* __restrict__ w,
                               int n, int ld) {
    long long base = (long long)blockIdx.x * ld;
    float ss = 0.f;
    for (int i = threadIdx.x; i < n; i += blockDim.x) {
        float v = join2(x[base + i], x[base + i + ps]); ss += v * v;
    }
    ss = blockReduce(ss, false);
    float rn = rsqrtf(ss / (float)n + EPSF);
    for (int i = threadIdx.x; i < n; i += blockDim.x) {
        float v = join2(x[base + i], x[base + i + ps]) * rn * w[i];
        hf16 h, l; split2(v, h, l);
        x[base + i] = h; x[base + i + ps] = l;
    }
}

// kv section of qakv (cols QLR..QLR+575, stride LDQK) -> kext (fp16, hi only)
__global__ void kv_process_k(const hf16* __restrict__ qakv, long long ps,
                             hf16* __restrict__ kext,
                             const float* __restrict__ w, const float* __restrict__ freqs) {
    const int m = blockIdx.x;
    const int s = m & (SEQ - 1);
    const hf16* kr = qakv + (long long)m * LDQK + QLR;
    hf16*       ke = kext + (long long)m * KVD;
    float ss = 0.f;
    for (int i = threadIdx.x; i < KVLR; i += blockDim.x) {
        float v = join2(kr[i], kr[i + ps]); ss += v * v;
    }
    ss = blockReduce(ss, false);
    float rn = rsqrtf(ss / (float)KVLR + EPSF);
    for (int i = threadIdx.x; i < KVLR; i += blockDim.x)
        ke[i] = __float2half_rn(join2(kr[i], kr[i + ps]) * rn * w[i]);
    if (threadIdx.x < 32) {
        const int i = threadIdx.x;
        float th = freqs[s * 32 + i];
        float co, sn; sincosf(th, &sn, &co);
        float x0 = join2(kr[KVLR + 2 * i], kr[KVLR + 2 * i + ps]);
        float x1 = join2(kr[KVLR + 2 * i + 1], kr[KVLR + 2 * i + 1 + ps]);
        ke[KVLR + 2 * i]     = __float2half_rn(x0 * co - x1 * sn);
        ke[KVLR + 2 * i + 1] = __float2half_rn(x0 * sn + x1 * co);
    }
}

// rope q_pe in place inside g_q planes ([m][h*192+128 .. +191])
__global__ void rope_q_k(hf16* q, const float* __restrict__ freqs) {
    const long long psQ = (long long)MS * QDIM;
    const int m = blockIdx.x;
    const int s = m & (SEQ - 1);
    const int h = threadIdx.x >> 5;
    const int i = threadIdx.x & 31;
    float th = freqs[s * 32 + i];
    float co, sn; sincosf(th, &sn, &co);
    hf16* qr = q + (long long)m * QDIM + h * D_QK + D_NOPE;
    float x0 = join2(qr[2 * i], qr[2 * i + psQ]);
    float x1 = join2(qr[2 * i + 1], qr[2 * i + 1 + psQ]);
    hf16 hh, ll;
    split2(x0 * co - x1 * sn, hh, ll);
    qr[2 * i] = hh; qr[2 * i + psQ] = ll;
    split2(x0 * sn + x1 * co, hh, ll);
    qr[2 * i + 1] = hh; qr[2 * i + 1 + psQ] = ll;
}

// ------------------------------- host side ---------------------------------
static void launchGemm(const hf16* A, const hf16* B,
                       void* C, long long cPS,
                       int M, int N, int K,
                       long long lda, long long ldb, long long ldc,
                       int nb, int nInner,
                       long long aSb, long long aSh,
                       long long bSb, long long bSh,
                       long long cSb, long long cSh,
                       int outMode) {
    GemmP p;
    p.A = A; p.B = B; p.C = C;
    p.cPS = cPS;
    p.M = M; p.N = N; p.K = K;
    p.lda = lda; p.ldb = ldb; p.ldc = ldc;
    p.aSb = aSb; p.aSh = aSh; p.bSb = bSb; p.bSh = bSh; p.cSb = cSb; p.cSh = cSh;
    p.nInner = nInner; p.outMode = outMode;
    dim3 grid((N + 127) / 128, (M + 127) / 128, nb);
    gemm_hmma<<<grid, 256, GEMM_DYN>>>(p);
}

extern "C" void kernel_launch(void* const* d_in, const int* in_sizes, int n_in,
                              void* d_out, int out_size) {
    const float* x         = (const float*)d_in[0];
    const float* freqs     = (const float*)d_in[1];
    const float* wq_a      = (const float*)d_in[3];
    const float* q_norm_w  = (const float*)d_in[4];
    const float* wq_b      = (const float*)d_in[5];
    const float* wkv_a     = (const float*)d_in[6];
    const float* kv_norm_w = (const float*)d_in[7];
    const float* wkv_b     = (const float*)d_in[8];
    const float* wo        = (const float*)d_in[9];
    float* out = (float*)d_out;

    cudaFuncSetAttribute(flash_k, cudaFuncAttributeMaxDynamicSharedMemorySize, FL_SMEM);
    cudaFuncSetAttribute(gemm_hmma, cudaFuncAttributeMaxDynamicSharedMemorySize, GEMM_DYN);

    hf16 *xp, *wqkT, *wqbT, *wkvbT, *woT;
    hf16 *qakv, *q, *kext, *kabs, *vT, *ohead;
    cudaGetSymbolAddress((void**)&xp,     g_xp);
    cudaGetSymbolAddress((void**)&wqkT,   g_wqkT);
    cudaGetSymbolAddress((void**)&wqbT,   g_wqbT);
    cudaGetSymbolAddress((void**)&wkvbT,  g_wkvbT);
    cudaGetSymbolAddress((void**)&woT,    g_woT);
    cudaGetSymbolAddress((void**)&qakv,   g_qakv);
    cudaGetSymbolAddress((void**)&q,      g_q);
    cudaGetSymbolAddress((void**)&kext,   g_kext);
    cudaGetSymbolAddress((void**)&kabs,   g_kabs);
    cudaGetSymbolAddress((void**)&vT,     g_vT);
    cudaGetSymbolAddress((void**)&ohead,  g_ohead);

    const float scale = 1.0f / sqrtf((float)D_QK);
    const float s2 = scale * 1.4426950408889634f;   // scale * log2(e)

    const long long psQK = (long long)MS * LDQK;
    const long long psQ  = (long long)MS * QDIM;

    // ---- pack inputs (fp16, hi only) ----
    pack1_k<<<512, 256>>>(x, xp, MS * DMODEL);
    packT1_k<<<dim3(QLR / 32, DMODEL / 32), dim3(32, 8)>>>(wq_a, wqkT, DMODEL, QLR);
    packT1_k<<<dim3(KVD / 32, DMODEL / 32), dim3(32, 8)>>>(
        wkv_a, wqkT + (size_t)QLR * DMODEL, DMODEL, KVD);
    packT1_k<<<dim3(QDIM / 32, QLR / 32), dim3(32, 8)>>>(wq_b, wqbT, QLR, QDIM);
    packT1_k<<<dim3((NH * HDIM) / 32, KVLR / 32), dim3(32, 8)>>>(wkv_b, wkvbT, KVLR, NH * HDIM);
    packT1_k<<<dim3(DMODEL / 32, DMODEL / 32), dim3(32, 8)>>>(wo, woT, DMODEL, DMODEL);

    // 1. qakv = x @ [wq_a | wkv_a]  (merged, planes out, N=2112)
    launchGemm(xp, wqkT, qakv, psQK, MS, LDQK, DMODEL,
               DMODEL, DMODEL, LDQK, 1, 1, 0, 0, 0, 0, 0, 0, 1);
    // 2. rmsnorm over qa section (cols 0..1535)
    rmsnorm_rows_k<<<MS, 256>>>(qakv, psQK, q_norm_w, QLR, LDQK);
    // 3. kext = [rmsnorm(latent), rope(k_pe)] from kv section
    kv_process_k<<<MS, 256>>>(qakv, psQK, kext, kv_norm_w, freqs);
    // 4. q = qa @ wq_b (A = qakv first 1536 cols, planes out)
    launchGemm(qakv, wqbT, q, psQ, MS, QDIM, QLR,
               LDQK, QLR, QDIM, 1, 1, 0, 0, 0, 0, 0, 0, 1);
    // 5. rope q_pe in place
    rope_q_k<<<MS, NH * 32>>>(q, freqs);
    // 6. k_abs[b,h,s,0:128] = kv_cache @ Wuk[h]^T  (fp16 out)
    launchGemm(kext, wkvbT, kabs, 0,
               SEQ, D_NOPE, KVLR,
               KVD, KVLR, D_NOPE,
               BSZ * NH, NH,
               (long long)SEQ * KVD, 0,
               0, (long long)HDIM * KVLR,
               (long long)NH * SEQ * D_NOPE, (long long)SEQ * D_NOPE,
               2);
    // 7. vT[b,h,d,t] = Wuv[h] @ kv_cache^T  (fp16 out)
    launchGemm(wkvbT + (long long)D_NOPE * KVLR, kext, vT, 0,
               D_V, SEQ, KVLR,
               KVLR, KVD, SEQ,
               BSZ * NH, NH,
               0, (long long)HDIM * KVLR,
               (long long)SEQ * KVD, 0,
               (long long)NH * D_V * SEQ, (long long)D_V * SEQ,
               2);
    // 8. fused flash attention (all-fp16 operands) -> ohead (fp16)
    flash_k<<<dim3(32, BSZ * NH), 256, FL_SMEM>>>(q, kabs, kext, vT, ohead, s2);
    // 9. out = ohead @ wo (fp32 out)
    launchGemm(ohead, woT, out, 0, MS, DMODEL, DMODEL,
               DMODEL, DMODEL, DMODEL, 1, 1, 0, 0, 0, 0, 0, 0, 0);
}